// round 1
// baseline (speedup 1.0000x reference)
#include <cuda_runtime.h>
#include <cstdint>
#include <cstddef>

// ---------------------------------------------------------------------------
// FocusedLinearAttention — round 1 baseline
//   B=8, N=4096 (64x64), C=640, heads=5, HD=128, KS=5, FOCUS=3
// Pipeline:
//   1. v      = x2 @ Wq^T                         (sgemm_nt, f32x2)
//   2. k_raw  = x1 @ Wkv[0:640]^T                 (sgemm_nt)
//      q_raw  = x1 @ Wkv[640:1280]^T              (sgemm_nt)
//   3. softplus(scale) -> g_sc
//   4. focusing per row: relu/+eps/ /sc, cube, renorm (q; k with +pos_enc)
//   5. ksum, kv2 = K^T V per head (atomics over j-chunks), z = 1/(q.ksum+eps)
//   6. depthwise 5x5 conv of v -> g_x  (writes)
//   7. x += z * (q @ kv2)                         (attn_out, f32x2)
//   8. out = g_x @ Wproj^T + bproj                (sgemm_nt)
// ---------------------------------------------------------------------------

#define BATCH 8
#define SEQ   4096
#define CH    640
#define NH    5
#define HD    128
#define BH    (BATCH*NH)   // 40

// ---- scratch (device globals: allocation-free rule) ----
__device__ float g_v[BATCH*SEQ*CH];
__device__ float g_q[BATCH*SEQ*CH];
__device__ float g_k[BATCH*SEQ*CH];
__device__ float g_x[BATCH*SEQ*CH];
__device__ float g_kv2[BH*HD*HD];
__device__ float g_ksum[BH*HD];
__device__ float g_z[BH*SEQ];
__device__ float g_sc[CH];

// ---- packed f32x2 helpers (2x fp32 FMA throughput vs FFMA-3reg) ----
__device__ __forceinline__ unsigned long long pk2(float lo, float hi) {
    unsigned long long r;
    asm("mov.b64 %0, {%1, %2};" : "=l"(r) : "f"(lo), "f"(hi));
    return r;
}
__device__ __forceinline__ float2 upk(unsigned long long v) {
    float2 f;
    asm("mov.b64 {%0, %1}, %2;" : "=f"(f.x), "=f"(f.y) : "l"(v));
    return f;
}
#define FMA2(d, a, b) asm("fma.rn.f32x2 %0, %1, %2, %0;" : "+l"(d) : "l"(a), "l"(b))

// ---------------------------------------------------------------------------
// sgemm NT: C[m,n] = sum_k A[m*K+k] * Bw[n*K+k] (+ bias[n])
// Tiles: BM=128, BN=128, BK=16; 256 threads; 8x8 per thread via f32x2.
// Requires M%128==0, N%128==0, K%16==0 (all shapes here satisfy this).
// ---------------------------------------------------------------------------
__global__ __launch_bounds__(256) void sgemm_nt(
    const float* __restrict__ A, const float* __restrict__ Bw,
    float* __restrict__ C, const float* __restrict__ bias,
    int M, int Nc, int K)
{
    __shared__ float As[16][132];
    __shared__ float Bs[16][132];
    const int tid = threadIdx.x;
    const int tx = tid & 15, ty = tid >> 4;
    const int m0 = blockIdx.y * 128, n0 = blockIdx.x * 128;

    unsigned long long acc[8][4];
#pragma unroll
    for (int r = 0; r < 8; r++)
#pragma unroll
        for (int c = 0; c < 4; c++) acc[r][c] = 0ull;

    for (int k0 = 0; k0 < K; k0 += 16) {
#pragma unroll
        for (int i = 0; i < 2; i++) {
            int f = tid + i * 256;
            int m = f >> 2, kq = f & 3;
            float4 va = *reinterpret_cast<const float4*>(&A[(size_t)(m0 + m) * K + k0 + kq * 4]);
            As[kq*4+0][m] = va.x; As[kq*4+1][m] = va.y;
            As[kq*4+2][m] = va.z; As[kq*4+3][m] = va.w;
            float4 vb = *reinterpret_cast<const float4*>(&Bw[(size_t)(n0 + m) * K + k0 + kq * 4]);
            Bs[kq*4+0][m] = vb.x; Bs[kq*4+1][m] = vb.y;
            Bs[kq*4+2][m] = vb.z; Bs[kq*4+3][m] = vb.w;
        }
        __syncthreads();
#pragma unroll
        for (int kk = 0; kk < 16; kk++) {
            float4 a0 = *reinterpret_cast<const float4*>(&As[kk][ty * 4]);
            float4 a1 = *reinterpret_cast<const float4*>(&As[kk][64 + ty * 4]);
            unsigned long long ad[8];
            ad[0] = pk2(a0.x, a0.x); ad[1] = pk2(a0.y, a0.y);
            ad[2] = pk2(a0.z, a0.z); ad[3] = pk2(a0.w, a0.w);
            ad[4] = pk2(a1.x, a1.x); ad[5] = pk2(a1.y, a1.y);
            ad[6] = pk2(a1.z, a1.z); ad[7] = pk2(a1.w, a1.w);
            const unsigned long long* b0 =
                reinterpret_cast<const unsigned long long*>(&Bs[kk][tx * 4]);
            const unsigned long long* b1 =
                reinterpret_cast<const unsigned long long*>(&Bs[kk][64 + tx * 4]);
            unsigned long long bb[4] = { b0[0], b0[1], b1[0], b1[1] };
#pragma unroll
            for (int r = 0; r < 8; r++)
#pragma unroll
                for (int c = 0; c < 4; c++) FMA2(acc[r][c], ad[r], bb[c]);
        }
        __syncthreads();
    }
#pragma unroll
    for (int r = 0; r < 8; r++) {
        int m = m0 + ((r < 4) ? (ty * 4 + r) : (64 + ty * 4 + r - 4));
#pragma unroll
        for (int c = 0; c < 4; c++) {
            int n = n0 + ((c < 2) ? (tx * 4 + 2 * c) : (64 + tx * 4 + 2 * (c - 2)));
            float2 v = upk(acc[r][c]);
            float bv0 = bias ? bias[n] : 0.f;
            float bv1 = bias ? bias[n + 1] : 0.f;
            C[(size_t)m * Nc + n]     = v.x + bv0;
            C[(size_t)m * Nc + n + 1] = v.y + bv1;
        }
    }
}

// ---------------------------------------------------------------------------
// softplus(scale) -> g_sc
// ---------------------------------------------------------------------------
__global__ void softplus_kernel(const float* __restrict__ scale) {
    int c = blockIdx.x * 256 + threadIdx.x;
    if (c < CH) g_sc[c] = log1pf(expf(scale[c]));
}

// ---------------------------------------------------------------------------
// focusing: per (b,n) row over full C=640
//   v = (relu(raw)+eps)/sc ; n1=||v|| ; v=v^3 ; v = v/||v^3|| * n1
// q: raw = q_raw ;  k: raw = k_raw + pos_enc
// ---------------------------------------------------------------------------
__device__ __forceinline__ float block_sum(float v, float* red, int tid) {
    red[tid] = v;
    __syncthreads();
#pragma unroll
    for (int s = 128; s > 0; s >>= 1) {
        if (tid < s) red[tid] += red[tid + s];
        __syncthreads();
    }
    float r = red[0];
    __syncthreads();
    return r;
}

__global__ __launch_bounds__(256) void qknorm_kernel(const float* __restrict__ pos) {
    __shared__ float red[256];
    const int tid = threadIdx.x;
    const size_t row = blockIdx.x;            // 0..B*N-1
    const int n = (int)(row & (SEQ - 1));
    float* qrow = g_q + row * CH;
    float* krow = g_k + row * CH;
    const float* prow = pos + (size_t)n * CH;

    // ---- q ----
    {
        float v[3]; float s = 0.f;
#pragma unroll
        for (int j = 0; j < 3; j++) {
            int c = tid + j * 256;
            float val = 0.f;
            if (c < CH) {
                float raw = qrow[c];
                val = (fmaxf(raw, 0.f) + 1e-6f) / g_sc[c];
            }
            v[j] = val; s += val * val;
        }
        float n1 = sqrtf(block_sum(s, red, tid));
        s = 0.f;
#pragma unroll
        for (int j = 0; j < 3; j++) { float c3 = v[j]*v[j]*v[j]; v[j] = c3; s += c3 * c3; }
        float n2 = sqrtf(block_sum(s, red, tid));
        float sc2 = n1 / n2;
#pragma unroll
        for (int j = 0; j < 3; j++) {
            int c = tid + j * 256;
            if (c < CH) qrow[c] = v[j] * sc2;
        }
    }
    // ---- k (with pos_enc) ----
    {
        float v[3]; float s = 0.f;
#pragma unroll
        for (int j = 0; j < 3; j++) {
            int c = tid + j * 256;
            float val = 0.f;
            if (c < CH) {
                float raw = krow[c] + prow[c];
                val = (fmaxf(raw, 0.f) + 1e-6f) / g_sc[c];
            }
            v[j] = val; s += val * val;
        }
        float n1 = sqrtf(block_sum(s, red, tid));
        s = 0.f;
#pragma unroll
        for (int j = 0; j < 3; j++) { float c3 = v[j]*v[j]*v[j]; v[j] = c3; s += c3 * c3; }
        float n2 = sqrtf(block_sum(s, red, tid));
        float sc2 = n1 / n2;
#pragma unroll
        for (int j = 0; j < 3; j++) {
            int c = tid + j * 256;
            if (c < CH) krow[c] = v[j] * sc2;
        }
    }
}

// ---------------------------------------------------------------------------
// zero accumulators (must run every launch: device globals persist)
// ---------------------------------------------------------------------------
__global__ void zero_kernel() {
    int idx = blockIdx.x * 256 + threadIdx.x;
    if (idx < BH * HD * HD) g_kv2[idx] = 0.f;
    if (idx < BH * HD)      g_ksum[idx] = 0.f;
}

// ---------------------------------------------------------------------------
// ksum[bh][c] = sum_j k[bh][j][c]   (grid: 40 heads x 8 j-chunks, atomics)
// ---------------------------------------------------------------------------
__global__ __launch_bounds__(128) void ksum_kernel() {
    const int bh = blockIdx.x, jc = blockIdx.y;
    const int b = bh / NH, hoff = (bh % NH) * HD;
    const float* Kp = g_k + (size_t)b * SEQ * CH + hoff + threadIdx.x;
    const int j0 = jc * 512;
    float s = 0.f;
#pragma unroll 4
    for (int j = 0; j < 512; j++) s += Kp[(size_t)(j0 + j) * CH];
    atomicAdd(&g_ksum[bh * HD + threadIdx.x], s);
}

// ---------------------------------------------------------------------------
// kv2[bh][c][d] = sum_j k[bh][j][c] * v[bh][j][d]
// grid (40, 8 j-chunks of 512); 256 threads; 8x8/thread via f32x2; atomicAdd.
// ---------------------------------------------------------------------------
__global__ __launch_bounds__(256) void kv2_kernel() {
    const int bh = blockIdx.x, jc = blockIdx.y;
    const int b = bh / NH, hoff = (bh % NH) * HD;
    const float* Kp = g_k + (size_t)b * SEQ * CH + hoff;
    const float* Vp = g_v + (size_t)b * SEQ * CH + hoff;
    __shared__ float Ks[16][132];
    __shared__ float Vs[16][132];
    const int tid = threadIdx.x;
    const int tx = tid & 15, ty = tid >> 4;

    unsigned long long acc[8][4];
#pragma unroll
    for (int r = 0; r < 8; r++)
#pragma unroll
        for (int c = 0; c < 4; c++) acc[r][c] = 0ull;

    const int jbase = jc * 512;
    for (int j0 = jbase; j0 < jbase + 512; j0 += 16) {
#pragma unroll
        for (int i = 0; i < 2; i++) {
            int f = tid + i * 256;
            int jj = f >> 5, cq = f & 31;
            float4 kv4 = *reinterpret_cast<const float4*>(&Kp[(size_t)(j0 + jj) * CH + cq * 4]);
            *reinterpret_cast<float4*>(&Ks[jj][cq * 4]) = kv4;
            float4 vv4 = *reinterpret_cast<const float4*>(&Vp[(size_t)(j0 + jj) * CH + cq * 4]);
            *reinterpret_cast<float4*>(&Vs[jj][cq * 4]) = vv4;
        }
        __syncthreads();
#pragma unroll
        for (int jj = 0; jj < 16; jj++) {
            float4 a0 = *reinterpret_cast<const float4*>(&Ks[jj][ty * 4]);
            float4 a1 = *reinterpret_cast<const float4*>(&Ks[jj][64 + ty * 4]);
            unsigned long long ad[8];
            ad[0] = pk2(a0.x, a0.x); ad[1] = pk2(a0.y, a0.y);
            ad[2] = pk2(a0.z, a0.z); ad[3] = pk2(a0.w, a0.w);
            ad[4] = pk2(a1.x, a1.x); ad[5] = pk2(a1.y, a1.y);
            ad[6] = pk2(a1.z, a1.z); ad[7] = pk2(a1.w, a1.w);
            const unsigned long long* b0 =
                reinterpret_cast<const unsigned long long*>(&Vs[jj][tx * 4]);
            const unsigned long long* b1 =
                reinterpret_cast<const unsigned long long*>(&Vs[jj][64 + tx * 4]);
            unsigned long long bb[4] = { b0[0], b0[1], b1[0], b1[1] };
#pragma unroll
            for (int r = 0; r < 8; r++)
#pragma unroll
                for (int c = 0; c < 4; c++) FMA2(acc[r][c], ad[r], bb[c]);
        }
        __syncthreads();
    }
    float* dst = g_kv2 + bh * HD * HD;
#pragma unroll
    for (int r = 0; r < 8; r++) {
        int cdx = (r < 4) ? (ty * 4 + r) : (64 + ty * 4 + r - 4);
#pragma unroll
        for (int c = 0; c < 4; c++) {
            int ddx = (c < 2) ? (tx * 4 + 2 * c) : (64 + tx * 4 + 2 * (c - 2));
            float2 v = upk(acc[r][c]);
            atomicAdd(&dst[cdx * HD + ddx], v.x);
            atomicAdd(&dst[cdx * HD + ddx + 1], v.y);
        }
    }
}

// ---------------------------------------------------------------------------
// z[bh][i] = 1 / (dot(q[bh][i], ksum[bh]) + eps)   (one warp per row)
// ---------------------------------------------------------------------------
__global__ __launch_bounds__(256) void zrow_kernel() {
    const int gw = blockIdx.x * 8 + (threadIdx.x >> 5);
    const int lane = threadIdx.x & 31;
    const int bh = gw >> 12;           // /4096
    const int i = gw & (SEQ - 1);
    const int b = bh / NH, hoff = (bh % NH) * HD;
    const float* qrow = g_q + (size_t)(b * SEQ + i) * CH + hoff;
    const float* ks = g_ksum + bh * HD;
    float s = 0.f;
#pragma unroll
    for (int t = 0; t < 4; t++) s += qrow[lane + 32 * t] * ks[lane + 32 * t];
#pragma unroll
    for (int o = 16; o > 0; o >>= 1) s += __shfl_xor_sync(0xffffffffu, s, o);
    if (lane == 0) g_z[bh * SEQ + i] = 1.f / (s + 1e-6f);
}

// ---------------------------------------------------------------------------
// depthwise 5x5 conv of v (per head, channel-fastest) -> writes g_x (+bias)
// one thread per output element; idx = ((bh*64+y)*64+x)*128+d
// ---------------------------------------------------------------------------
__global__ __launch_bounds__(256) void conv_kernel(
    const float* __restrict__ w, const float* __restrict__ bias)
{
    __shared__ float ws[HD * 25];
    for (int t = threadIdx.x; t < HD * 25; t += 256) ws[t] = w[t];
    __syncthreads();

    const int idx = blockIdx.x * 256 + threadIdx.x;
    const int d  = idx & 127;
    const int x  = (idx >> 7) & 63;
    const int y  = (idx >> 13) & 63;
    const int bh = idx >> 19;
    const int b = bh / NH, hoff = (bh % NH) * HD;
    const float* vb = g_v + (size_t)b * SEQ * CH + hoff + d;

    float acc = bias[d];
#pragma unroll
    for (int ky = 0; ky < 5; ky++) {
        int iy = y + ky - 2;
        if ((unsigned)iy < 64u) {
#pragma unroll
            for (int kx = 0; kx < 5; kx++) {
                int ix = x + kx - 2;
                if ((unsigned)ix < 64u)
                    acc += ws[d * 25 + ky * 5 + kx] * vb[(size_t)(iy * 64 + ix) * CH];
            }
        }
    }
    g_x[(size_t)(b * SEQ + y * 64 + x) * CH + hoff + d] = acc;
}

// ---------------------------------------------------------------------------
// attn out: g_x[b, i, hoff+d] += z[bh,i] * sum_c q[b,i,hoff+c] * kv2[bh,c,d]
// grid (40 heads, 32 row-tiles of 128); NN gemm, K=128; f32x2 core.
// ---------------------------------------------------------------------------
__global__ __launch_bounds__(256) void attn_out_kernel() {
    const int bh = blockIdx.x;
    const int i0 = blockIdx.y * 128;
    const int b = bh / NH, hoff = (bh % NH) * HD;
    const float* Qp = g_q + (size_t)b * SEQ * CH + hoff;
    const float* K2 = g_kv2 + bh * HD * HD;
    __shared__ float Qs[16][132];
    __shared__ float Bs[16][132];
    const int tid = threadIdx.x;
    const int tx = tid & 15, ty = tid >> 4;

    unsigned long long acc[8][4];
#pragma unroll
    for (int r = 0; r < 8; r++)
#pragma unroll
        for (int c = 0; c < 4; c++) acc[r][c] = 0ull;

    for (int k0 = 0; k0 < HD; k0 += 16) {
#pragma unroll
        for (int i = 0; i < 2; i++) {
            int f = tid + i * 256;
            int m = f >> 2, kq = f & 3;
            float4 va = *reinterpret_cast<const float4*>(
                &Qp[(size_t)(i0 + m) * CH + k0 + kq * 4]);
            Qs[kq*4+0][m] = va.x; Qs[kq*4+1][m] = va.y;
            Qs[kq*4+2][m] = va.z; Qs[kq*4+3][m] = va.w;
            int kk = f >> 5, dq = f & 31;
            float4 vb = *reinterpret_cast<const float4*>(&K2[(k0 + kk) * HD + dq * 4]);
            *reinterpret_cast<float4*>(&Bs[kk][dq * 4]) = vb;
        }
        __syncthreads();
#pragma unroll
        for (int kk = 0; kk < 16; kk++) {
            float4 a0 = *reinterpret_cast<const float4*>(&Qs[kk][ty * 4]);
            float4 a1 = *reinterpret_cast<const float4*>(&Qs[kk][64 + ty * 4]);
            unsigned long long ad[8];
            ad[0] = pk2(a0.x, a0.x); ad[1] = pk2(a0.y, a0.y);
            ad[2] = pk2(a0.z, a0.z); ad[3] = pk2(a0.w, a0.w);
            ad[4] = pk2(a1.x, a1.x); ad[5] = pk2(a1.y, a1.y);
            ad[6] = pk2(a1.z, a1.z); ad[7] = pk2(a1.w, a1.w);
            const unsigned long long* b0 =
                reinterpret_cast<const unsigned long long*>(&Bs[kk][tx * 4]);
            const unsigned long long* b1 =
                reinterpret_cast<const unsigned long long*>(&Bs[kk][64 + tx * 4]);
            unsigned long long bb[4] = { b0[0], b0[1], b1[0], b1[1] };
#pragma unroll
            for (int r = 0; r < 8; r++)
#pragma unroll
                for (int c = 0; c < 4; c++) FMA2(acc[r][c], ad[r], bb[c]);
        }
        __syncthreads();
    }
#pragma unroll
    for (int r = 0; r < 8; r++) {
        int m = i0 + ((r < 4) ? (ty * 4 + r) : (64 + ty * 4 + r - 4));
        float zv = g_z[bh * SEQ + m];
        float* orow = g_x + (size_t)(b * SEQ + m) * CH + hoff;
#pragma unroll
        for (int c = 0; c < 4; c++) {
            int n = (c < 2) ? (tx * 4 + 2 * c) : (64 + tx * 4 + 2 * (c - 2));
            float2 v = upk(acc[r][c]);
            orow[n]     += v.x * zv;
            orow[n + 1] += v.y * zv;
        }
    }
}

// ---------------------------------------------------------------------------
// launch
// ---------------------------------------------------------------------------
extern "C" void kernel_launch(void* const* d_in, const int* in_sizes, int n_in,
                              void* d_out, int out_size)
{
    const float* x1    = (const float*)d_in[0];
    const float* x2    = (const float*)d_in[1];
    const float* Wq    = (const float*)d_in[2];
    const float* Wkv   = (const float*)d_in[3];
    const float* Wproj = (const float*)d_in[4];
    const float* bproj = (const float*)d_in[5];
    const float* dwc_w = (const float*)d_in[6];
    const float* dwc_b = (const float*)d_in[7];
    const float* scale = (const float*)d_in[8];
    const float* pos   = (const float*)d_in[9];
    float* out = (float*)d_out;

    float *pv, *pq, *pk, *px;
    cudaGetSymbolAddress((void**)&pv, g_v);
    cudaGetSymbolAddress((void**)&pq, g_q);
    cudaGetSymbolAddress((void**)&pk, g_k);
    cudaGetSymbolAddress((void**)&px, g_x);

    const int M = BATCH * SEQ;                 // 32768
    dim3 gg(CH / 128, M / 128);                // (5, 256)

    sgemm_nt<<<gg, 256>>>(x2, Wq, pv, nullptr, M, CH, CH);               // v
    sgemm_nt<<<gg, 256>>>(x1, Wkv, pk, nullptr, M, CH, CH);              // k_raw
    sgemm_nt<<<gg, 256>>>(x1, Wkv + CH * CH, pq, nullptr, M, CH, CH);    // q_raw
    softplus_kernel<<<3, 256>>>(scale);
    qknorm_kernel<<<M, 256>>>(pos);
    zero_kernel<<<(BH * HD * HD + 255) / 256, 256>>>();
    ksum_kernel<<<dim3(BH, 8), 128>>>();
    kv2_kernel<<<dim3(BH, 8), 256>>>();
    zrow_kernel<<<BH * SEQ / 8, 256>>>();
    conv_kernel<<<(BH * SEQ * HD) / 256, 256>>>(dwc_w, dwc_b);
    attn_out_kernel<<<dim3(BH, SEQ / 128), 256>>>();
    sgemm_nt<<<gg, 256>>>(px, Wproj, out, bproj, M, CH, CH);             // proj
}

// round 3
// speedup vs baseline: 1.0586x; 1.0586x over previous
#include <cuda_runtime.h>
#include <cstdint>
#include <cstddef>

// ---------------------------------------------------------------------------
// FocusedLinearAttention — round 3: warp-level mma.sync tf32 (3xTF32) GEMMs
//   (PTX target is sm_100 without 'a': tcgen05 unavailable, mma.sync is)
//   B=8, N=4096 (64x64), C=640, heads=5, HD=128, KS=5, FOCUS=3
// ---------------------------------------------------------------------------

#define BATCH 8
#define SEQ   4096
#define CH    640
#define NH    5
#define HD    128
#define BH    (BATCH*NH)   // 40

#define BMM 128
#define BNN 128
#define BK32 32                // K floats per chunk
#define NCH  (CH/BK32)         // 20
#define ROWW 36                // floats per row (32 + 4 pad), 144B
#define ABUF (128*ROWW)        // floats per buffer (A or B, hi or lo)
#define STAGEF (4*ABUF)        // floats per stage {Ah, Al, Bh, Bl}
#define SMEM_GEMM (2*STAGEF*4) // bytes = 147456

// ---- scratch (device globals: allocation-free rule) ----
__device__ float g_v[BATCH*SEQ*CH];
__device__ float g_q[BATCH*SEQ*CH];
__device__ float g_k[BATCH*SEQ*CH];
__device__ float g_x[BATCH*SEQ*CH];
__device__ float g_ahi[BATCH*SEQ*CH];
__device__ float g_alo[BATCH*SEQ*CH];
__device__ float g_wh[2560*CH];
__device__ float g_wl[2560*CH];
__device__ float g_kv2[BH*HD*HD];
__device__ float g_ksum[BH*HD];
__device__ float g_z[BH*SEQ];
__device__ float g_sc[CH];

// ---------------------------------------------------------------------------
// helpers
// ---------------------------------------------------------------------------
__device__ __forceinline__ float tf32_rn(float x) {
    uint32_t u;
    asm("cvt.rna.tf32.f32 %0, %1;" : "=r"(u) : "f"(x));
    return __uint_as_float(u);
}
__device__ __forceinline__ void cp16(uint32_t dst, const void* src) {
    asm volatile("cp.async.cg.shared.global [%0], [%1], 16;" :: "r"(dst), "l"(src));
}

#define MMA_TF32(d, A, B) \
    asm volatile( \
        "mma.sync.aligned.m16n8k8.row.col.f32.tf32.tf32.f32 " \
        "{%0,%1,%2,%3}, {%4,%5,%6,%7}, {%8,%9}, {%0,%1,%2,%3};" \
        : "+f"((d)[0]), "+f"((d)[1]), "+f"((d)[2]), "+f"((d)[3]) \
        : "r"((A)[0]), "r"((A)[1]), "r"((A)[2]), "r"((A)[3]), \
          "r"((B)[0]), "r"((B)[1]))

// ---------------------------------------------------------------------------
// split: x -> (hi = tf32_rn(x), lo = tf32_rn(x - hi)) ; n4 = count/4
// ---------------------------------------------------------------------------
__global__ __launch_bounds__(256) void split_kernel(
    const float* __restrict__ src, float* __restrict__ hi,
    float* __restrict__ lo, int n4)
{
    int i = blockIdx.x * 256 + threadIdx.x;
    if (i >= n4) return;
    float4 v = reinterpret_cast<const float4*>(src)[i];
    float4 h, l;
    h.x = tf32_rn(v.x); l.x = tf32_rn(v.x - h.x);
    h.y = tf32_rn(v.y); l.y = tf32_rn(v.y - h.y);
    h.z = tf32_rn(v.z); l.z = tf32_rn(v.z - h.z);
    h.w = tf32_rn(v.w); l.w = tf32_rn(v.w - h.w);
    reinterpret_cast<float4*>(hi)[i] = h;
    reinterpret_cast<float4*>(lo)[i] = l;
}

// ---------------------------------------------------------------------------
// mma.sync tf32 GEMM: C[m,n] = sum_k (Ah+Al)[m,k]*(Bh+Bl)[n,k] (+bias[n])
// grid(5, 256), 256 threads, 144KB dyn smem, 2-stage cp.async pipeline.
// Warp layout 4x2 (warp tile 32x64); mma m16n8k8; 3 passes hi*hi, hi*lo, lo*hi.
// ---------------------------------------------------------------------------
__global__ __launch_bounds__(256, 1) void gemm_mma(
    const float* __restrict__ Ah, const float* __restrict__ Al,
    const float* __restrict__ Bh, const float* __restrict__ Bl,
    float* __restrict__ C, const float* __restrict__ bias)
{
    extern __shared__ float smem[];
    const uint32_t sb = (uint32_t)__cvta_generic_to_shared(smem);
    const int tid = threadIdx.x;
    const int m0 = blockIdx.y * BMM;
    const int n0 = blockIdx.x * BNN;

    const int lane = tid & 31;
    const int wid = tid >> 5;
    const int warp_m = wid >> 1;         // 0..3 -> 32 rows each
    const int warp_n = wid & 1;          // 0..1 -> 64 cols each
    const int gid = lane >> 2;           // 0..7
    const int tig = lane & 3;            // 0..3

    float acc[2][8][4];
#pragma unroll
    for (int t = 0; t < 2; t++)
#pragma unroll
        for (int j = 0; j < 8; j++)
#pragma unroll
            for (int e = 0; e < 4; e++) acc[t][j][e] = 0.f;

    // ---- async fill of one stage with chunk c ----
    auto fill = [&](int stage, int chunk) {
        const int k0 = chunk * BK32;
        const uint32_t stb = sb + (uint32_t)(stage * STAGEF * 4);
#pragma unroll
        for (int t = 0; t < 4; t++) {
            int u = tid + t * 256;
            int r = u >> 3, c = u & 7;
            uint32_t off = (uint32_t)(r * 144 + c * 16);
            size_t ga = (size_t)(m0 + r) * CH + k0 + c * 4;
            size_t gb = (size_t)(n0 + r) * CH + k0 + c * 4;
            cp16(stb + off,                 Ah + ga);
            cp16(stb + ABUF * 4 + off,      Al + ga);
            cp16(stb + ABUF * 8 + off,      Bh + gb);
            cp16(stb + ABUF * 12 + off,     Bl + gb);
        }
        asm volatile("cp.async.commit_group;" ::: "memory");
    };

    fill(0, 0);
    for (int i = 0; i < NCH; i++) {
        if (i + 1 < NCH) fill((i + 1) & 1, i + 1);
        if (i + 1 < NCH) asm volatile("cp.async.wait_group 1;" ::: "memory");
        else             asm volatile("cp.async.wait_group 0;" ::: "memory");
        __syncthreads();

        const float* As  = smem + (i & 1) * STAGEF;
        const float* Als = As + ABUF;
        const float* Bs  = As + 2 * ABUF;
        const float* Bls = As + 3 * ABUF;
#pragma unroll
        for (int ks = 0; ks < 4; ks++) {
            const int kb = ks * 8 + tig;
            uint32_t ah[2][4], al[2][4];
#pragma unroll
            for (int t = 0; t < 2; t++) {
                int r0 = warp_m * 32 + t * 16 + gid;
                ah[t][0] = __float_as_uint(As[r0 * ROWW + kb]);
                ah[t][1] = __float_as_uint(As[(r0 + 8) * ROWW + kb]);
                ah[t][2] = __float_as_uint(As[r0 * ROWW + kb + 4]);
                ah[t][3] = __float_as_uint(As[(r0 + 8) * ROWW + kb + 4]);
                al[t][0] = __float_as_uint(Als[r0 * ROWW + kb]);
                al[t][1] = __float_as_uint(Als[(r0 + 8) * ROWW + kb]);
                al[t][2] = __float_as_uint(Als[r0 * ROWW + kb + 4]);
                al[t][3] = __float_as_uint(Als[(r0 + 8) * ROWW + kb + 4]);
            }
            uint32_t bh[8][2], bl[8][2];
#pragma unroll
            for (int j = 0; j < 8; j++) {
                int n = warp_n * 64 + j * 8 + gid;
                bh[j][0] = __float_as_uint(Bs[n * ROWW + kb]);
                bh[j][1] = __float_as_uint(Bs[n * ROWW + kb + 4]);
                bl[j][0] = __float_as_uint(Bls[n * ROWW + kb]);
                bl[j][1] = __float_as_uint(Bls[n * ROWW + kb + 4]);
            }
#pragma unroll
            for (int t = 0; t < 2; t++)
#pragma unroll
                for (int j = 0; j < 8; j++) {
                    MMA_TF32(acc[t][j], ah[t], bh[j]);
                    MMA_TF32(acc[t][j], ah[t], bl[j]);
                    MMA_TF32(acc[t][j], al[t], bh[j]);
                }
        }
        __syncthreads();
    }

    // ---- epilogue: direct stores (float2 per frag row) ----
#pragma unroll
    for (int t = 0; t < 2; t++) {
        int r0 = m0 + warp_m * 32 + t * 16 + gid;
#pragma unroll
        for (int j = 0; j < 8; j++) {
            int cc = n0 + warp_n * 64 + j * 8 + 2 * tig;
            float b0 = bias ? bias[cc] : 0.f;
            float b1 = bias ? bias[cc + 1] : 0.f;
            float2 v0 = make_float2(acc[t][j][0] + b0, acc[t][j][1] + b1);
            float2 v1 = make_float2(acc[t][j][2] + b0, acc[t][j][3] + b1);
            *reinterpret_cast<float2*>(&C[(size_t)r0 * CH + cc]) = v0;
            *reinterpret_cast<float2*>(&C[(size_t)(r0 + 8) * CH + cc]) = v1;
        }
    }
}

// ---------------------------------------------------------------------------
// softplus(scale) -> g_sc
// ---------------------------------------------------------------------------
__global__ void softplus_kernel(const float* __restrict__ scale) {
    int c = blockIdx.x * 256 + threadIdx.x;
    if (c < CH) g_sc[c] = log1pf(expf(scale[c]));
}

// ---------------------------------------------------------------------------
// focusing
// ---------------------------------------------------------------------------
__device__ __forceinline__ float block_sum(float v, float* red, int tid) {
    red[tid] = v;
    __syncthreads();
#pragma unroll
    for (int s = 128; s > 0; s >>= 1) {
        if (tid < s) red[tid] += red[tid + s];
        __syncthreads();
    }
    float r = red[0];
    __syncthreads();
    return r;
}

__global__ __launch_bounds__(256) void qknorm_kernel(const float* __restrict__ pos) {
    __shared__ float red[256];
    const int tid = threadIdx.x;
    const size_t row = blockIdx.x;
    const int n = (int)(row & (SEQ - 1));
    float* qrow = g_q + row * CH;
    float* krow = g_k + row * CH;
    const float* prow = pos + (size_t)n * CH;
    {
        float v[3]; float s = 0.f;
#pragma unroll
        for (int j = 0; j < 3; j++) {
            int c = tid + j * 256;
            float val = 0.f;
            if (c < CH) {
                float raw = qrow[c];
                val = (fmaxf(raw, 0.f) + 1e-6f) / g_sc[c];
            }
            v[j] = val; s += val * val;
        }
        float n1 = sqrtf(block_sum(s, red, tid));
        s = 0.f;
#pragma unroll
        for (int j = 0; j < 3; j++) { float c3 = v[j]*v[j]*v[j]; v[j] = c3; s += c3 * c3; }
        float n2 = sqrtf(block_sum(s, red, tid));
        float sc2 = n1 / n2;
#pragma unroll
        for (int j = 0; j < 3; j++) {
            int c = tid + j * 256;
            if (c < CH) qrow[c] = v[j] * sc2;
        }
    }
    {
        float v[3]; float s = 0.f;
#pragma unroll
        for (int j = 0; j < 3; j++) {
            int c = tid + j * 256;
            float val = 0.f;
            if (c < CH) {
                float raw = krow[c] + prow[c];
                val = (fmaxf(raw, 0.f) + 1e-6f) / g_sc[c];
            }
            v[j] = val; s += val * val;
        }
        float n1 = sqrtf(block_sum(s, red, tid));
        s = 0.f;
#pragma unroll
        for (int j = 0; j < 3; j++) { float c3 = v[j]*v[j]*v[j]; v[j] = c3; s += c3 * c3; }
        float n2 = sqrtf(block_sum(s, red, tid));
        float sc2 = n1 / n2;
#pragma unroll
        for (int j = 0; j < 3; j++) {
            int c = tid + j * 256;
            if (c < CH) krow[c] = v[j] * sc2;
        }
    }
}

__global__ void zero_kernel() {
    int idx = blockIdx.x * 256 + threadIdx.x;
    if (idx < BH * HD * HD) g_kv2[idx] = 0.f;
    if (idx < BH * HD)      g_ksum[idx] = 0.f;
}

__global__ __launch_bounds__(128) void ksum_kernel() {
    const int bh = blockIdx.x, jc = blockIdx.y;
    const int b = bh / NH, hoff = (bh % NH) * HD;
    const float* Kp = g_k + (size_t)b * SEQ * CH + hoff + threadIdx.x;
    const int j0 = jc * 512;
    float s = 0.f;
#pragma unroll 4
    for (int j = 0; j < 512; j++) s += Kp[(size_t)(j0 + j) * CH];
    atomicAdd(&g_ksum[bh * HD + threadIdx.x], s);
}

// ---- packed f32x2 helpers ----
__device__ __forceinline__ unsigned long long pk2(float lo, float hi) {
    unsigned long long r;
    asm("mov.b64 %0, {%1, %2};" : "=l"(r) : "f"(lo), "f"(hi));
    return r;
}
__device__ __forceinline__ float2 upk(unsigned long long v) {
    float2 f;
    asm("mov.b64 {%0, %1}, %2;" : "=f"(f.x), "=f"(f.y) : "l"(v));
    return f;
}
#define FMA2(d, a, b) asm("fma.rn.f32x2 %0, %1, %2, %0;" : "+l"(d) : "l"(a), "l"(b))

__global__ __launch_bounds__(256) void kv2_kernel() {
    const int bh = blockIdx.x, jc = blockIdx.y;
    const int b = bh / NH, hoff = (bh % NH) * HD;
    const float* Kp = g_k + (size_t)b * SEQ * CH + hoff;
    const float* Vp = g_v + (size_t)b * SEQ * CH + hoff;
    __shared__ float Ks[16][132];
    __shared__ float Vs[16][132];
    const int tid = threadIdx.x;
    const int tx = tid & 15, ty = tid >> 4;

    unsigned long long acc[8][4];
#pragma unroll
    for (int r = 0; r < 8; r++)
#pragma unroll
        for (int c = 0; c < 4; c++) acc[r][c] = 0ull;

    const int jbase = jc * 512;
    for (int j0 = jbase; j0 < jbase + 512; j0 += 16) {
#pragma unroll
        for (int i = 0; i < 2; i++) {
            int f = tid + i * 256;
            int jj = f >> 5, cq = f & 31;
            float4 kv4 = *reinterpret_cast<const float4*>(&Kp[(size_t)(j0 + jj) * CH + cq * 4]);
            *reinterpret_cast<float4*>(&Ks[jj][cq * 4]) = kv4;
            float4 vv4 = *reinterpret_cast<const float4*>(&Vp[(size_t)(j0 + jj) * CH + cq * 4]);
            *reinterpret_cast<float4*>(&Vs[jj][cq * 4]) = vv4;
        }
        __syncthreads();
#pragma unroll
        for (int jj = 0; jj < 16; jj++) {
            float4 a0 = *reinterpret_cast<const float4*>(&Ks[jj][ty * 4]);
            float4 a1 = *reinterpret_cast<const float4*>(&Ks[jj][64 + ty * 4]);
            unsigned long long ad[8];
            ad[0] = pk2(a0.x, a0.x); ad[1] = pk2(a0.y, a0.y);
            ad[2] = pk2(a0.z, a0.z); ad[3] = pk2(a0.w, a0.w);
            ad[4] = pk2(a1.x, a1.x); ad[5] = pk2(a1.y, a1.y);
            ad[6] = pk2(a1.z, a1.z); ad[7] = pk2(a1.w, a1.w);
            const unsigned long long* b0 =
                reinterpret_cast<const unsigned long long*>(&Vs[jj][tx * 4]);
            const unsigned long long* b1 =
                reinterpret_cast<const unsigned long long*>(&Vs[jj][64 + tx * 4]);
            unsigned long long bb[4] = { b0[0], b0[1], b1[0], b1[1] };
#pragma unroll
            for (int r = 0; r < 8; r++)
#pragma unroll
                for (int c = 0; c < 4; c++) FMA2(acc[r][c], ad[r], bb[c]);
        }
        __syncthreads();
    }
    float* dst = g_kv2 + bh * HD * HD;
#pragma unroll
    for (int r = 0; r < 8; r++) {
        int cdx = (r < 4) ? (ty * 4 + r) : (64 + ty * 4 + r - 4);
#pragma unroll
        for (int c = 0; c < 4; c++) {
            int ddx = (c < 2) ? (tx * 4 + 2 * c) : (64 + tx * 4 + 2 * (c - 2));
            float2 v = upk(acc[r][c]);
            atomicAdd(&dst[cdx * HD + ddx], v.x);
            atomicAdd(&dst[cdx * HD + ddx + 1], v.y);
        }
    }
}

__global__ __launch_bounds__(256) void zrow_kernel() {
    const int gw = blockIdx.x * 8 + (threadIdx.x >> 5);
    const int lane = threadIdx.x & 31;
    const int bh = gw >> 12;
    const int i = gw & (SEQ - 1);
    const int b = bh / NH, hoff = (bh % NH) * HD;
    const float* qrow = g_q + (size_t)(b * SEQ + i) * CH + hoff;
    const float* ks = g_ksum + bh * HD;
    float s = 0.f;
#pragma unroll
    for (int t = 0; t < 4; t++) s += qrow[lane + 32 * t] * ks[lane + 32 * t];
#pragma unroll
    for (int o = 16; o > 0; o >>= 1) s += __shfl_xor_sync(0xffffffffu, s, o);
    if (lane == 0) g_z[bh * SEQ + i] = 1.f / (s + 1e-6f);
}

__global__ __launch_bounds__(256) void conv_kernel(
    const float* __restrict__ w, const float* __restrict__ bias)
{
    __shared__ float ws[HD * 25];
    for (int t = threadIdx.x; t < HD * 25; t += 256) ws[t] = w[t];
    __syncthreads();

    const int idx = blockIdx.x * 256 + threadIdx.x;
    const int d  = idx & 127;
    const int x  = (idx >> 7) & 63;
    const int y  = (idx >> 13) & 63;
    const int bh = idx >> 19;
    const int b = bh / NH, hoff = (bh % NH) * HD;
    const float* vb = g_v + (size_t)b * SEQ * CH + hoff + d;

    float acc = bias[d];
#pragma unroll
    for (int ky = 0; ky < 5; ky++) {
        int iy = y + ky - 2;
        if ((unsigned)iy < 64u) {
#pragma unroll
            for (int kx = 0; kx < 5; kx++) {
                int ix = x + kx - 2;
                if ((unsigned)ix < 64u)
                    acc += ws[d * 25 + ky * 5 + kx] * vb[(size_t)(iy * 64 + ix) * CH];
            }
        }
    }
    g_x[(size_t)(b * SEQ + y * 64 + x) * CH + hoff + d] = acc;
}

__global__ __launch_bounds__(256) void attn_out_kernel() {
    const int bh = blockIdx.x;
    const int i0 = blockIdx.y * 128;
    const int b = bh / NH, hoff = (bh % NH) * HD;
    const float* Qp = g_q + (size_t)b * SEQ * CH + hoff;
    const float* K2 = g_kv2 + bh * HD * HD;
    __shared__ float Qs[16][132];
    __shared__ float Bs[16][132];
    const int tid = threadIdx.x;
    const int tx = tid & 15, ty = tid >> 4;

    unsigned long long acc[8][4];
#pragma unroll
    for (int r = 0; r < 8; r++)
#pragma unroll
        for (int c = 0; c < 4; c++) acc[r][c] = 0ull;

    for (int k0 = 0; k0 < HD; k0 += 16) {
#pragma unroll
        for (int i = 0; i < 2; i++) {
            int f = tid + i * 256;
            int m = f >> 2, kq = f & 3;
            float4 va = *reinterpret_cast<const float4*>(
                &Qp[(size_t)(i0 + m) * CH + k0 + kq * 4]);
            Qs[kq*4+0][m] = va.x; Qs[kq*4+1][m] = va.y;
            Qs[kq*4+2][m] = va.z; Qs[kq*4+3][m] = va.w;
            int kk = f >> 5, dq = f & 31;
            float4 vb = *reinterpret_cast<const float4*>(&K2[(k0 + kk) * HD + dq * 4]);
            *reinterpret_cast<float4*>(&Bs[kk][dq * 4]) = vb;
        }
        __syncthreads();
#pragma unroll
        for (int kk = 0; kk < 16; kk++) {
            float4 a0 = *reinterpret_cast<const float4*>(&Qs[kk][ty * 4]);
            float4 a1 = *reinterpret_cast<const float4*>(&Qs[kk][64 + ty * 4]);
            unsigned long long ad[8];
            ad[0] = pk2(a0.x, a0.x); ad[1] = pk2(a0.y, a0.y);
            ad[2] = pk2(a0.z, a0.z); ad[3] = pk2(a0.w, a0.w);
            ad[4] = pk2(a1.x, a1.x); ad[5] = pk2(a1.y, a1.y);
            ad[6] = pk2(a1.z, a1.z); ad[7] = pk2(a1.w, a1.w);
            const unsigned long long* b0 =
                reinterpret_cast<const unsigned long long*>(&Bs[kk][tx * 4]);
            const unsigned long long* b1 =
                reinterpret_cast<const unsigned long long*>(&Bs[kk][64 + tx * 4]);
            unsigned long long bb[4] = { b0[0], b0[1], b1[0], b1[1] };
#pragma unroll
            for (int r = 0; r < 8; r++)
#pragma unroll
                for (int c = 0; c < 4; c++) FMA2(acc[r][c], ad[r], bb[c]);
        }
        __syncthreads();
    }
#pragma unroll
    for (int r = 0; r < 8; r++) {
        int m = i0 + ((r < 4) ? (ty * 4 + r) : (64 + ty * 4 + r - 4));
        float zv = g_z[bh * SEQ + m];
        float* orow = g_x + (size_t)(b * SEQ + m) * CH + hoff;
#pragma unroll
        for (int c = 0; c < 4; c++) {
            int n = (c < 2) ? (tx * 4 + 2 * c) : (64 + tx * 4 + 2 * (c - 2));
            float2 v = upk(acc[r][c]);
            orow[n]     += v.x * zv;
            orow[n + 1] += v.y * zv;
        }
    }
}

// ---------------------------------------------------------------------------
// launch
// ---------------------------------------------------------------------------
extern "C" void kernel_launch(void* const* d_in, const int* in_sizes, int n_in,
                              void* d_out, int out_size)
{
    const float* x1    = (const float*)d_in[0];
    const float* x2    = (const float*)d_in[1];
    const float* Wq    = (const float*)d_in[2];
    const float* Wkv   = (const float*)d_in[3];
    const float* Wproj = (const float*)d_in[4];
    const float* bproj = (const float*)d_in[5];
    const float* dwc_w = (const float*)d_in[6];
    const float* dwc_b = (const float*)d_in[7];
    const float* scale = (const float*)d_in[8];
    const float* pos   = (const float*)d_in[9];
    float* out = (float*)d_out;

    float *pv, *pq, *pk, *px, *pah, *pal, *pwh, *pwl;
    cudaGetSymbolAddress((void**)&pv, g_v);
    cudaGetSymbolAddress((void**)&pq, g_q);
    cudaGetSymbolAddress((void**)&pk, g_k);
    cudaGetSymbolAddress((void**)&px, g_x);
    cudaGetSymbolAddress((void**)&pah, g_ahi);
    cudaGetSymbolAddress((void**)&pal, g_alo);
    cudaGetSymbolAddress((void**)&pwh, g_wh);
    cudaGetSymbolAddress((void**)&pwl, g_wl);

    cudaFuncSetAttribute(gemm_mma,
        cudaFuncAttributeMaxDynamicSharedMemorySize, SMEM_GEMM);

    const int M = BATCH * SEQ;              // 32768
    const int XN4 = M * CH / 4;             // 5242880
    dim3 gg(CH / BNN, M / BMM);             // (5, 256)

    // weight splits: Wq at 0, Wkv at 409600, Wproj at 1228800 (floats)
    split_kernel<<<CH*CH/1024, 256>>>(Wq, pwh, pwl, CH*CH/4);
    split_kernel<<<2*CH*CH/1024, 256>>>(Wkv, pwh + CH*CH, pwl + CH*CH, 2*CH*CH/4);
    split_kernel<<<CH*CH/1024, 256>>>(Wproj, pwh + 3*CH*CH, pwl + 3*CH*CH, CH*CH/4);
    softplus_kernel<<<3, 256>>>(scale);

    // v = x2 @ Wq^T
    split_kernel<<<XN4/256, 256>>>(x2, pah, pal, XN4);
    gemm_mma<<<gg, 256, SMEM_GEMM>>>(pah, pal, pwh, pwl, pv, nullptr);

    // k_raw = x1 @ Wkv[0:640]^T ; q_raw = x1 @ Wkv[640:1280]^T
    split_kernel<<<XN4/256, 256>>>(x1, pah, pal, XN4);
    gemm_mma<<<gg, 256, SMEM_GEMM>>>(pah, pal, pwh + CH*CH, pwl + CH*CH, pk, nullptr);
    gemm_mma<<<gg, 256, SMEM_GEMM>>>(pah, pal, pwh + 2*CH*CH, pwl + 2*CH*CH, pq, nullptr);

    qknorm_kernel<<<M, 256>>>(pos);
    zero_kernel<<<(BH * HD * HD + 255) / 256, 256>>>();
    ksum_kernel<<<dim3(BH, 8), 128>>>();
    kv2_kernel<<<dim3(BH, 8), 256>>>();
    zrow_kernel<<<BH * SEQ / 8, 256>>>();
    conv_kernel<<<(BH * SEQ * HD) / 256, 256>>>(dwc_w, dwc_b);
    attn_out_kernel<<<dim3(BH, SEQ / 128), 256>>>();

    // out = g_x @ Wproj^T + bproj
    split_kernel<<<XN4/256, 256>>>(px, pah, pal, XN4);
    gemm_mma<<<gg, 256, SMEM_GEMM>>>(pah, pal, pwh + 3*CH*CH, pwl + 3*CH*CH, out, bproj);
}

// round 4
// speedup vs baseline: 1.6584x; 1.5665x over previous
#include <cuda_runtime.h>
#include <cuda_bf16.h>
#include <cstdint>
#include <cstddef>

// ---------------------------------------------------------------------------
// FocusedLinearAttention — round 4: bf16x3 mma.m16n8k16 GEMMs + smem conv
//   B=8, N=4096 (64x64), C=640, heads=5, HD=128, KS=5, FOCUS=3
// ---------------------------------------------------------------------------

#define BATCH 8
#define SEQ   4096
#define CH    640
#define CC    (CH*CH)
#define NH    5
#define HD    128
#define BH    (BATCH*NH)   // 40

// ---- bf16 GEMM tiling ----
#define BMM 128
#define BNN 128
#define BKE 64                  // bf16 elements per K-chunk
#define NCHB (CH/BKE)           // 10
#define RWB 144                 // bytes per smem row (64 bf16 + 8 pad)
#define BUFB (128*RWB)          // 18432 B per buffer
#define OFFAH 0
#define OFFAL BUFB
#define OFFBH (2*BUFB)
#define OFFBL (3*BUFB)
#define STB   (4*BUFB)          // 73728 B per stage
#define SMEM_GB (2*STB)         // 147456 B

// ---- scratch (device globals: allocation-free rule) ----
__device__ float g_v[BATCH*SEQ*CH];
__device__ float g_q[BATCH*SEQ*CH];
__device__ float g_k[BATCH*SEQ*CH];
__device__ float g_x[BATCH*SEQ*CH];
__device__ __nv_bfloat16 g_abh[BATCH*SEQ*CH];
__device__ __nv_bfloat16 g_abl[BATCH*SEQ*CH];
__device__ __nv_bfloat16 g_wbh[4*CC];
__device__ __nv_bfloat16 g_wbl[4*CC];
__device__ float g_kv2[BH*HD*HD];
__device__ float g_ksum[BH*HD];
__device__ float g_z[BH*SEQ];
__device__ float g_sc[CH];

// ---------------------------------------------------------------------------
// helpers
// ---------------------------------------------------------------------------
__device__ __forceinline__ void cp16(uint32_t dst, const void* src) {
    asm volatile("cp.async.cg.shared.global [%0], [%1], 16;" :: "r"(dst), "l"(src));
}

#define LDM4(r0, r1, r2, r3, a) \
    asm volatile("ldmatrix.sync.aligned.m8n8.x4.shared.b16 {%0,%1,%2,%3}, [%4];" \
        : "=r"(r0), "=r"(r1), "=r"(r2), "=r"(r3) : "r"(a))

#define MMA_BF16(d, a, b) \
    asm volatile( \
        "mma.sync.aligned.m16n8k16.row.col.f32.bf16.bf16.f32 " \
        "{%0,%1,%2,%3}, {%4,%5,%6,%7}, {%8,%9}, {%0,%1,%2,%3};" \
        : "+f"((d)[0]), "+f"((d)[1]), "+f"((d)[2]), "+f"((d)[3]) \
        : "r"((a)[0]), "r"((a)[1]), "r"((a)[2]), "r"((a)[3]), \
          "r"((b)[0]), "r"((b)[1]))

// ---------------------------------------------------------------------------
// splits: x -> (hi = bf16(x), lo = bf16(x - hi))
// ---------------------------------------------------------------------------
__device__ __forceinline__ void split4(float4 v, __nv_bfloat16* hp, __nv_bfloat16* lp) {
    float f[4] = { v.x, v.y, v.z, v.w };
    __nv_bfloat16 h[4], l[4];
#pragma unroll
    for (int j = 0; j < 4; j++) {
        h[j] = __float2bfloat16_rn(f[j]);
        l[j] = __float2bfloat16_rn(f[j] - __bfloat162float(h[j]));
    }
    *reinterpret_cast<__nv_bfloat162*>(hp)     = { h[0], h[1] };
    *reinterpret_cast<__nv_bfloat162*>(hp + 2) = { h[2], h[3] };
    *reinterpret_cast<__nv_bfloat162*>(lp)     = { l[0], l[1] };
    *reinterpret_cast<__nv_bfloat162*>(lp + 2) = { l[2], l[3] };
}

__global__ __launch_bounds__(256) void split_x(
    const float* __restrict__ src, __nv_bfloat16* __restrict__ hi,
    __nv_bfloat16* __restrict__ lo, int n4)
{
    int i = blockIdx.x * 256 + threadIdx.x;
    if (i >= n4) return;
    split4(reinterpret_cast<const float4*>(src)[i], hi + 4 * i, lo + 4 * i);
}

// all weights -> g_wbh/g_wbl: [0]=Wq(CC), [CC]=Wkv(2CC), [3CC]=Wproj(CC)
__global__ __launch_bounds__(256) void split_w(
    const float* __restrict__ Wq, const float* __restrict__ Wkv,
    const float* __restrict__ Wproj)
{
    int i = blockIdx.x * 256 + threadIdx.x;   // float4 index over 4*CC/4
    int fi = i * 4;
    const float* src; int off;
    if (fi < CC)          { src = Wq;    off = 0; }
    else if (fi < 3 * CC) { src = Wkv;   off = CC; }
    else                  { src = Wproj; off = 3 * CC; }
    float4 v = *reinterpret_cast<const float4*>(&src[fi - off]);
    split4(v, g_wbh + fi, g_wbl + fi);
}

// ---------------------------------------------------------------------------
// bf16x3 GEMM: C[m,n] = sum_k (Ah+Al)[m,k]*(Bh+Bl)[n,k] (+bias[n])
// grid(5, 256), 256 threads (8 warps, 4x2), 144KB dyn smem, 2-stage cp.async.
// ---------------------------------------------------------------------------
__global__ __launch_bounds__(256, 1) void gemm_bf16(
    const __nv_bfloat16* __restrict__ Ah, const __nv_bfloat16* __restrict__ Al,
    const __nv_bfloat16* __restrict__ Bh, const __nv_bfloat16* __restrict__ Bl,
    float* __restrict__ C, const float* __restrict__ bias)
{
    extern __shared__ char smem[];
    const uint32_t sb = (uint32_t)__cvta_generic_to_shared(smem);
    const int tid = threadIdx.x;
    const int m0 = blockIdx.y * BMM;
    const int n0 = blockIdx.x * BNN;

    const int lane = tid & 31;
    const int wid = tid >> 5;
    const int warp_m = wid >> 1;         // 0..3 -> 32 rows
    const int warp_n = wid & 1;          // 0..1 -> 64 cols
    const int gid = lane >> 2;
    const int tig = lane & 3;
    // ldmatrix lane -> (row within 16, 16B col half)
    const int lr = (lane & 7) + ((lane >> 3) & 1) * 8;
    const uint32_t lc = (uint32_t)(((lane >> 4) & 1) * 16);

    float acc[2][8][4];
#pragma unroll
    for (int t = 0; t < 2; t++)
#pragma unroll
        for (int j = 0; j < 8; j++)
#pragma unroll
            for (int e = 0; e < 4; e++) acc[t][j][e] = 0.f;

    auto fill = [&](int stage, int chunk) {
        const int k0 = chunk * BKE;
        const uint32_t stb = sb + (uint32_t)(stage * STB);
#pragma unroll
        for (int t = 0; t < 4; t++) {
            int u = tid + t * 256;
            int r = u >> 3, c = u & 7;
            uint32_t off = (uint32_t)(r * RWB + c * 16);
            size_t ga = (size_t)(m0 + r) * CH + k0 + c * 8;
            size_t gb = (size_t)(n0 + r) * CH + k0 + c * 8;
            cp16(stb + OFFAH + off, Ah + ga);
            cp16(stb + OFFAL + off, Al + ga);
            cp16(stb + OFFBH + off, Bh + gb);
            cp16(stb + OFFBL + off, Bl + gb);
        }
        asm volatile("cp.async.commit_group;" ::: "memory");
    };

    fill(0, 0);
    for (int i = 0; i < NCHB; i++) {
        if (i + 1 < NCHB) {
            fill((i + 1) & 1, i + 1);
            asm volatile("cp.async.wait_group 1;" ::: "memory");
        } else {
            asm volatile("cp.async.wait_group 0;" ::: "memory");
        }
        __syncthreads();

        const uint32_t stb = sb + (uint32_t)((i & 1) * STB);
#pragma unroll
        for (int ks = 0; ks < 4; ks++) {
            const uint32_t kofs = (uint32_t)(ks * 32);   // 16 bf16 = 32B
            uint32_t ah[2][4], al[2][4];
#pragma unroll
            for (int t = 0; t < 2; t++) {
                uint32_t ra = stb + OFFAH +
                    (uint32_t)((warp_m * 32 + t * 16 + lr) * RWB) + kofs + lc;
                LDM4(ah[t][0], ah[t][1], ah[t][2], ah[t][3], ra);
                LDM4(al[t][0], al[t][1], al[t][2], al[t][3], ra + (OFFAL - OFFAH));
            }
#pragma unroll
            for (int g = 0; g < 4; g++) {
                uint32_t rb = stb + OFFBH +
                    (uint32_t)((warp_n * 64 + g * 16 + lr) * RWB) + kofs + lc;
                uint32_t bh4[4], bl4[4];
                LDM4(bh4[0], bh4[1], bh4[2], bh4[3], rb);
                LDM4(bl4[0], bl4[1], bl4[2], bl4[3], rb + (OFFBL - OFFBH));
                // j0 frag = {r0, r2}; j1 frag = {r1, r3}
                uint32_t b0h[2] = { bh4[0], bh4[2] }, b1h[2] = { bh4[1], bh4[3] };
                uint32_t b0l[2] = { bl4[0], bl4[2] }, b1l[2] = { bl4[1], bl4[3] };
#pragma unroll
                for (int t = 0; t < 2; t++) {
                    MMA_BF16(acc[t][2*g],   ah[t], b0h);
                    MMA_BF16(acc[t][2*g+1], ah[t], b1h);
                }
#pragma unroll
                for (int t = 0; t < 2; t++) {
                    MMA_BF16(acc[t][2*g],   ah[t], b0l);
                    MMA_BF16(acc[t][2*g+1], ah[t], b1l);
                }
#pragma unroll
                for (int t = 0; t < 2; t++) {
                    MMA_BF16(acc[t][2*g],   al[t], b0h);
                    MMA_BF16(acc[t][2*g+1], al[t], b1h);
                }
            }
        }
        __syncthreads();
    }

    // epilogue
#pragma unroll
    for (int t = 0; t < 2; t++) {
        int r0 = m0 + warp_m * 32 + t * 16 + gid;
#pragma unroll
        for (int j = 0; j < 8; j++) {
            int cc = n0 + warp_n * 64 + j * 8 + 2 * tig;
            float b0 = bias ? bias[cc] : 0.f;
            float b1 = bias ? bias[cc + 1] : 0.f;
            float2 v0 = make_float2(acc[t][j][0] + b0, acc[t][j][1] + b1);
            float2 v1 = make_float2(acc[t][j][2] + b0, acc[t][j][3] + b1);
            *reinterpret_cast<float2*>(&C[(size_t)r0 * CH + cc]) = v0;
            *reinterpret_cast<float2*>(&C[(size_t)(r0 + 8) * CH + cc]) = v1;
        }
    }
}

// ---------------------------------------------------------------------------
// softplus(scale) -> g_sc
// ---------------------------------------------------------------------------
__global__ void softplus_kernel(const float* __restrict__ scale) {
    int c = blockIdx.x * 256 + threadIdx.x;
    if (c < CH) g_sc[c] = log1pf(expf(scale[c]));
}

// ---------------------------------------------------------------------------
// focusing
// ---------------------------------------------------------------------------
__device__ __forceinline__ float block_sum(float v, float* red, int tid) {
    red[tid] = v;
    __syncthreads();
#pragma unroll
    for (int s = 128; s > 0; s >>= 1) {
        if (tid < s) red[tid] += red[tid + s];
        __syncthreads();
    }
    float r = red[0];
    __syncthreads();
    return r;
}

__global__ __launch_bounds__(256) void qknorm_kernel(const float* __restrict__ pos) {
    __shared__ float red[256];
    const int tid = threadIdx.x;
    const size_t row = blockIdx.x;
    const int n = (int)(row & (SEQ - 1));
    float* qrow = g_q + row * CH;
    float* krow = g_k + row * CH;
    const float* prow = pos + (size_t)n * CH;
    {
        float v[3]; float s = 0.f;
#pragma unroll
        for (int j = 0; j < 3; j++) {
            int c = tid + j * 256;
            float val = 0.f;
            if (c < CH) {
                float raw = qrow[c];
                val = (fmaxf(raw, 0.f) + 1e-6f) / g_sc[c];
            }
            v[j] = val; s += val * val;
        }
        float n1 = sqrtf(block_sum(s, red, tid));
        s = 0.f;
#pragma unroll
        for (int j = 0; j < 3; j++) { float c3 = v[j]*v[j]*v[j]; v[j] = c3; s += c3 * c3; }
        float n2 = sqrtf(block_sum(s, red, tid));
        float sc2 = n1 / n2;
#pragma unroll
        for (int j = 0; j < 3; j++) {
            int c = tid + j * 256;
            if (c < CH) qrow[c] = v[j] * sc2;
        }
    }
    {
        float v[3]; float s = 0.f;
#pragma unroll
        for (int j = 0; j < 3; j++) {
            int c = tid + j * 256;
            float val = 0.f;
            if (c < CH) {
                float raw = krow[c] + prow[c];
                val = (fmaxf(raw, 0.f) + 1e-6f) / g_sc[c];
            }
            v[j] = val; s += val * val;
        }
        float n1 = sqrtf(block_sum(s, red, tid));
        s = 0.f;
#pragma unroll
        for (int j = 0; j < 3; j++) { float c3 = v[j]*v[j]*v[j]; v[j] = c3; s += c3 * c3; }
        float n2 = sqrtf(block_sum(s, red, tid));
        float sc2 = n1 / n2;
#pragma unroll
        for (int j = 0; j < 3; j++) {
            int c = tid + j * 256;
            if (c < CH) krow[c] = v[j] * sc2;
        }
    }
}

__global__ void zero_kernel() {
    int idx = blockIdx.x * 256 + threadIdx.x;
    if (idx < BH * HD * HD) g_kv2[idx] = 0.f;
    if (idx < BH * HD)      g_ksum[idx] = 0.f;
}

__global__ __launch_bounds__(128) void ksum_kernel() {
    const int bh = blockIdx.x, jc = blockIdx.y;
    const int b = bh / NH, hoff = (bh % NH) * HD;
    const float* Kp = g_k + (size_t)b * SEQ * CH + hoff + threadIdx.x;
    const int j0 = jc * 512;
    float s = 0.f;
#pragma unroll 4
    for (int j = 0; j < 512; j++) s += Kp[(size_t)(j0 + j) * CH];
    atomicAdd(&g_ksum[bh * HD + threadIdx.x], s);
}

// ---- packed f32x2 helpers ----
__device__ __forceinline__ unsigned long long pk2(float lo, float hi) {
    unsigned long long r;
    asm("mov.b64 %0, {%1, %2};" : "=l"(r) : "f"(lo), "f"(hi));
    return r;
}
__device__ __forceinline__ float2 upk(unsigned long long v) {
    float2 f;
    asm("mov.b64 {%0, %1}, %2;" : "=f"(f.x), "=f"(f.y) : "l"(v));
    return f;
}
#define FMA2(d, a, b) asm("fma.rn.f32x2 %0, %1, %2, %0;" : "+l"(d) : "l"(a), "l"(b))

__global__ __launch_bounds__(256) void kv2_kernel() {
    const int bh = blockIdx.x, jc = blockIdx.y;
    const int b = bh / NH, hoff = (bh % NH) * HD;
    const float* Kp = g_k + (size_t)b * SEQ * CH + hoff;
    const float* Vp = g_v + (size_t)b * SEQ * CH + hoff;
    __shared__ float Ks[16][132];
    __shared__ float Vs[16][132];
    const int tid = threadIdx.x;
    const int tx = tid & 15, ty = tid >> 4;

    unsigned long long acc[8][4];
#pragma unroll
    for (int r = 0; r < 8; r++)
#pragma unroll
        for (int c = 0; c < 4; c++) acc[r][c] = 0ull;

    const int jbase = jc * 512;
    for (int j0 = jbase; j0 < jbase + 512; j0 += 16) {
#pragma unroll
        for (int i = 0; i < 2; i++) {
            int f = tid + i * 256;
            int jj = f >> 5, cq = f & 31;
            float4 kv4 = *reinterpret_cast<const float4*>(&Kp[(size_t)(j0 + jj) * CH + cq * 4]);
            *reinterpret_cast<float4*>(&Ks[jj][cq * 4]) = kv4;
            float4 vv4 = *reinterpret_cast<const float4*>(&Vp[(size_t)(j0 + jj) * CH + cq * 4]);
            *reinterpret_cast<float4*>(&Vs[jj][cq * 4]) = vv4;
        }
        __syncthreads();
#pragma unroll
        for (int jj = 0; jj < 16; jj++) {
            float4 a0 = *reinterpret_cast<const float4*>(&Ks[jj][ty * 4]);
            float4 a1 = *reinterpret_cast<const float4*>(&Ks[jj][64 + ty * 4]);
            unsigned long long ad[8];
            ad[0] = pk2(a0.x, a0.x); ad[1] = pk2(a0.y, a0.y);
            ad[2] = pk2(a0.z, a0.z); ad[3] = pk2(a0.w, a0.w);
            ad[4] = pk2(a1.x, a1.x); ad[5] = pk2(a1.y, a1.y);
            ad[6] = pk2(a1.z, a1.z); ad[7] = pk2(a1.w, a1.w);
            const unsigned long long* b0 =
                reinterpret_cast<const unsigned long long*>(&Vs[jj][tx * 4]);
            const unsigned long long* b1 =
                reinterpret_cast<const unsigned long long*>(&Vs[jj][64 + tx * 4]);
            unsigned long long bb[4] = { b0[0], b0[1], b1[0], b1[1] };
#pragma unroll
            for (int r = 0; r < 8; r++)
#pragma unroll
                for (int c = 0; c < 4; c++) FMA2(acc[r][c], ad[r], bb[c]);
        }
        __syncthreads();
    }
    float* dst = g_kv2 + bh * HD * HD;
#pragma unroll
    for (int r = 0; r < 8; r++) {
        int cdx = (r < 4) ? (ty * 4 + r) : (64 + ty * 4 + r - 4);
#pragma unroll
        for (int c = 0; c < 4; c++) {
            int ddx = (c < 2) ? (tx * 4 + 2 * c) : (64 + tx * 4 + 2 * (c - 2));
            float2 v = upk(acc[r][c]);
            atomicAdd(&dst[cdx * HD + ddx], v.x);
            atomicAdd(&dst[cdx * HD + ddx + 1], v.y);
        }
    }
}

__global__ __launch_bounds__(256) void zrow_kernel() {
    const int gw = blockIdx.x * 8 + (threadIdx.x >> 5);
    const int lane = threadIdx.x & 31;
    const int bh = gw >> 12;
    const int i = gw & (SEQ - 1);
    const int b = bh / NH, hoff = (bh % NH) * HD;
    const float* qrow = g_q + (size_t)(b * SEQ + i) * CH + hoff;
    const float* ks = g_ksum + bh * HD;
    float s = 0.f;
#pragma unroll
    for (int t = 0; t < 4; t++) s += qrow[lane + 32 * t] * ks[lane + 32 * t];
#pragma unroll
    for (int o = 16; o > 0; o >>= 1) s += __shfl_xor_sync(0xffffffffu, s, o);
    if (lane == 0) g_z[bh * SEQ + i] = 1.f / (s + 1e-6f);
}

// ---------------------------------------------------------------------------
// depthwise 5x5 conv, smem-tiled: grid (bh=40, ytile=16, dchunk=4), 256 thr
// smem tile [8 rows][68 x (x-padded)][32 d] = 69632 B (dynamic)
// ---------------------------------------------------------------------------
__global__ __launch_bounds__(256) void conv_s(
    const float* __restrict__ w, const float* __restrict__ bias)
{
    extern __shared__ float sv[];   // [8][68][32]
    const int bh = blockIdx.x, yt = blockIdx.y, dc = blockIdx.z;
    const int b = bh / NH, hoff = (bh % NH) * HD;
    const int tid = threadIdx.x;
    const int d = tid & 31;
    const int xg = tid >> 5;        // 0..7, 8 x per group
    const float* vbase = g_v + (size_t)b * SEQ * CH + hoff + dc * 32;

    // zero x-pads: 8 rows x 4 pad-x x 8 float4 = 256 float4
    {
        int p = tid;                 // exactly 256
        int r = p >> 5, rest = p & 31;
        int xi = rest >> 3, d4 = rest & 7;
        int ix = (xi < 2) ? xi : (xi + 64);   // 0,1,66,67
        *reinterpret_cast<float4*>(&sv[(r * 68 + ix) * 32 + d4 * 4]) =
            make_float4(0.f, 0.f, 0.f, 0.f);
    }
    // load 8 rows (y = yt*4 - 2 + r), zero if OOB
    for (int p = tid; p < 8 * 512; p += 256) {      // 512 float4 per row
        int r = p >> 9, rest = p & 511;
        int x = rest >> 3, d4 = rest & 7;
        int y = yt * 4 - 2 + r;
        float4 val = make_float4(0.f, 0.f, 0.f, 0.f);
        if ((unsigned)y < 64u)
            val = *reinterpret_cast<const float4*>(
                &vbase[(size_t)(y * 64 + x) * CH + d4 * 4]);
        *reinterpret_cast<float4*>(&sv[(r * 68 + x + 2) * 32 + d4 * 4]) = val;
    }
    __syncthreads();

    // weights for this d (25 regs)
    float wr[25];
#pragma unroll
    for (int k = 0; k < 25; k++) wr[k] = __ldg(&w[(dc * 32 + d) * 25 + k]);
    const float bv = __ldg(&bias[dc * 32 + d]);

#pragma unroll
    for (int y = 0; y < 4; y++) {
#pragma unroll
        for (int xo = 0; xo < 8; xo++) {
            int x = xg * 8 + xo;
            float acc = bv;
#pragma unroll
            for (int ky = 0; ky < 5; ky++)
#pragma unroll
                for (int kx = 0; kx < 5; kx++)
                    acc += wr[ky * 5 + kx] * sv[((y + ky) * 68 + (x + kx)) * 32 + d];
            int oy = yt * 4 + y;
            g_x[(size_t)(b * SEQ + oy * 64 + x) * CH + hoff + dc * 32 + d] = acc;
        }
    }
}

__global__ __launch_bounds__(256) void attn_out_kernel() {
    const int bh = blockIdx.x;
    const int i0 = blockIdx.y * 128;
    const int b = bh / NH, hoff = (bh % NH) * HD;
    const float* Qp = g_q + (size_t)b * SEQ * CH + hoff;
    const float* K2 = g_kv2 + bh * HD * HD;
    __shared__ float Qs[16][132];
    __shared__ float Bs[16][132];
    const int tid = threadIdx.x;
    const int tx = tid & 15, ty = tid >> 4;

    unsigned long long acc[8][4];
#pragma unroll
    for (int r = 0; r < 8; r++)
#pragma unroll
        for (int c = 0; c < 4; c++) acc[r][c] = 0ull;

    for (int k0 = 0; k0 < HD; k0 += 16) {
#pragma unroll
        for (int i = 0; i < 2; i++) {
            int f = tid + i * 256;
            int m = f >> 2, kq = f & 3;
            float4 va = *reinterpret_cast<const float4*>(
                &Qp[(size_t)(i0 + m) * CH + k0 + kq * 4]);
            Qs[kq*4+0][m] = va.x; Qs[kq*4+1][m] = va.y;
            Qs[kq*4+2][m] = va.z; Qs[kq*4+3][m] = va.w;
            int kk = f >> 5, dq = f & 31;
            float4 vb = *reinterpret_cast<const float4*>(&K2[(k0 + kk) * HD + dq * 4]);
            *reinterpret_cast<float4*>(&Bs[kk][dq * 4]) = vb;
        }
        __syncthreads();
#pragma unroll
        for (int kk = 0; kk < 16; kk++) {
            float4 a0 = *reinterpret_cast<const float4*>(&Qs[kk][ty * 4]);
            float4 a1 = *reinterpret_cast<const float4*>(&Qs[kk][64 + ty * 4]);
            unsigned long long ad[8];
            ad[0] = pk2(a0.x, a0.x); ad[1] = pk2(a0.y, a0.y);
            ad[2] = pk2(a0.z, a0.z); ad[3] = pk2(a0.w, a0.w);
            ad[4] = pk2(a1.x, a1.x); ad[5] = pk2(a1.y, a1.y);
            ad[6] = pk2(a1.z, a1.z); ad[7] = pk2(a1.w, a1.w);
            const unsigned long long* b0 =
                reinterpret_cast<const unsigned long long*>(&Bs[kk][tx * 4]);
            const unsigned long long* b1 =
                reinterpret_cast<const unsigned long long*>(&Bs[kk][64 + tx * 4]);
            unsigned long long bb[4] = { b0[0], b0[1], b1[0], b1[1] };
#pragma unroll
            for (int r = 0; r < 8; r++)
#pragma unroll
                for (int c = 0; c < 4; c++) FMA2(acc[r][c], ad[r], bb[c]);
        }
        __syncthreads();
    }
#pragma unroll
    for (int r = 0; r < 8; r++) {
        int m = i0 + ((r < 4) ? (ty * 4 + r) : (64 + ty * 4 + r - 4));
        float zv = g_z[bh * SEQ + m];
        float* orow = g_x + (size_t)(b * SEQ + m) * CH + hoff;
#pragma unroll
        for (int c = 0; c < 4; c++) {
            int n = (c < 2) ? (tx * 4 + 2 * c) : (64 + tx * 4 + 2 * (c - 2));
            float2 v = upk(acc[r][c]);
            orow[n]     += v.x * zv;
            orow[n + 1] += v.y * zv;
        }
    }
}

// ---------------------------------------------------------------------------
// launch
// ---------------------------------------------------------------------------
extern "C" void kernel_launch(void* const* d_in, const int* in_sizes, int n_in,
                              void* d_out, int out_size)
{
    const float* x1    = (const float*)d_in[0];
    const float* x2    = (const float*)d_in[1];
    const float* Wq    = (const float*)d_in[2];
    const float* Wkv   = (const float*)d_in[3];
    const float* Wproj = (const float*)d_in[4];
    const float* bproj = (const float*)d_in[5];
    const float* dwc_w = (const float*)d_in[6];
    const float* dwc_b = (const float*)d_in[7];
    const float* scale = (const float*)d_in[8];
    const float* pos   = (const float*)d_in[9];
    float* out = (float*)d_out;

    float *pv, *pq, *pk, *px;
    __nv_bfloat16 *pah, *pal, *pwh, *pwl;
    cudaGetSymbolAddress((void**)&pv, g_v);
    cudaGetSymbolAddress((void**)&pq, g_q);
    cudaGetSymbolAddress((void**)&pk, g_k);
    cudaGetSymbolAddress((void**)&px, g_x);
    cudaGetSymbolAddress((void**)&pah, g_abh);
    cudaGetSymbolAddress((void**)&pal, g_abl);
    cudaGetSymbolAddress((void**)&pwh, g_wbh);
    cudaGetSymbolAddress((void**)&pwl, g_wbl);

    cudaFuncSetAttribute(gemm_bf16,
        cudaFuncAttributeMaxDynamicSharedMemorySize, SMEM_GB);
    cudaFuncSetAttribute(conv_s,
        cudaFuncAttributeMaxDynamicSharedMemorySize, 8 * 68 * 32 * 4);

    const int M = BATCH * SEQ;              // 32768
    const int XN4 = M * CH / 4;             // 5242880
    dim3 gg(CH / BNN, M / BMM);             // (5, 256)

    // launch order puts gemm_bf16 at index 3 for the ncu fixed-skip capture
    split_w<<<4 * CC / 1024, 256>>>(Wq, Wkv, Wproj);                       // 0
    softplus_kernel<<<3, 256>>>(scale);                                    // 1
    split_x<<<XN4 / 256, 256>>>(x2, pah, pal, XN4);                        // 2
    gemm_bf16<<<gg, 256, SMEM_GB>>>(pah, pal, pwh, pwl, pv, nullptr);      // 3: v
    split_x<<<XN4 / 256, 256>>>(x1, pah, pal, XN4);                        // 4
    gemm_bf16<<<gg, 256, SMEM_GB>>>(pah, pal, pwh + CC, pwl + CC, pk, nullptr);       // k
    gemm_bf16<<<gg, 256, SMEM_GB>>>(pah, pal, pwh + 2 * CC, pwl + 2 * CC, pq, nullptr); // q

    qknorm_kernel<<<M, 256>>>(pos);
    zero_kernel<<<(BH * HD * HD + 255) / 256, 256>>>();
    ksum_kernel<<<dim3(BH, 8), 128>>>();
    kv2_kernel<<<dim3(BH, 8), 256>>>();
    zrow_kernel<<<BH * SEQ / 8, 256>>>();
    conv_s<<<dim3(BH, 16, 4), 256, 8 * 68 * 32 * 4>>>(dwc_w, dwc_b);
    attn_out_kernel<<<dim3(BH, SEQ / 128), 256>>>();

    split_x<<<XN4 / 256, 256>>>(px, pah, pal, XN4);
    gemm_bf16<<<gg, 256, SMEM_GB>>>(pah, pal, pwh + 3 * CC, pwl + 3 * CC, out, bproj);
}

// round 6
// speedup vs baseline: 1.6823x; 1.0144x over previous
#include <cuda_runtime.h>
#include <cuda_bf16.h>
#include <cstdint>
#include <cstddef>

// ---------------------------------------------------------------------------
// FocusedLinearAttention — round 6: round-5 (2 CTAs/SM bf16x3) with fill fix
//   B=8, N=4096 (64x64), C=640, heads=5, HD=128, KS=5, FOCUS=3
// ---------------------------------------------------------------------------

#define BATCH 8
#define SEQ   4096
#define CH    640
#define CC    (CH*CH)
#define NH    5
#define HD    128
#define BH    (BATCH*NH)   // 40

// ---- bf16 GEMM tiling (BK=32 elements, 2 CTAs/SM) ----
#define BMM 128
#define BNN 128
#define BKE 32                  // bf16 elements per K-chunk
#define NCHB (CH/BKE)           // 20
#define RWB 80                  // bytes per smem row (32 bf16 = 64B + 16 pad)
#define BUFB (128*RWB)          // 10240 B per buffer
#define OFFAH 0
#define OFFAL BUFB
#define OFFBH (2*BUFB)
#define OFFBL (3*BUFB)
#define STB   (4*BUFB)          // 40960 B per stage
#define SMEM_GB (2*STB)         // 81920 B  -> 2 CTAs/SM

// ---- scratch (device globals: allocation-free rule) ----
__device__ float g_v[BATCH*SEQ*CH];
__device__ float g_q[BATCH*SEQ*CH];
__device__ float g_k[BATCH*SEQ*CH];
__device__ float g_x[BATCH*SEQ*CH];
__device__ __nv_bfloat16 g_abh[BATCH*SEQ*CH];
__device__ __nv_bfloat16 g_abl[BATCH*SEQ*CH];
__device__ __nv_bfloat16 g_wbh[4*CC];
__device__ __nv_bfloat16 g_wbl[4*CC];
__device__ float g_kv2[BH*HD*HD];
__device__ float g_ksum[BH*HD];
__device__ float g_z[BH*SEQ];
__device__ float g_sc[CH];

// ---------------------------------------------------------------------------
// helpers
// ---------------------------------------------------------------------------
__device__ __forceinline__ void cp16(uint32_t dst, const void* src) {
    asm volatile("cp.async.cg.shared.global [%0], [%1], 16;" :: "r"(dst), "l"(src));
}

#define LDM4(r0, r1, r2, r3, a) \
    asm volatile("ldmatrix.sync.aligned.m8n8.x4.shared.b16 {%0,%1,%2,%3}, [%4];" \
        : "=r"(r0), "=r"(r1), "=r"(r2), "=r"(r3) : "r"(a))

#define MMA_BF16(d, a, b) \
    asm volatile( \
        "mma.sync.aligned.m16n8k16.row.col.f32.bf16.bf16.f32 " \
        "{%0,%1,%2,%3}, {%4,%5,%6,%7}, {%8,%9}, {%0,%1,%2,%3};" \
        : "+f"((d)[0]), "+f"((d)[1]), "+f"((d)[2]), "+f"((d)[3]) \
        : "r"((a)[0]), "r"((a)[1]), "r"((a)[2]), "r"((a)[3]), \
          "r"((b)[0]), "r"((b)[1]))

// ---------------------------------------------------------------------------
// splits: x -> (hi = bf16(x), lo = bf16(x - hi))
// ---------------------------------------------------------------------------
__device__ __forceinline__ void split4(float4 v, __nv_bfloat16* hp, __nv_bfloat16* lp) {
    float f[4] = { v.x, v.y, v.z, v.w };
    __nv_bfloat16 h[4], l[4];
#pragma unroll
    for (int j = 0; j < 4; j++) {
        h[j] = __float2bfloat16_rn(f[j]);
        l[j] = __float2bfloat16_rn(f[j] - __bfloat162float(h[j]));
    }
    *reinterpret_cast<__nv_bfloat162*>(hp)     = { h[0], h[1] };
    *reinterpret_cast<__nv_bfloat162*>(hp + 2) = { h[2], h[3] };
    *reinterpret_cast<__nv_bfloat162*>(lp)     = { l[0], l[1] };
    *reinterpret_cast<__nv_bfloat162*>(lp + 2) = { l[2], l[3] };
}

__global__ __launch_bounds__(256) void split_x(
    const float* __restrict__ src, __nv_bfloat16* __restrict__ hi,
    __nv_bfloat16* __restrict__ lo, int n4)
{
    int i = blockIdx.x * 256 + threadIdx.x;
    if (i >= n4) return;
    split4(reinterpret_cast<const float4*>(src)[i], hi + 4 * i, lo + 4 * i);
}

// all weights -> g_wbh/g_wbl: [0]=Wq(CC), [CC]=Wkv(2CC), [3CC]=Wproj(CC)
__global__ __launch_bounds__(256) void split_w(
    const float* __restrict__ Wq, const float* __restrict__ Wkv,
    const float* __restrict__ Wproj)
{
    int i = blockIdx.x * 256 + threadIdx.x;
    int fi = i * 4;
    const float* src; int off;
    if (fi < CC)          { src = Wq;    off = 0; }
    else if (fi < 3 * CC) { src = Wkv;   off = CC; }
    else                  { src = Wproj; off = 3 * CC; }
    float4 v = *reinterpret_cast<const float4*>(&src[fi - off]);
    split4(v, g_wbh + fi, g_wbl + fi);
}

// ---------------------------------------------------------------------------
// bf16x3 GEMM: C[m,n] = sum_k (Ah+Al)[m,k]*(Bh+Bl)[n,k] (+bias[n])
// grid(5, 256), 256 threads (8 warps, 4x2), 80KB dyn smem, 2 CTAs/SM.
// ---------------------------------------------------------------------------
__global__ __launch_bounds__(256, 2) void gemm_bf16(
    const __nv_bfloat16* __restrict__ Ah, const __nv_bfloat16* __restrict__ Al,
    const __nv_bfloat16* __restrict__ Bh, const __nv_bfloat16* __restrict__ Bl,
    float* __restrict__ C, const float* __restrict__ bias)
{
    extern __shared__ char smem[];
    const uint32_t sb = (uint32_t)__cvta_generic_to_shared(smem);
    const int tid = threadIdx.x;
    const int m0 = blockIdx.y * BMM;
    const int n0 = blockIdx.x * BNN;

    const int lane = tid & 31;
    const int wid = tid >> 5;
    const int warp_m = wid >> 1;         // 0..3 -> 32 rows
    const int warp_n = wid & 1;          // 0..1 -> 64 cols
    const int gid = lane >> 2;
    const int tig = lane & 3;
    const int lr = (lane & 7) + ((lane >> 3) & 1) * 8;
    const uint32_t lc = (uint32_t)(((lane >> 4) & 1) * 16);

    float acc[2][8][4];
#pragma unroll
    for (int t = 0; t < 2; t++)
#pragma unroll
        for (int j = 0; j < 8; j++)
#pragma unroll
            for (int e = 0; e < 4; e++) acc[t][j][e] = 0.f;

    // per buffer: 128 rows x 4 x 16B = 512 transfers -> 2 per thread per buffer
    auto fill = [&](int stage, int chunk) {
        const int k0 = chunk * BKE;
        const uint32_t stb = sb + (uint32_t)(stage * STB);
#pragma unroll
        for (int t = 0; t < 2; t++) {
            int u = tid + t * 256;          // 0..511
            int r = u >> 2, c = u & 3;      // r: 0..127, c: 0..3
            uint32_t off = (uint32_t)(r * RWB + c * 16);
            size_t ga = (size_t)(m0 + r) * CH + k0 + c * 8;
            size_t gb = (size_t)(n0 + r) * CH + k0 + c * 8;
            cp16(stb + OFFAH + off, Ah + ga);
            cp16(stb + OFFAL + off, Al + ga);
            cp16(stb + OFFBH + off, Bh + gb);
            cp16(stb + OFFBL + off, Bl + gb);
        }
        asm volatile("cp.async.commit_group;" ::: "memory");
    };

    fill(0, 0);
    for (int i = 0; i < NCHB; i++) {
        if (i + 1 < NCHB) {
            fill((i + 1) & 1, i + 1);
            asm volatile("cp.async.wait_group 1;" ::: "memory");
        } else {
            asm volatile("cp.async.wait_group 0;" ::: "memory");
        }
        __syncthreads();

        const uint32_t stb = sb + (uint32_t)((i & 1) * STB);
#pragma unroll
        for (int ks = 0; ks < 2; ks++) {
            const uint32_t kofs = (uint32_t)(ks * 32);   // 16 bf16 = 32B
            uint32_t ah[2][4], al[2][4];
#pragma unroll
            for (int t = 0; t < 2; t++) {
                uint32_t ra = stb + OFFAH +
                    (uint32_t)((warp_m * 32 + t * 16 + lr) * RWB) + kofs + lc;
                LDM4(ah[t][0], ah[t][1], ah[t][2], ah[t][3], ra);
                LDM4(al[t][0], al[t][1], al[t][2], al[t][3], ra + (OFFAL - OFFAH));
            }
#pragma unroll
            for (int g = 0; g < 4; g++) {
                uint32_t rb = stb + OFFBH +
                    (uint32_t)((warp_n * 64 + g * 16 + lr) * RWB) + kofs + lc;
                uint32_t bh4[4], bl4[4];
                LDM4(bh4[0], bh4[1], bh4[2], bh4[3], rb);
                LDM4(bl4[0], bl4[1], bl4[2], bl4[3], rb + (OFFBL - OFFBH));
                uint32_t b0h[2] = { bh4[0], bh4[2] }, b1h[2] = { bh4[1], bh4[3] };
                uint32_t b0l[2] = { bl4[0], bl4[2] }, b1l[2] = { bl4[1], bl4[3] };
#pragma unroll
                for (int t = 0; t < 2; t++) {
                    MMA_BF16(acc[t][2*g],   ah[t], b0h);
                    MMA_BF16(acc[t][2*g+1], ah[t], b1h);
                }
#pragma unroll
                for (int t = 0; t < 2; t++) {
                    MMA_BF16(acc[t][2*g],   ah[t], b0l);
                    MMA_BF16(acc[t][2*g+1], ah[t], b1l);
                }
#pragma unroll
                for (int t = 0; t < 2; t++) {
                    MMA_BF16(acc[t][2*g],   al[t], b0h);
                    MMA_BF16(acc[t][2*g+1], al[t], b1h);
                }
            }
        }
        __syncthreads();
    }

    // epilogue
#pragma unroll
    for (int t = 0; t < 2; t++) {
        int r0 = m0 + warp_m * 32 + t * 16 + gid;
#pragma unroll
        for (int j = 0; j < 8; j++) {
            int cc = n0 + warp_n * 64 + j * 8 + 2 * tig;
            float b0 = bias ? bias[cc] : 0.f;
            float b1 = bias ? bias[cc + 1] : 0.f;
            float2 v0 = make_float2(acc[t][j][0] + b0, acc[t][j][1] + b1);
            float2 v1 = make_float2(acc[t][j][2] + b0, acc[t][j][3] + b1);
            *reinterpret_cast<float2*>(&C[(size_t)r0 * CH + cc]) = v0;
            *reinterpret_cast<float2*>(&C[(size_t)(r0 + 8) * CH + cc]) = v1;
        }
    }
}

// ---------------------------------------------------------------------------
// softplus(scale) -> g_sc
// ---------------------------------------------------------------------------
__global__ void softplus_kernel(const float* __restrict__ scale) {
    int c = blockIdx.x * 256 + threadIdx.x;
    if (c < CH) g_sc[c] = log1pf(expf(scale[c]));
}

// ---------------------------------------------------------------------------
// focusing
// ---------------------------------------------------------------------------
__device__ __forceinline__ float block_sum(float v, float* red, int tid) {
    red[tid] = v;
    __syncthreads();
#pragma unroll
    for (int s = 128; s > 0; s >>= 1) {
        if (tid < s) red[tid] += red[tid + s];
        __syncthreads();
    }
    float r = red[0];
    __syncthreads();
    return r;
}

__global__ __launch_bounds__(256) void qknorm_kernel(const float* __restrict__ pos) {
    __shared__ float red[256];
    const int tid = threadIdx.x;
    const size_t row = blockIdx.x;
    const int n = (int)(row & (SEQ - 1));
    float* qrow = g_q + row * CH;
    float* krow = g_k + row * CH;
    const float* prow = pos + (size_t)n * CH;
    {
        float v[3]; float s = 0.f;
#pragma unroll
        for (int j = 0; j < 3; j++) {
            int c = tid + j * 256;
            float val = 0.f;
            if (c < CH) {
                float raw = qrow[c];
                val = (fmaxf(raw, 0.f) + 1e-6f) / g_sc[c];
            }
            v[j] = val; s += val * val;
        }
        float n1 = sqrtf(block_sum(s, red, tid));
        s = 0.f;
#pragma unroll
        for (int j = 0; j < 3; j++) { float c3 = v[j]*v[j]*v[j]; v[j] = c3; s += c3 * c3; }
        float n2 = sqrtf(block_sum(s, red, tid));
        float sc2 = n1 / n2;
#pragma unroll
        for (int j = 0; j < 3; j++) {
            int c = tid + j * 256;
            if (c < CH) qrow[c] = v[j] * sc2;
        }
    }
    {
        float v[3]; float s = 0.f;
#pragma unroll
        for (int j = 0; j < 3; j++) {
            int c = tid + j * 256;
            float val = 0.f;
            if (c < CH) {
                float raw = krow[c] + prow[c];
                val = (fmaxf(raw, 0.f) + 1e-6f) / g_sc[c];
            }
            v[j] = val; s += val * val;
        }
        float n1 = sqrtf(block_sum(s, red, tid));
        s = 0.f;
#pragma unroll
        for (int j = 0; j < 3; j++) { float c3 = v[j]*v[j]*v[j]; v[j] = c3; s += c3 * c3; }
        float n2 = sqrtf(block_sum(s, red, tid));
        float sc2 = n1 / n2;
#pragma unroll
        for (int j = 0; j < 3; j++) {
            int c = tid + j * 256;
            if (c < CH) krow[c] = v[j] * sc2;
        }
    }
}

__global__ void zero_kernel() {
    int idx = blockIdx.x * 256 + threadIdx.x;
    if (idx < BH * HD * HD) g_kv2[idx] = 0.f;
    if (idx < BH * HD)      g_ksum[idx] = 0.f;
}

__global__ __launch_bounds__(128) void ksum_kernel() {
    const int bh = blockIdx.x, jc = blockIdx.y;
    const int b = bh / NH, hoff = (bh % NH) * HD;
    const float* Kp = g_k + (size_t)b * SEQ * CH + hoff + threadIdx.x;
    const int j0 = jc * 512;
    float s = 0.f;
#pragma unroll 4
    for (int j = 0; j < 512; j++) s += Kp[(size_t)(j0 + j) * CH];
    atomicAdd(&g_ksum[bh * HD + threadIdx.x], s);
}

// ---- packed f32x2 helpers ----
__device__ __forceinline__ unsigned long long pk2(float lo, float hi) {
    unsigned long long r;
    asm("mov.b64 %0, {%1, %2};" : "=l"(r) : "f"(lo), "f"(hi));
    return r;
}
__device__ __forceinline__ float2 upk(unsigned long long v) {
    float2 f;
    asm("mov.b64 {%0, %1}, %2;" : "=f"(f.x), "=f"(f.y) : "l"(v));
    return f;
}
#define FMA2(d, a, b) asm("fma.rn.f32x2 %0, %1, %2, %0;" : "+l"(d) : "l"(a), "l"(b))

__global__ __launch_bounds__(256) void kv2_kernel() {
    const int bh = blockIdx.x, jc = blockIdx.y;
    const int b = bh / NH, hoff = (bh % NH) * HD;
    const float* Kp = g_k + (size_t)b * SEQ * CH + hoff;
    const float* Vp = g_v + (size_t)b * SEQ * CH + hoff;
    __shared__ float Ks[16][132];
    __shared__ float Vs[16][132];
    const int tid = threadIdx.x;
    const int tx = tid & 15, ty = tid >> 4;

    unsigned long long acc[8][4];
#pragma unroll
    for (int r = 0; r < 8; r++)
#pragma unroll
        for (int c = 0; c < 4; c++) acc[r][c] = 0ull;

    const int jbase = jc * 512;
    for (int j0 = jbase; j0 < jbase + 512; j0 += 16) {
#pragma unroll
        for (int i = 0; i < 2; i++) {
            int f = tid + i * 256;
            int jj = f >> 5, cq = f & 31;
            float4 kv4 = *reinterpret_cast<const float4*>(&Kp[(size_t)(j0 + jj) * CH + cq * 4]);
            *reinterpret_cast<float4*>(&Ks[jj][cq * 4]) = kv4;
            float4 vv4 = *reinterpret_cast<const float4*>(&Vp[(size_t)(j0 + jj) * CH + cq * 4]);
            *reinterpret_cast<float4*>(&Vs[jj][cq * 4]) = vv4;
        }
        __syncthreads();
#pragma unroll
        for (int jj = 0; jj < 16; jj++) {
            float4 a0 = *reinterpret_cast<const float4*>(&Ks[jj][ty * 4]);
            float4 a1 = *reinterpret_cast<const float4*>(&Ks[jj][64 + ty * 4]);
            unsigned long long ad[8];
            ad[0] = pk2(a0.x, a0.x); ad[1] = pk2(a0.y, a0.y);
            ad[2] = pk2(a0.z, a0.z); ad[3] = pk2(a0.w, a0.w);
            ad[4] = pk2(a1.x, a1.x); ad[5] = pk2(a1.y, a1.y);
            ad[6] = pk2(a1.z, a1.z); ad[7] = pk2(a1.w, a1.w);
            const unsigned long long* b0 =
                reinterpret_cast<const unsigned long long*>(&Vs[jj][tx * 4]);
            const unsigned long long* b1 =
                reinterpret_cast<const unsigned long long*>(&Vs[jj][64 + tx * 4]);
            unsigned long long bb[4] = { b0[0], b0[1], b1[0], b1[1] };
#pragma unroll
            for (int r = 0; r < 8; r++)
#pragma unroll
                for (int c = 0; c < 4; c++) FMA2(acc[r][c], ad[r], bb[c]);
        }
        __syncthreads();
    }
    float* dst = g_kv2 + bh * HD * HD;
#pragma unroll
    for (int r = 0; r < 8; r++) {
        int cdx = (r < 4) ? (ty * 4 + r) : (64 + ty * 4 + r - 4);
#pragma unroll
        for (int c = 0; c < 4; c++) {
            int ddx = (c < 2) ? (tx * 4 + 2 * c) : (64 + tx * 4 + 2 * (c - 2));
            float2 v = upk(acc[r][c]);
            atomicAdd(&dst[cdx * HD + ddx], v.x);
            atomicAdd(&dst[cdx * HD + ddx + 1], v.y);
        }
    }
}

__global__ __launch_bounds__(256) void zrow_kernel() {
    const int gw = blockIdx.x * 8 + (threadIdx.x >> 5);
    const int lane = threadIdx.x & 31;
    const int bh = gw >> 12;
    const int i = gw & (SEQ - 1);
    const int b = bh / NH, hoff = (bh % NH) * HD;
    const float* qrow = g_q + (size_t)(b * SEQ + i) * CH + hoff;
    const float* ks = g_ksum + bh * HD;
    float s = 0.f;
#pragma unroll
    for (int t = 0; t < 4; t++) s += qrow[lane + 32 * t] * ks[lane + 32 * t];
#pragma unroll
    for (int o = 16; o > 0; o >>= 1) s += __shfl_xor_sync(0xffffffffu, s, o);
    if (lane == 0) g_z[bh * SEQ + i] = 1.f / (s + 1e-6f);
}

// ---------------------------------------------------------------------------
// depthwise 5x5 conv, smem-tiled -> g_x
// ---------------------------------------------------------------------------
__global__ __launch_bounds__(256) void conv_s(
    const float* __restrict__ w, const float* __restrict__ bias)
{
    extern __shared__ float sv[];   // [8][68][32]
    const int bh = blockIdx.x, yt = blockIdx.y, dc = blockIdx.z;
    const int b = bh / NH, hoff = (bh % NH) * HD;
    const int tid = threadIdx.x;
    const int d = tid & 31;
    const int xg = tid >> 5;
    const float* vbase = g_v + (size_t)b * SEQ * CH + hoff + dc * 32;

    {
        int p = tid;
        int r = p >> 5, rest = p & 31;
        int xi = rest >> 3, d4 = rest & 7;
        int ix = (xi < 2) ? xi : (xi + 64);
        *reinterpret_cast<float4*>(&sv[(r * 68 + ix) * 32 + d4 * 4]) =
            make_float4(0.f, 0.f, 0.f, 0.f);
    }
    for (int p = tid; p < 8 * 512; p += 256) {
        int r = p >> 9, rest = p & 511;
        int x = rest >> 3, d4 = rest & 7;
        int y = yt * 4 - 2 + r;
        float4 val = make_float4(0.f, 0.f, 0.f, 0.f);
        if ((unsigned)y < 64u)
            val = *reinterpret_cast<const float4*>(
                &vbase[(size_t)(y * 64 + x) * CH + d4 * 4]);
        *reinterpret_cast<float4*>(&sv[(r * 68 + x + 2) * 32 + d4 * 4]) = val;
    }
    __syncthreads();

    float wr[25];
#pragma unroll
    for (int k = 0; k < 25; k++) wr[k] = __ldg(&w[(dc * 32 + d) * 25 + k]);
    const float bv = __ldg(&bias[dc * 32 + d]);

#pragma unroll
    for (int y = 0; y < 4; y++) {
#pragma unroll
        for (int xo = 0; xo < 8; xo++) {
            int x = xg * 8 + xo;
            float acc = bv;
#pragma unroll
            for (int ky = 0; ky < 5; ky++)
#pragma unroll
                for (int kx = 0; kx < 5; kx++)
                    acc += wr[ky * 5 + kx] * sv[((y + ky) * 68 + (x + kx)) * 32 + d];
            int oy = yt * 4 + y;
            g_x[(size_t)(b * SEQ + oy * 64 + x) * CH + hoff + dc * 32 + d] = acc;
        }
    }
}

// ---------------------------------------------------------------------------
// attn out + fused bf16 split: for each element
//   val = g_x[...] (conv) + z * (q @ kv2);  write split(val) -> g_abh/g_abl
// ---------------------------------------------------------------------------
__global__ __launch_bounds__(256) void attn_out_kernel() {
    const int bh = blockIdx.x;
    const int i0 = blockIdx.y * 128;
    const int b = bh / NH, hoff = (bh % NH) * HD;
    const float* Qp = g_q + (size_t)b * SEQ * CH + hoff;
    const float* K2 = g_kv2 + bh * HD * HD;
    __shared__ float Qs[16][132];
    __shared__ float Bs[16][132];
    const int tid = threadIdx.x;
    const int tx = tid & 15, ty = tid >> 4;

    unsigned long long acc[8][4];
#pragma unroll
    for (int r = 0; r < 8; r++)
#pragma unroll
        for (int c = 0; c < 4; c++) acc[r][c] = 0ull;

    for (int k0 = 0; k0 < HD; k0 += 16) {
#pragma unroll
        for (int i = 0; i < 2; i++) {
            int f = tid + i * 256;
            int m = f >> 2, kq = f & 3;
            float4 va = *reinterpret_cast<const float4*>(
                &Qp[(size_t)(i0 + m) * CH + k0 + kq * 4]);
            Qs[kq*4+0][m] = va.x; Qs[kq*4+1][m] = va.y;
            Qs[kq*4+2][m] = va.z; Qs[kq*4+3][m] = va.w;
            int kk = f >> 5, dq = f & 31;
            float4 vb = *reinterpret_cast<const float4*>(&K2[(k0 + kk) * HD + dq * 4]);
            *reinterpret_cast<float4*>(&Bs[kk][dq * 4]) = vb;
        }
        __syncthreads();
#pragma unroll
        for (int kk = 0; kk < 16; kk++) {
            float4 a0 = *reinterpret_cast<const float4*>(&Qs[kk][ty * 4]);
            float4 a1 = *reinterpret_cast<const float4*>(&Qs[kk][64 + ty * 4]);
            unsigned long long ad[8];
            ad[0] = pk2(a0.x, a0.x); ad[1] = pk2(a0.y, a0.y);
            ad[2] = pk2(a0.z, a0.z); ad[3] = pk2(a0.w, a0.w);
            ad[4] = pk2(a1.x, a1.x); ad[5] = pk2(a1.y, a1.y);
            ad[6] = pk2(a1.z, a1.z); ad[7] = pk2(a1.w, a1.w);
            const unsigned long long* b0 =
                reinterpret_cast<const unsigned long long*>(&Bs[kk][tx * 4]);
            const unsigned long long* b1 =
                reinterpret_cast<const unsigned long long*>(&Bs[kk][64 + tx * 4]);
            unsigned long long bb[4] = { b0[0], b0[1], b1[0], b1[1] };
#pragma unroll
            for (int r = 0; r < 8; r++)
#pragma unroll
                for (int c = 0; c < 4; c++) FMA2(acc[r][c], ad[r], bb[c]);
        }
        __syncthreads();
    }
#pragma unroll
    for (int r = 0; r < 8; r++) {
        int m = i0 + ((r < 4) ? (ty * 4 + r) : (64 + ty * 4 + r - 4));
        float zv = g_z[bh * SEQ + m];
        size_t rowb = (size_t)(b * SEQ + m) * CH + hoff;
#pragma unroll
        for (int c = 0; c < 4; c++) {
            int n = (c < 2) ? (tx * 4 + 2 * c) : (64 + tx * 4 + 2 * (c - 2));
            float2 v = upk(acc[r][c]);
            float f0 = g_x[rowb + n]     + v.x * zv;
            float f1 = g_x[rowb + n + 1] + v.y * zv;
            __nv_bfloat16 h0 = __float2bfloat16_rn(f0);
            __nv_bfloat16 h1 = __float2bfloat16_rn(f1);
            __nv_bfloat16 l0 = __float2bfloat16_rn(f0 - __bfloat162float(h0));
            __nv_bfloat16 l1 = __float2bfloat16_rn(f1 - __bfloat162float(h1));
            *reinterpret_cast<__nv_bfloat162*>(&g_abh[rowb + n]) = { h0, h1 };
            *reinterpret_cast<__nv_bfloat162*>(&g_abl[rowb + n]) = { l0, l1 };
        }
    }
}

// ---------------------------------------------------------------------------
// launch
// ---------------------------------------------------------------------------
extern "C" void kernel_launch(void* const* d_in, const int* in_sizes, int n_in,
                              void* d_out, int out_size)
{
    const float* x1    = (const float*)d_in[0];
    const float* x2    = (const float*)d_in[1];
    const float* Wq    = (const float*)d_in[2];
    const float* Wkv   = (const float*)d_in[3];
    const float* Wproj = (const float*)d_in[4];
    const float* bproj = (const float*)d_in[5];
    const float* dwc_w = (const float*)d_in[6];
    const float* dwc_b = (const float*)d_in[7];
    const float* scale = (const float*)d_in[8];
    const float* pos   = (const float*)d_in[9];
    float* out = (float*)d_out;

    float *pv, *pq, *pk;
    __nv_bfloat16 *pah, *pal, *pwh, *pwl;
    cudaGetSymbolAddress((void**)&pv, g_v);
    cudaGetSymbolAddress((void**)&pq, g_q);
    cudaGetSymbolAddress((void**)&pk, g_k);
    cudaGetSymbolAddress((void**)&pah, g_abh);
    cudaGetSymbolAddress((void**)&pal, g_abl);
    cudaGetSymbolAddress((void**)&pwh, g_wbh);
    cudaGetSymbolAddress((void**)&pwl, g_wbl);

    cudaFuncSetAttribute(gemm_bf16,
        cudaFuncAttributeMaxDynamicSharedMemorySize, SMEM_GB);
    cudaFuncSetAttribute(conv_s,
        cudaFuncAttributeMaxDynamicSharedMemorySize, 8 * 68 * 32 * 4);

    const int M = BATCH * SEQ;              // 32768
    const int XN4 = M * CH / 4;             // 5242880
    dim3 gg(CH / BNN, M / BMM);             // (5, 256)

    split_w<<<4 * CC / 1024, 256>>>(Wq, Wkv, Wproj);                       // 0
    softplus_kernel<<<3, 256>>>(scale);                                    // 1
    split_x<<<XN4 / 256, 256>>>(x2, pah, pal, XN4);                        // 2
    gemm_bf16<<<gg, 256, SMEM_GB>>>(pah, pal, pwh, pwl, pv, nullptr);      // 3: v
    split_x<<<XN4 / 256, 256>>>(x1, pah, pal, XN4);                        // 4
    gemm_bf16<<<gg, 256, SMEM_GB>>>(pah, pal, pwh + CC, pwl + CC, pk, nullptr);         // k
    gemm_bf16<<<gg, 256, SMEM_GB>>>(pah, pal, pwh + 2 * CC, pwl + 2 * CC, pq, nullptr); // q

    qknorm_kernel<<<M, 256>>>(pos);
    zero_kernel<<<(BH * HD * HD + 255) / 256, 256>>>();
    ksum_kernel<<<dim3(BH, 8), 128>>>();
    kv2_kernel<<<dim3(BH, 8), 256>>>();
    zrow_kernel<<<BH * SEQ / 8, 256>>>();
    conv_s<<<dim3(BH, 16, 4), 256, 8 * 68 * 32 * 4>>>(dwc_w, dwc_b);
    attn_out_kernel<<<dim3(BH, SEQ / 128), 256>>>();   // writes split directly

    gemm_bf16<<<gg, 256, SMEM_GB>>>(pah, pal, pwh + 3 * CC, pwl + 3 * CC, out, bproj);
}

// round 8
// speedup vs baseline: 1.6847x; 1.0014x over previous
#include <cuda_runtime.h>
#include <cuda_bf16.h>
#include <cstdint>
#include <cstddef>

// ---------------------------------------------------------------------------
// FocusedLinearAttention — round 8: resubmit of round 7 (infra failure retry)
//   qknorm warp-per-row, ksum widened, fused k+q GEMM, fill addr hoist
// ---------------------------------------------------------------------------

#define BATCH 8
#define SEQ   4096
#define CH    640
#define CC    (CH*CH)
#define NH    5
#define HD    128
#define BH    (BATCH*NH)   // 40

#define BMM 128
#define BNN 128
#define BKE 32
#define NCHB (CH/BKE)           // 20
#define RWB 80
#define BUFB (128*RWB)
#define OFFAH 0
#define OFFAL BUFB
#define OFFBH (2*BUFB)
#define OFFBL (3*BUFB)
#define STB   (4*BUFB)          // 40960 B
#define SMEM_GB (2*STB)         // 81920 B -> 2 CTAs/SM

__device__ float g_v[BATCH*SEQ*CH];
__device__ float g_q[BATCH*SEQ*CH];
__device__ float g_k[BATCH*SEQ*CH];
__device__ float g_x[BATCH*SEQ*CH];
__device__ __nv_bfloat16 g_abh[BATCH*SEQ*CH];
__device__ __nv_bfloat16 g_abl[BATCH*SEQ*CH];
__device__ __nv_bfloat16 g_wbh[4*CC];
__device__ __nv_bfloat16 g_wbl[4*CC];
__device__ float g_kv2[BH*HD*HD];
__device__ float g_ksum[BH*HD];
__device__ float g_z[BH*SEQ];
__device__ float g_sc[CH];

// ---------------------------------------------------------------------------
__device__ __forceinline__ void cp16(uint32_t dst, const void* src) {
    asm volatile("cp.async.cg.shared.global [%0], [%1], 16;" :: "r"(dst), "l"(src));
}

#define LDM4(r0, r1, r2, r3, a) \
    asm volatile("ldmatrix.sync.aligned.m8n8.x4.shared.b16 {%0,%1,%2,%3}, [%4];" \
        : "=r"(r0), "=r"(r1), "=r"(r2), "=r"(r3) : "r"(a))

#define MMA_BF16(d, a, b) \
    asm volatile( \
        "mma.sync.aligned.m16n8k16.row.col.f32.bf16.bf16.f32 " \
        "{%0,%1,%2,%3}, {%4,%5,%6,%7}, {%8,%9}, {%0,%1,%2,%3};" \
        : "+f"((d)[0]), "+f"((d)[1]), "+f"((d)[2]), "+f"((d)[3]) \
        : "r"((a)[0]), "r"((a)[1]), "r"((a)[2]), "r"((a)[3]), \
          "r"((b)[0]), "r"((b)[1]))

// ---------------------------------------------------------------------------
__device__ __forceinline__ void split4(float4 v, __nv_bfloat16* hp, __nv_bfloat16* lp) {
    float f[4] = { v.x, v.y, v.z, v.w };
    __nv_bfloat16 h[4], l[4];
#pragma unroll
    for (int j = 0; j < 4; j++) {
        h[j] = __float2bfloat16_rn(f[j]);
        l[j] = __float2bfloat16_rn(f[j] - __bfloat162float(h[j]));
    }
    *reinterpret_cast<__nv_bfloat162*>(hp)     = { h[0], h[1] };
    *reinterpret_cast<__nv_bfloat162*>(hp + 2) = { h[2], h[3] };
    *reinterpret_cast<__nv_bfloat162*>(lp)     = { l[0], l[1] };
    *reinterpret_cast<__nv_bfloat162*>(lp + 2) = { l[2], l[3] };
}

__global__ __launch_bounds__(256) void split_x(
    const float* __restrict__ src, __nv_bfloat16* __restrict__ hi,
    __nv_bfloat16* __restrict__ lo, int n4)
{
    int i = blockIdx.x * 256 + threadIdx.x;
    if (i >= n4) return;
    split4(reinterpret_cast<const float4*>(src)[i], hi + 4 * i, lo + 4 * i);
}

__global__ __launch_bounds__(256) void split_w(
    const float* __restrict__ Wq, const float* __restrict__ Wkv,
    const float* __restrict__ Wproj)
{
    int i = blockIdx.x * 256 + threadIdx.x;
    int fi = i * 4;
    const float* src; int off;
    if (fi < CC)          { src = Wq;    off = 0; }
    else if (fi < 3 * CC) { src = Wkv;   off = CC; }
    else                  { src = Wproj; off = 3 * CC; }
    float4 v = *reinterpret_cast<const float4*>(&src[fi - off]);
    split4(v, g_wbh + fi, g_wbl + fi);
}

// ---------------------------------------------------------------------------
// bf16x3 GEMM; if Cq != nullptr, B-rows n<640 -> C, rows >=640 -> Cq.
// ---------------------------------------------------------------------------
__global__ __launch_bounds__(256, 2) void gemm_bf16(
    const __nv_bfloat16* __restrict__ Ah, const __nv_bfloat16* __restrict__ Al,
    const __nv_bfloat16* __restrict__ Bh, const __nv_bfloat16* __restrict__ Bl,
    float* __restrict__ C, float* __restrict__ Cq, const float* __restrict__ bias)
{
    extern __shared__ char smem[];
    const uint32_t sb = (uint32_t)__cvta_generic_to_shared(smem);
    const int tid = threadIdx.x;
    const int m0 = blockIdx.y * BMM;
    const int n0g = blockIdx.x * BNN;
    float* Cout = C;
    int n0 = n0g;
    if (Cq != nullptr && n0g >= CH) { Cout = Cq; n0 = n0g - CH; }

    const int lane = tid & 31;
    const int wid = tid >> 5;
    const int warp_m = wid >> 1;
    const int warp_n = wid & 1;
    const int gid = lane >> 2;
    const int tig = lane & 3;
    const int lr = (lane & 7) + ((lane >> 3) & 1) * 8;
    const uint32_t lc = (uint32_t)(((lane >> 4) & 1) * 16);

    float acc[2][8][4];
#pragma unroll
    for (int t = 0; t < 2; t++)
#pragma unroll
        for (int j = 0; j < 8; j++)
#pragma unroll
            for (int e = 0; e < 4; e++) acc[t][j][e] = 0.f;

    int r0f = tid >> 2, c0f = tid & 3;
    int r1f = (tid + 256) >> 2, c1f = (tid + 256) & 3;
    const uint32_t so0 = (uint32_t)(r0f * RWB + c0f * 16);
    const uint32_t so1 = (uint32_t)(r1f * RWB + c1f * 16);
    const size_t gA0 = (size_t)(m0 + r0f) * CH + c0f * 8;
    const size_t gA1 = (size_t)(m0 + r1f) * CH + c1f * 8;
    const size_t gB0 = (size_t)(n0g + r0f) * CH + c0f * 8;
    const size_t gB1 = (size_t)(n0g + r1f) * CH + c1f * 8;

    auto fill = [&](int stage, int chunk) {
        const int k0 = chunk * BKE;
        const uint32_t stb = sb + (uint32_t)(stage * STB);
        cp16(stb + OFFAH + so0, Ah + gA0 + k0);
        cp16(stb + OFFAL + so0, Al + gA0 + k0);
        cp16(stb + OFFBH + so0, Bh + gB0 + k0);
        cp16(stb + OFFBL + so0, Bl + gB0 + k0);
        cp16(stb + OFFAH + so1, Ah + gA1 + k0);
        cp16(stb + OFFAL + so1, Al + gA1 + k0);
        cp16(stb + OFFBH + so1, Bh + gB1 + k0);
        cp16(stb + OFFBL + so1, Bl + gB1 + k0);
        asm volatile("cp.async.commit_group;" ::: "memory");
    };

    const uint32_t raF = (uint32_t)((warp_m * 32 + lr) * RWB) + lc;
    const uint32_t rbF = (uint32_t)((warp_n * 64 + lr) * RWB) + lc;

    fill(0, 0);
    for (int i = 0; i < NCHB; i++) {
        if (i + 1 < NCHB) {
            fill((i + 1) & 1, i + 1);
            asm volatile("cp.async.wait_group 1;" ::: "memory");
        } else {
            asm volatile("cp.async.wait_group 0;" ::: "memory");
        }
        __syncthreads();

        const uint32_t stb = sb + (uint32_t)((i & 1) * STB);
#pragma unroll
        for (int ks = 0; ks < 2; ks++) {
            const uint32_t kofs = (uint32_t)(ks * 32);
            uint32_t ah[2][4], al[2][4];
#pragma unroll
            for (int t = 0; t < 2; t++) {
                uint32_t ra = stb + OFFAH + raF + (uint32_t)(t * 16 * RWB) + kofs;
                LDM4(ah[t][0], ah[t][1], ah[t][2], ah[t][3], ra);
                LDM4(al[t][0], al[t][1], al[t][2], al[t][3], ra + (OFFAL - OFFAH));
            }
#pragma unroll
            for (int g = 0; g < 4; g++) {
                uint32_t rb = stb + OFFBH + rbF + (uint32_t)(g * 16 * RWB) + kofs;
                uint32_t bh4[4], bl4[4];
                LDM4(bh4[0], bh4[1], bh4[2], bh4[3], rb);
                LDM4(bl4[0], bl4[1], bl4[2], bl4[3], rb + (OFFBL - OFFBH));
                uint32_t b0h[2] = { bh4[0], bh4[2] }, b1h[2] = { bh4[1], bh4[3] };
                uint32_t b0l[2] = { bl4[0], bl4[2] }, b1l[2] = { bl4[1], bl4[3] };
#pragma unroll
                for (int t = 0; t < 2; t++) {
                    MMA_BF16(acc[t][2*g],   ah[t], b0h);
                    MMA_BF16(acc[t][2*g+1], ah[t], b1h);
                }
#pragma unroll
                for (int t = 0; t < 2; t++) {
                    MMA_BF16(acc[t][2*g],   ah[t], b0l);
                    MMA_BF16(acc[t][2*g+1], ah[t], b1l);
                }
#pragma unroll
                for (int t = 0; t < 2; t++) {
                    MMA_BF16(acc[t][2*g],   al[t], b0h);
                    MMA_BF16(acc[t][2*g+1], al[t], b1h);
                }
            }
        }
        __syncthreads();
    }

#pragma unroll
    for (int t = 0; t < 2; t++) {
        int r0 = m0 + warp_m * 32 + t * 16 + gid;
#pragma unroll
        for (int j = 0; j < 8; j++) {
            int cc = n0 + warp_n * 64 + j * 8 + 2 * tig;
            float b0 = bias ? bias[cc] : 0.f;
            float b1 = bias ? bias[cc + 1] : 0.f;
            float2 v0 = make_float2(acc[t][j][0] + b0, acc[t][j][1] + b1);
            float2 v1 = make_float2(acc[t][j][2] + b0, acc[t][j][3] + b1);
            *reinterpret_cast<float2*>(&Cout[(size_t)r0 * CH + cc]) = v0;
            *reinterpret_cast<float2*>(&Cout[(size_t)(r0 + 8) * CH + cc]) = v1;
        }
    }
}

// ---------------------------------------------------------------------------
__global__ void softplus_kernel(const float* __restrict__ scale) {
    int c = blockIdx.x * 256 + threadIdx.x;
    if (c < CH) g_sc[c] = log1pf(expf(scale[c]));
}

// ---------------------------------------------------------------------------
// qknorm: 1 warp per row; 20 elems per lane (640 = 32*20); shfl reductions.
// ---------------------------------------------------------------------------
__device__ __forceinline__ float warp_sum(float s) {
#pragma unroll
    for (int o = 16; o > 0; o >>= 1) s += __shfl_xor_sync(0xffffffffu, s, o);
    return s;
}

__global__ __launch_bounds__(256) void qknorm_kernel(const float* __restrict__ pos) {
    const int w = blockIdx.x * 8 + (threadIdx.x >> 5);   // row id 0..32767
    const int lane = threadIdx.x & 31;
    const size_t row = (size_t)w;
    const int n = w & (SEQ - 1);
    float* qrow = g_q + row * CH;
    float* krow = g_k + row * CH;
    const float* prow = pos + (size_t)n * CH;

    float scv[20];
#pragma unroll
    for (int t = 0; t < 20; t++) scv[t] = g_sc[lane + 32 * t];

    // ---- q ----
    {
        float v[20]; float s = 0.f;
#pragma unroll
        for (int t = 0; t < 20; t++) {
            float raw = qrow[lane + 32 * t];
            float val = (fmaxf(raw, 0.f) + 1e-6f) / scv[t];
            v[t] = val; s += val * val;
        }
        float n1 = sqrtf(warp_sum(s));
        s = 0.f;
#pragma unroll
        for (int t = 0; t < 20; t++) { float c3 = v[t]*v[t]*v[t]; v[t] = c3; s += c3*c3; }
        float sc2 = n1 / sqrtf(warp_sum(s));
#pragma unroll
        for (int t = 0; t < 20; t++) qrow[lane + 32 * t] = v[t] * sc2;
    }
    // ---- k ----
    {
        float v[20]; float s = 0.f;
#pragma unroll
        for (int t = 0; t < 20; t++) {
            float raw = krow[lane + 32 * t] + prow[lane + 32 * t];
            float val = (fmaxf(raw, 0.f) + 1e-6f) / scv[t];
            v[t] = val; s += val * val;
        }
        float n1 = sqrtf(warp_sum(s));
        s = 0.f;
#pragma unroll
        for (int t = 0; t < 20; t++) { float c3 = v[t]*v[t]*v[t]; v[t] = c3; s += c3*c3; }
        float sc2 = n1 / sqrtf(warp_sum(s));
#pragma unroll
        for (int t = 0; t < 20; t++) krow[lane + 32 * t] = v[t] * sc2;
    }
}

__global__ void zero_kernel() {
    int idx = blockIdx.x * 256 + threadIdx.x;
    if (idx < BH * HD * HD) g_kv2[idx] = 0.f;
    if (idx < BH * HD)      g_ksum[idx] = 0.f;
}

// ksum: grid (40, 32), 128-j chunks per block
__global__ __launch_bounds__(128) void ksum_kernel() {
    const int bh = blockIdx.x, jc = blockIdx.y;
    const int b = bh / NH, hoff = (bh % NH) * HD;
    const float* Kp = g_k + (size_t)b * SEQ * CH + hoff + threadIdx.x;
    const int j0 = jc * 128;
    float s = 0.f;
#pragma unroll 8
    for (int j = 0; j < 128; j++) s += Kp[(size_t)(j0 + j) * CH];
    atomicAdd(&g_ksum[bh * HD + threadIdx.x], s);
}

// ---- packed f32x2 helpers ----
__device__ __forceinline__ unsigned long long pk2(float lo, float hi) {
    unsigned long long r;
    asm("mov.b64 %0, {%1, %2};" : "=l"(r) : "f"(lo), "f"(hi));
    return r;
}
__device__ __forceinline__ float2 upk(unsigned long long v) {
    float2 f;
    asm("mov.b64 {%0, %1}, %2;" : "=f"(f.x), "=f"(f.y) : "l"(v));
    return f;
}
#define FMA2(d, a, b) asm("fma.rn.f32x2 %0, %1, %2, %0;" : "+l"(d) : "l"(a), "l"(b))

__global__ __launch_bounds__(256) void kv2_kernel() {
    const int bh = blockIdx.x, jc = blockIdx.y;
    const int b = bh / NH, hoff = (bh % NH) * HD;
    const float* Kp = g_k + (size_t)b * SEQ * CH + hoff;
    const float* Vp = g_v + (size_t)b * SEQ * CH + hoff;
    __shared__ float Ks[16][132];
    __shared__ float Vs[16][132];
    const int tid = threadIdx.x;
    const int tx = tid & 15, ty = tid >> 4;

    unsigned long long acc[8][4];
#pragma unroll
    for (int r = 0; r < 8; r++)
#pragma unroll
        for (int c = 0; c < 4; c++) acc[r][c] = 0ull;

    const int jbase = jc * 512;
    for (int j0 = jbase; j0 < jbase + 512; j0 += 16) {
#pragma unroll
        for (int i = 0; i < 2; i++) {
            int f = tid + i * 256;
            int jj = f >> 5, cq = f & 31;
            float4 kv4 = *reinterpret_cast<const float4*>(&Kp[(size_t)(j0 + jj) * CH + cq * 4]);
            *reinterpret_cast<float4*>(&Ks[jj][cq * 4]) = kv4;
            float4 vv4 = *reinterpret_cast<const float4*>(&Vp[(size_t)(j0 + jj) * CH + cq * 4]);
            *reinterpret_cast<float4*>(&Vs[jj][cq * 4]) = vv4;
        }
        __syncthreads();
#pragma unroll
        for (int jj = 0; jj < 16; jj++) {
            float4 a0 = *reinterpret_cast<const float4*>(&Ks[jj][ty * 4]);
            float4 a1 = *reinterpret_cast<const float4*>(&Ks[jj][64 + ty * 4]);
            unsigned long long ad[8];
            ad[0] = pk2(a0.x, a0.x); ad[1] = pk2(a0.y, a0.y);
            ad[2] = pk2(a0.z, a0.z); ad[3] = pk2(a0.w, a0.w);
            ad[4] = pk2(a1.x, a1.x); ad[5] = pk2(a1.y, a1.y);
            ad[6] = pk2(a1.z, a1.z); ad[7] = pk2(a1.w, a1.w);
            const unsigned long long* b0 =
                reinterpret_cast<const unsigned long long*>(&Vs[jj][tx * 4]);
            const unsigned long long* b1 =
                reinterpret_cast<const unsigned long long*>(&Vs[jj][64 + tx * 4]);
            unsigned long long bb[4] = { b0[0], b0[1], b1[0], b1[1] };
#pragma unroll
            for (int r = 0; r < 8; r++)
#pragma unroll
                for (int c = 0; c < 4; c++) FMA2(acc[r][c], ad[r], bb[c]);
        }
        __syncthreads();
    }
    float* dst = g_kv2 + bh * HD * HD;
#pragma unroll
    for (int r = 0; r < 8; r++) {
        int cdx = (r < 4) ? (ty * 4 + r) : (64 + ty * 4 + r - 4);
#pragma unroll
        for (int c = 0; c < 4; c++) {
            int ddx = (c < 2) ? (tx * 4 + 2 * c) : (64 + tx * 4 + 2 * (c - 2));
            float2 v = upk(acc[r][c]);
            atomicAdd(&dst[cdx * HD + ddx], v.x);
            atomicAdd(&dst[cdx * HD + ddx + 1], v.y);
        }
    }
}

__global__ __launch_bounds__(256) void zrow_kernel() {
    const int gw = blockIdx.x * 8 + (threadIdx.x >> 5);
    const int lane = threadIdx.x & 31;
    const int bh = gw >> 12;
    const int i = gw & (SEQ - 1);
    const int b = bh / NH, hoff = (bh % NH) * HD;
    const float* qrow = g_q + (size_t)(b * SEQ + i) * CH + hoff;
    const float* ks = g_ksum + bh * HD;
    float s = 0.f;
#pragma unroll
    for (int t = 0; t < 4; t++) s += qrow[lane + 32 * t] * ks[lane + 32 * t];
#pragma unroll
    for (int o = 16; o > 0; o >>= 1) s += __shfl_xor_sync(0xffffffffu, s, o);
    if (lane == 0) g_z[bh * SEQ + i] = 1.f / (s + 1e-6f);
}

// ---------------------------------------------------------------------------
__global__ __launch_bounds__(256) void conv_s(
    const float* __restrict__ w, const float* __restrict__ bias)
{
    extern __shared__ float sv[];
    const int bh = blockIdx.x, yt = blockIdx.y, dc = blockIdx.z;
    const int b = bh / NH, hoff = (bh % NH) * HD;
    const int tid = threadIdx.x;
    const int d = tid & 31;
    const int xg = tid >> 5;
    const float* vbase = g_v + (size_t)b * SEQ * CH + hoff + dc * 32;

    {
        int p = tid;
        int r = p >> 5, rest = p & 31;
        int xi = rest >> 3, d4 = rest & 7;
        int ix = (xi < 2) ? xi : (xi + 64);
        *reinterpret_cast<float4*>(&sv[(r * 68 + ix) * 32 + d4 * 4]) =
            make_float4(0.f, 0.f, 0.f, 0.f);
    }
    for (int p = tid; p < 8 * 512; p += 256) {
        int r = p >> 9, rest = p & 511;
        int x = rest >> 3, d4 = rest & 7;
        int y = yt * 4 - 2 + r;
        float4 val = make_float4(0.f, 0.f, 0.f, 0.f);
        if ((unsigned)y < 64u)
            val = *reinterpret_cast<const float4*>(
                &vbase[(size_t)(y * 64 + x) * CH + d4 * 4]);
        *reinterpret_cast<float4*>(&sv[(r * 68 + x + 2) * 32 + d4 * 4]) = val;
    }
    __syncthreads();

    float wr[25];
#pragma unroll
    for (int k = 0; k < 25; k++) wr[k] = __ldg(&w[(dc * 32 + d) * 25 + k]);
    const float bv = __ldg(&bias[dc * 32 + d]);

#pragma unroll
    for (int y = 0; y < 4; y++) {
#pragma unroll
        for (int xo = 0; xo < 8; xo++) {
            int x = xg * 8 + xo;
            float acc = bv;
#pragma unroll
            for (int ky = 0; ky < 5; ky++)
#pragma unroll
                for (int kx = 0; kx < 5; kx++)
                    acc += wr[ky * 5 + kx] * sv[((y + ky) * 68 + (x + kx)) * 32 + d];
            int oy = yt * 4 + y;
            g_x[(size_t)(b * SEQ + oy * 64 + x) * CH + hoff + dc * 32 + d] = acc;
        }
    }
}

// ---------------------------------------------------------------------------
__global__ __launch_bounds__(256) void attn_out_kernel() {
    const int bh = blockIdx.x;
    const int i0 = blockIdx.y * 128;
    const int b = bh / NH, hoff = (bh % NH) * HD;
    const float* Qp = g_q + (size_t)b * SEQ * CH + hoff;
    const float* K2 = g_kv2 + bh * HD * HD;
    __shared__ float Qs[16][132];
    __shared__ float Bs[16][132];
    const int tid = threadIdx.x;
    const int tx = tid & 15, ty = tid >> 4;

    unsigned long long acc[8][4];
#pragma unroll
    for (int r = 0; r < 8; r++)
#pragma unroll
        for (int c = 0; c < 4; c++) acc[r][c] = 0ull;

    for (int k0 = 0; k0 < HD; k0 += 16) {
#pragma unroll
        for (int i = 0; i < 2; i++) {
            int f = tid + i * 256;
            int m = f >> 2, kq = f & 3;
            float4 va = *reinterpret_cast<const float4*>(
                &Qp[(size_t)(i0 + m) * CH + k0 + kq * 4]);
            Qs[kq*4+0][m] = va.x; Qs[kq*4+1][m] = va.y;
            Qs[kq*4+2][m] = va.z; Qs[kq*4+3][m] = va.w;
            int kk = f >> 5, dq = f & 31;
            float4 vb = *reinterpret_cast<const float4*>(&K2[(k0 + kk) * HD + dq * 4]);
            *reinterpret_cast<float4*>(&Bs[kk][dq * 4]) = vb;
        }
        __syncthreads();
#pragma unroll
        for (int kk = 0; kk < 16; kk++) {
            float4 a0 = *reinterpret_cast<const float4*>(&Qs[kk][ty * 4]);
            float4 a1 = *reinterpret_cast<const float4*>(&Qs[kk][64 + ty * 4]);
            unsigned long long ad[8];
            ad[0] = pk2(a0.x, a0.x); ad[1] = pk2(a0.y, a0.y);
            ad[2] = pk2(a0.z, a0.z); ad[3] = pk2(a0.w, a0.w);
            ad[4] = pk2(a1.x, a1.x); ad[5] = pk2(a1.y, a1.y);
            ad[6] = pk2(a1.z, a1.z); ad[7] = pk2(a1.w, a1.w);
            const unsigned long long* b0 =
                reinterpret_cast<const unsigned long long*>(&Bs[kk][tx * 4]);
            const unsigned long long* b1 =
                reinterpret_cast<const unsigned long long*>(&Bs[kk][64 + tx * 4]);
            unsigned long long bb[4] = { b0[0], b0[1], b1[0], b1[1] };
#pragma unroll
            for (int r = 0; r < 8; r++)
#pragma unroll
                for (int c = 0; c < 4; c++) FMA2(acc[r][c], ad[r], bb[c]);
        }
        __syncthreads();
    }
#pragma unroll
    for (int r = 0; r < 8; r++) {
        int m = i0 + ((r < 4) ? (ty * 4 + r) : (64 + ty * 4 + r - 4));
        float zv = g_z[bh * SEQ + m];
        size_t rowb = (size_t)(b * SEQ + m) * CH + hoff;
#pragma unroll
        for (int c = 0; c < 4; c++) {
            int n = (c < 2) ? (tx * 4 + 2 * c) : (64 + tx * 4 + 2 * (c - 2));
            float2 v = upk(acc[r][c]);
            float f0 = g_x[rowb + n]     + v.x * zv;
            float f1 = g_x[rowb + n + 1] + v.y * zv;
            __nv_bfloat16 h0 = __float2bfloat16_rn(f0);
            __nv_bfloat16 h1 = __float2bfloat16_rn(f1);
            __nv_bfloat16 l0 = __float2bfloat16_rn(f0 - __bfloat162float(h0));
            __nv_bfloat16 l1 = __float2bfloat16_rn(f1 - __bfloat162float(h1));
            *reinterpret_cast<__nv_bfloat162*>(&g_abh[rowb + n]) = { h0, h1 };
            *reinterpret_cast<__nv_bfloat162*>(&g_abl[rowb + n]) = { l0, l1 };
        }
    }
}

// ---------------------------------------------------------------------------
extern "C" void kernel_launch(void* const* d_in, const int* in_sizes, int n_in,
                              void* d_out, int out_size)
{
    const float* x1    = (const float*)d_in[0];
    const float* x2    = (const float*)d_in[1];
    const float* Wq    = (const float*)d_in[2];
    const float* Wkv   = (const float*)d_in[3];
    const float* Wproj = (const float*)d_in[4];
    const float* bproj = (const float*)d_in[5];
    const float* dwc_w = (const float*)d_in[6];
    const float* dwc_b = (const float*)d_in[7];
    const float* scale = (const float*)d_in[8];
    const float* pos   = (const float*)d_in[9];
    float* out = (float*)d_out;

    float *pv, *pq, *pk;
    __nv_bfloat16 *pah, *pal, *pwh, *pwl;
    cudaGetSymbolAddress((void**)&pv, g_v);
    cudaGetSymbolAddress((void**)&pq, g_q);
    cudaGetSymbolAddress((void**)&pk, g_k);
    cudaGetSymbolAddress((void**)&pah, g_abh);
    cudaGetSymbolAddress((void**)&pal, g_abl);
    cudaGetSymbolAddress((void**)&pwh, g_wbh);
    cudaGetSymbolAddress((void**)&pwl, g_wbl);

    cudaFuncSetAttribute(gemm_bf16,
        cudaFuncAttributeMaxDynamicSharedMemorySize, SMEM_GB);
    cudaFuncSetAttribute(conv_s,
        cudaFuncAttributeMaxDynamicSharedMemorySize, 8 * 68 * 32 * 4);

    const int M = BATCH * SEQ;              // 32768
    const int XN4 = M * CH / 4;
    dim3 gg(CH / BNN, M / BMM);             // (5, 256)
    dim3 ggkq(2 * CH / BNN, M / BMM);       // (10, 256) fused k+q

    split_w<<<4 * CC / 1024, 256>>>(Wq, Wkv, Wproj);                        // 0
    softplus_kernel<<<3, 256>>>(scale);                                     // 1
    split_x<<<XN4 / 256, 256>>>(x2, pah, pal, XN4);                         // 2
    gemm_bf16<<<gg, 256, SMEM_GB>>>(pah, pal, pwh, pwl, pv, nullptr, nullptr); // 3: v
    split_x<<<XN4 / 256, 256>>>(x1, pah, pal, XN4);                         // 4
    // fused k (rows 0..639) + q (rows 640..1279) from Wkv
    gemm_bf16<<<ggkq, 256, SMEM_GB>>>(pah, pal, pwh + CC, pwl + CC, pk, pq, nullptr);

    qknorm_kernel<<<M / 8, 256>>>(pos);
    zero_kernel<<<(BH * HD * HD + 255) / 256, 256>>>();
    ksum_kernel<<<dim3(BH, 32), 128>>>();
    kv2_kernel<<<dim3(BH, 8), 256>>>();
    zrow_kernel<<<BH * SEQ / 8, 256>>>();
    conv_s<<<dim3(BH, 16, 4), 256, 8 * 68 * 32 * 4>>>(dwc_w, dwc_b);
    attn_out_kernel<<<dim3(BH, SEQ / 128), 256>>>();

    gemm_bf16<<<gg, 256, SMEM_GB>>>(pah, pal, pwh + 3 * CC, pwl + 3 * CC, out, nullptr, bproj);
}

// round 9
// speedup vs baseline: 1.7139x; 1.0173x over previous
#include <cuda_runtime.h>
#include <cuda_bf16.h>
#include <cstdint>
#include <cstddef>

// ---------------------------------------------------------------------------
// FocusedLinearAttention — round 9:
//   merged v+kq GEMM launch; attn_out on tensor pipe (bf16x3, K=128);
//   qknorm emits q as bf16 hi/lo; kv2 transposed+split; zrow reads hi/lo.
// ---------------------------------------------------------------------------

#define BATCH 8
#define SEQ   4096
#define CH    640
#define CC    (CH*CH)
#define NH    5
#define HD    128
#define BH    (BATCH*NH)   // 40

#define BMM 128
#define BNN 128
#define BKE 32
#define NCHB (CH/BKE)           // 20
#define RWB 80
#define BUFB (128*RWB)
#define OFFAH 0
#define OFFAL BUFB
#define OFFBH (2*BUFB)
#define OFFBL (3*BUFB)
#define STB   (4*BUFB)          // 40960 B
#define SMEM_GB (2*STB)         // 81920 B -> 2 CTAs/SM

__device__ float g_v[BATCH*SEQ*CH];
__device__ float g_q[BATCH*SEQ*CH];      // raw q (gemm out, qknorm in)
__device__ float g_k[BATCH*SEQ*CH];      // raw/focused k (fp32)
__device__ float g_x[BATCH*SEQ*CH];      // conv output
__device__ __nv_bfloat16 g_abh[BATCH*SEQ*CH];   // x1 split -> later proj input
__device__ __nv_bfloat16 g_abl[BATCH*SEQ*CH];
__device__ __nv_bfloat16 g_a2h[BATCH*SEQ*CH];   // x2 split
__device__ __nv_bfloat16 g_a2l[BATCH*SEQ*CH];
__device__ __nv_bfloat16 g_qbh[BATCH*SEQ*CH];   // focused q split
__device__ __nv_bfloat16 g_qbl[BATCH*SEQ*CH];
__device__ __nv_bfloat16 g_wbh[4*CC];
__device__ __nv_bfloat16 g_wbl[4*CC];
__device__ __nv_bfloat16 g_k2h[BH*HD*HD];       // kv2^T split [bh][d][c]
__device__ __nv_bfloat16 g_k2l[BH*HD*HD];
__device__ float g_kv2[BH*HD*HD];
__device__ float g_ksum[BH*HD];
__device__ float g_z[BH*SEQ];
__device__ float g_sc[CH];

// ---------------------------------------------------------------------------
__device__ __forceinline__ void cp16(uint32_t dst, const void* src) {
    asm volatile("cp.async.cg.shared.global [%0], [%1], 16;" :: "r"(dst), "l"(src));
}

#define LDM4(r0, r1, r2, r3, a) \
    asm volatile("ldmatrix.sync.aligned.m8n8.x4.shared.b16 {%0,%1,%2,%3}, [%4];" \
        : "=r"(r0), "=r"(r1), "=r"(r2), "=r"(r3) : "r"(a))

#define MMA_BF16(d, a, b) \
    asm volatile( \
        "mma.sync.aligned.m16n8k16.row.col.f32.bf16.bf16.f32 " \
        "{%0,%1,%2,%3}, {%4,%5,%6,%7}, {%8,%9}, {%0,%1,%2,%3};" \
        : "+f"((d)[0]), "+f"((d)[1]), "+f"((d)[2]), "+f"((d)[3]) \
        : "r"((a)[0]), "r"((a)[1]), "r"((a)[2]), "r"((a)[3]), \
          "r"((b)[0]), "r"((b)[1]))

// ---------------------------------------------------------------------------
__device__ __forceinline__ void split4(float4 v, __nv_bfloat16* hp, __nv_bfloat16* lp) {
    float f[4] = { v.x, v.y, v.z, v.w };
    __nv_bfloat16 h[4], l[4];
#pragma unroll
    for (int j = 0; j < 4; j++) {
        h[j] = __float2bfloat16_rn(f[j]);
        l[j] = __float2bfloat16_rn(f[j] - __bfloat162float(h[j]));
    }
    *reinterpret_cast<__nv_bfloat162*>(hp)     = { h[0], h[1] };
    *reinterpret_cast<__nv_bfloat162*>(hp + 2) = { h[2], h[3] };
    *reinterpret_cast<__nv_bfloat162*>(lp)     = { l[0], l[1] };
    *reinterpret_cast<__nv_bfloat162*>(lp + 2) = { l[2], l[3] };
}

__global__ __launch_bounds__(256) void split_x(
    const float* __restrict__ src, __nv_bfloat16* __restrict__ hi,
    __nv_bfloat16* __restrict__ lo, int n4)
{
    int i = blockIdx.x * 256 + threadIdx.x;
    if (i >= n4) return;
    split4(reinterpret_cast<const float4*>(src)[i], hi + 4 * i, lo + 4 * i);
}

__global__ __launch_bounds__(256) void split_w(
    const float* __restrict__ Wq, const float* __restrict__ Wkv,
    const float* __restrict__ Wproj)
{
    int i = blockIdx.x * 256 + threadIdx.x;
    int fi = i * 4;
    const float* src; int off;
    if (fi < CC)          { src = Wq;    off = 0; }
    else if (fi < 3 * CC) { src = Wkv;   off = CC; }
    else                  { src = Wproj; off = 3 * CC; }
    float4 v = *reinterpret_cast<const float4*>(&src[fi - off]);
    split4(v, g_wbh + fi, g_wbl + fi);
}

// ---------------------------------------------------------------------------
// common bf16x3 GEMM core: C[m0+.., n0+..] = A[m0+..]·B[nb0+..]^T (+bias)
// A rows stride CH, B rows stride CH, K = 640 (20 chunks of 32).
// ---------------------------------------------------------------------------
__device__ __forceinline__ void gemm_core(
    const __nv_bfloat16* __restrict__ Ah, const __nv_bfloat16* __restrict__ Al,
    const __nv_bfloat16* __restrict__ Bh, const __nv_bfloat16* __restrict__ Bl,
    float* __restrict__ Cout, const float* __restrict__ bias,
    int m0, int nb0, int n0, uint32_t sb)
{
    const int tid = threadIdx.x;
    const int lane = tid & 31;
    const int wid = tid >> 5;
    const int warp_m = wid >> 1;
    const int warp_n = wid & 1;
    const int gid = lane >> 2;
    const int tig = lane & 3;
    const int lr = (lane & 7) + ((lane >> 3) & 1) * 8;
    const uint32_t lc = (uint32_t)(((lane >> 4) & 1) * 16);

    float acc[2][8][4];
#pragma unroll
    for (int t = 0; t < 2; t++)
#pragma unroll
        for (int j = 0; j < 8; j++)
#pragma unroll
            for (int e = 0; e < 4; e++) acc[t][j][e] = 0.f;

    int r0f = tid >> 2, c0f = tid & 3;
    int r1f = (tid + 256) >> 2, c1f = (tid + 256) & 3;
    const uint32_t so0 = (uint32_t)(r0f * RWB + c0f * 16);
    const uint32_t so1 = (uint32_t)(r1f * RWB + c1f * 16);
    const size_t gA0 = (size_t)(m0 + r0f) * CH + c0f * 8;
    const size_t gA1 = (size_t)(m0 + r1f) * CH + c1f * 8;
    const size_t gB0 = (size_t)(nb0 + r0f) * CH + c0f * 8;
    const size_t gB1 = (size_t)(nb0 + r1f) * CH + c1f * 8;

    auto fill = [&](int stage, int chunk) {
        const int k0 = chunk * BKE;
        const uint32_t stb = sb + (uint32_t)(stage * STB);
        cp16(stb + OFFAH + so0, Ah + gA0 + k0);
        cp16(stb + OFFAL + so0, Al + gA0 + k0);
        cp16(stb + OFFBH + so0, Bh + gB0 + k0);
        cp16(stb + OFFBL + so0, Bl + gB0 + k0);
        cp16(stb + OFFAH + so1, Ah + gA1 + k0);
        cp16(stb + OFFAL + so1, Al + gA1 + k0);
        cp16(stb + OFFBH + so1, Bh + gB1 + k0);
        cp16(stb + OFFBL + so1, Bl + gB1 + k0);
        asm volatile("cp.async.commit_group;" ::: "memory");
    };

    const uint32_t raF = (uint32_t)((warp_m * 32 + lr) * RWB) + lc;
    const uint32_t rbF = (uint32_t)((warp_n * 64 + lr) * RWB) + lc;

    fill(0, 0);
    for (int i = 0; i < NCHB; i++) {
        if (i + 1 < NCHB) {
            fill((i + 1) & 1, i + 1);
            asm volatile("cp.async.wait_group 1;" ::: "memory");
        } else {
            asm volatile("cp.async.wait_group 0;" ::: "memory");
        }
        __syncthreads();

        const uint32_t stb = sb + (uint32_t)((i & 1) * STB);
#pragma unroll
        for (int ks = 0; ks < 2; ks++) {
            const uint32_t kofs = (uint32_t)(ks * 32);
            uint32_t ah[2][4], al[2][4];
#pragma unroll
            for (int t = 0; t < 2; t++) {
                uint32_t ra = stb + OFFAH + raF + (uint32_t)(t * 16 * RWB) + kofs;
                LDM4(ah[t][0], ah[t][1], ah[t][2], ah[t][3], ra);
                LDM4(al[t][0], al[t][1], al[t][2], al[t][3], ra + (OFFAL - OFFAH));
            }
#pragma unroll
            for (int g = 0; g < 4; g++) {
                uint32_t rb = stb + OFFBH + rbF + (uint32_t)(g * 16 * RWB) + kofs;
                uint32_t bh4[4], bl4[4];
                LDM4(bh4[0], bh4[1], bh4[2], bh4[3], rb);
                LDM4(bl4[0], bl4[1], bl4[2], bl4[3], rb + (OFFBL - OFFBH));
                uint32_t b0h[2] = { bh4[0], bh4[2] }, b1h[2] = { bh4[1], bh4[3] };
                uint32_t b0l[2] = { bl4[0], bl4[2] }, b1l[2] = { bl4[1], bl4[3] };
#pragma unroll
                for (int t = 0; t < 2; t++) {
                    MMA_BF16(acc[t][2*g],   ah[t], b0h);
                    MMA_BF16(acc[t][2*g+1], ah[t], b1h);
                }
#pragma unroll
                for (int t = 0; t < 2; t++) {
                    MMA_BF16(acc[t][2*g],   ah[t], b0l);
                    MMA_BF16(acc[t][2*g+1], ah[t], b1l);
                }
#pragma unroll
                for (int t = 0; t < 2; t++) {
                    MMA_BF16(acc[t][2*g],   al[t], b0h);
                    MMA_BF16(acc[t][2*g+1], al[t], b1h);
                }
            }
        }
        __syncthreads();
    }

#pragma unroll
    for (int t = 0; t < 2; t++) {
        int r0 = m0 + warp_m * 32 + t * 16 + gid;
#pragma unroll
        for (int j = 0; j < 8; j++) {
            int cc = n0 + warp_n * 64 + j * 8 + 2 * tig;
            float b0 = bias ? bias[cc] : 0.f;
            float b1 = bias ? bias[cc + 1] : 0.f;
            float2 v0 = make_float2(acc[t][j][0] + b0, acc[t][j][1] + b1);
            float2 v1 = make_float2(acc[t][j][2] + b0, acc[t][j][3] + b1);
            *reinterpret_cast<float2*>(&Cout[(size_t)r0 * CH + cc]) = v0;
            *reinterpret_cast<float2*>(&Cout[(size_t)(r0 + 8) * CH + cc]) = v1;
        }
    }
}

// merged v + kq GEMM: grid (15, 256)
__global__ __launch_bounds__(256, 2) void gemm_merged() {
    extern __shared__ char smem[];
    const uint32_t sb = (uint32_t)__cvta_generic_to_shared(smem);
    const int m0 = blockIdx.y * BMM;
    const int bx = blockIdx.x;
    if (bx < 5) {
        gemm_core(g_a2h, g_a2l, g_wbh, g_wbl, g_v, nullptr,
                  m0, bx * BNN, bx * BNN, sb);
    } else {
        int nb0 = (bx - 5) * BNN;
        if (nb0 < CH)
            gemm_core(g_abh, g_abl, g_wbh + CC, g_wbl + CC, g_k, nullptr,
                      m0, nb0, nb0, sb);
        else
            gemm_core(g_abh, g_abl, g_wbh + CC, g_wbl + CC, g_q, nullptr,
                      m0, nb0, nb0 - CH, sb);
    }
}

// proj GEMM: grid (5, 256); out = g_abh/g_abl @ Wproj^T + bproj
__global__ __launch_bounds__(256, 2) void gemm_proj(
    float* __restrict__ out, const float* __restrict__ bias)
{
    extern __shared__ char smem[];
    const uint32_t sb = (uint32_t)__cvta_generic_to_shared(smem);
    gemm_core(g_abh, g_abl, g_wbh + 3 * CC, g_wbl + 3 * CC, out, bias,
              blockIdx.y * BMM, blockIdx.x * BNN, blockIdx.x * BNN, sb);
}

// ---------------------------------------------------------------------------
// attn GEMM: per head, D[i, d] = Q[i,:128] @ kv2T[d,:128]; K=128 (4 chunks).
// epilogue: val = g_x + z*D; split-write to g_abh/g_abl (proj input).
// grid 1280 linear = bh(40) x mtile(32); 256 threads; same smem layout.
// ---------------------------------------------------------------------------
__global__ __launch_bounds__(256, 2) void attn_gemm() {
    extern __shared__ char smem[];
    const uint32_t sb = (uint32_t)__cvta_generic_to_shared(smem);
    const int bx = blockIdx.x;
    const int bh = bx >> 5;
    const int m0 = (bx & 31) * BMM;       // local i base
    const int b = bh / NH, hoff = (bh % NH) * HD;
    const __nv_bfloat16* Ah = g_qbh + (size_t)b * SEQ * CH + hoff;
    const __nv_bfloat16* Al = g_qbl + (size_t)b * SEQ * CH + hoff;
    const __nv_bfloat16* Bh = g_k2h + (size_t)bh * HD * HD;
    const __nv_bfloat16* Bl = g_k2l + (size_t)bh * HD * HD;

    const int tid = threadIdx.x;
    const int lane = tid & 31;
    const int wid = tid >> 5;
    const int warp_m = wid >> 1;
    const int warp_n = wid & 1;
    const int gid = lane >> 2;
    const int tig = lane & 3;
    const int lr = (lane & 7) + ((lane >> 3) & 1) * 8;
    const uint32_t lc = (uint32_t)(((lane >> 4) & 1) * 16);

    float acc[2][8][4];
#pragma unroll
    for (int t = 0; t < 2; t++)
#pragma unroll
        for (int j = 0; j < 8; j++)
#pragma unroll
            for (int e = 0; e < 4; e++) acc[t][j][e] = 0.f;

    int r0f = tid >> 2, c0f = tid & 3;
    int r1f = (tid + 256) >> 2, c1f = (tid + 256) & 3;
    const uint32_t so0 = (uint32_t)(r0f * RWB + c0f * 16);
    const uint32_t so1 = (uint32_t)(r1f * RWB + c1f * 16);
    const size_t gA0 = (size_t)(m0 + r0f) * CH + c0f * 8;
    const size_t gA1 = (size_t)(m0 + r1f) * CH + c1f * 8;
    const size_t gB0 = (size_t)r0f * HD + c0f * 8;   // B stride = 128
    const size_t gB1 = (size_t)r1f * HD + c1f * 8;

    auto fill = [&](int stage, int chunk) {
        const int k0 = chunk * BKE;
        const uint32_t stb = sb + (uint32_t)(stage * STB);
        cp16(stb + OFFAH + so0, Ah + gA0 + k0);
        cp16(stb + OFFAL + so0, Al + gA0 + k0);
        cp16(stb + OFFBH + so0, Bh + gB0 + k0);
        cp16(stb + OFFBL + so0, Bl + gB0 + k0);
        cp16(stb + OFFAH + so1, Ah + gA1 + k0);
        cp16(stb + OFFAL + so1, Al + gA1 + k0);
        cp16(stb + OFFBH + so1, Bh + gB1 + k0);
        cp16(stb + OFFBL + so1, Bl + gB1 + k0);
        asm volatile("cp.async.commit_group;" ::: "memory");
    };

    const uint32_t raF = (uint32_t)((warp_m * 32 + lr) * RWB) + lc;
    const uint32_t rbF = (uint32_t)((warp_n * 64 + lr) * RWB) + lc;

    fill(0, 0);
#pragma unroll
    for (int i = 0; i < 4; i++) {
        if (i + 1 < 4) {
            fill((i + 1) & 1, i + 1);
            asm volatile("cp.async.wait_group 1;" ::: "memory");
        } else {
            asm volatile("cp.async.wait_group 0;" ::: "memory");
        }
        __syncthreads();

        const uint32_t stb = sb + (uint32_t)((i & 1) * STB);
#pragma unroll
        for (int ks = 0; ks < 2; ks++) {
            const uint32_t kofs = (uint32_t)(ks * 32);
            uint32_t ah[2][4], al[2][4];
#pragma unroll
            for (int t = 0; t < 2; t++) {
                uint32_t ra = stb + OFFAH + raF + (uint32_t)(t * 16 * RWB) + kofs;
                LDM4(ah[t][0], ah[t][1], ah[t][2], ah[t][3], ra);
                LDM4(al[t][0], al[t][1], al[t][2], al[t][3], ra + (OFFAL - OFFAH));
            }
#pragma unroll
            for (int g = 0; g < 4; g++) {
                uint32_t rb = stb + OFFBH + rbF + (uint32_t)(g * 16 * RWB) + kofs;
                uint32_t bh4[4], bl4[4];
                LDM4(bh4[0], bh4[1], bh4[2], bh4[3], rb);
                LDM4(bl4[0], bl4[1], bl4[2], bl4[3], rb + (OFFBL - OFFBH));
                uint32_t b0h[2] = { bh4[0], bh4[2] }, b1h[2] = { bh4[1], bh4[3] };
                uint32_t b0l[2] = { bl4[0], bl4[2] }, b1l[2] = { bl4[1], bl4[3] };
#pragma unroll
                for (int t = 0; t < 2; t++) {
                    MMA_BF16(acc[t][2*g],   ah[t], b0h);
                    MMA_BF16(acc[t][2*g+1], ah[t], b1h);
                }
#pragma unroll
                for (int t = 0; t < 2; t++) {
                    MMA_BF16(acc[t][2*g],   ah[t], b0l);
                    MMA_BF16(acc[t][2*g+1], ah[t], b1l);
                }
#pragma unroll
                for (int t = 0; t < 2; t++) {
                    MMA_BF16(acc[t][2*g],   al[t], b0h);
                    MMA_BF16(acc[t][2*g+1], al[t], b1h);
                }
            }
        }
        __syncthreads();
    }

    // epilogue: conv add + z scale + split write (proj input)
#pragma unroll
    for (int t = 0; t < 2; t++) {
        int i0 = m0 + warp_m * 32 + t * 16 + gid;   // local i (row-0 of pair)
#pragma unroll
        for (int j = 0; j < 8; j++) {
            int d = warp_n * 64 + j * 8 + 2 * tig;
#pragma unroll
            for (int half = 0; half < 2; half++) {
                int i = i0 + half * 8;
                float zv = g_z[bh * SEQ + i];
                size_t base = (size_t)(b * SEQ + i) * CH + hoff + d;
                float f0 = g_x[base]     + acc[t][j][half * 2]     * zv;
                float f1 = g_x[base + 1] + acc[t][j][half * 2 + 1] * zv;
                __nv_bfloat16 h0 = __float2bfloat16_rn(f0);
                __nv_bfloat16 h1 = __float2bfloat16_rn(f1);
                __nv_bfloat16 l0 = __float2bfloat16_rn(f0 - __bfloat162float(h0));
                __nv_bfloat16 l1 = __float2bfloat16_rn(f1 - __bfloat162float(h1));
                *reinterpret_cast<__nv_bfloat162*>(&g_abh[base]) = { h0, h1 };
                *reinterpret_cast<__nv_bfloat162*>(&g_abl[base]) = { l0, l1 };
            }
        }
    }
}

// ---------------------------------------------------------------------------
__global__ void softplus_kernel(const float* __restrict__ scale) {
    int c = blockIdx.x * 256 + threadIdx.x;
    if (c < CH) g_sc[c] = log1pf(expf(scale[c]));
}

// ---------------------------------------------------------------------------
__device__ __forceinline__ float warp_sum(float s) {
#pragma unroll
    for (int o = 16; o > 0; o >>= 1) s += __shfl_xor_sync(0xffffffffu, s, o);
    return s;
}

// qknorm: warp per row; q out -> bf16 hi/lo; k out -> fp32 in place.
__global__ __launch_bounds__(256) void qknorm_kernel(const float* __restrict__ pos) {
    const int w = blockIdx.x * 8 + (threadIdx.x >> 5);
    const int lane = threadIdx.x & 31;
    const size_t row = (size_t)w;
    const int n = w & (SEQ - 1);
    const float* qrow = g_q + row * CH;
    float* krow = g_k + row * CH;
    const float* prow = pos + (size_t)n * CH;

    float scv[20];
#pragma unroll
    for (int t = 0; t < 20; t++) scv[t] = g_sc[lane + 32 * t];

    // ---- q -> bf16 hi/lo ----
    {
        float v[20]; float s = 0.f;
#pragma unroll
        for (int t = 0; t < 20; t++) {
            float raw = qrow[lane + 32 * t];
            float val = (fmaxf(raw, 0.f) + 1e-6f) / scv[t];
            v[t] = val; s += val * val;
        }
        float n1 = sqrtf(warp_sum(s));
        s = 0.f;
#pragma unroll
        for (int t = 0; t < 20; t++) { float c3 = v[t]*v[t]*v[t]; v[t] = c3; s += c3*c3; }
        float sc2 = n1 / sqrtf(warp_sum(s));
#pragma unroll
        for (int t = 0; t < 20; t++) {
            float f = v[t] * sc2;
            __nv_bfloat16 h = __float2bfloat16_rn(f);
            __nv_bfloat16 l = __float2bfloat16_rn(f - __bfloat162float(h));
            g_qbh[row * CH + lane + 32 * t] = h;
            g_qbl[row * CH + lane + 32 * t] = l;
        }
    }
    // ---- k -> fp32 ----
    {
        float v[20]; float s = 0.f;
#pragma unroll
        for (int t = 0; t < 20; t++) {
            float raw = krow[lane + 32 * t] + prow[lane + 32 * t];
            float val = (fmaxf(raw, 0.f) + 1e-6f) / scv[t];
            v[t] = val; s += val * val;
        }
        float n1 = sqrtf(warp_sum(s));
        s = 0.f;
#pragma unroll
        for (int t = 0; t < 20; t++) { float c3 = v[t]*v[t]*v[t]; v[t] = c3; s += c3*c3; }
        float sc2 = n1 / sqrtf(warp_sum(s));
#pragma unroll
        for (int t = 0; t < 20; t++) krow[lane + 32 * t] = v[t] * sc2;
    }
}

__global__ void zero_kernel() {
    int idx = blockIdx.x * 256 + threadIdx.x;
    if (idx < BH * HD * HD) g_kv2[idx] = 0.f;
    if (idx < BH * HD)      g_ksum[idx] = 0.f;
}

__global__ __launch_bounds__(128) void ksum_kernel() {
    const int bh = blockIdx.x, jc = blockIdx.y;
    const int b = bh / NH, hoff = (bh % NH) * HD;
    const float* Kp = g_k + (size_t)b * SEQ * CH + hoff + threadIdx.x;
    const int j0 = jc * 128;
    float s = 0.f;
#pragma unroll 8
    for (int j = 0; j < 128; j++) s += Kp[(size_t)(j0 + j) * CH];
    atomicAdd(&g_ksum[bh * HD + threadIdx.x], s);
}

// ---- packed f32x2 helpers (kv2 only) ----
__device__ __forceinline__ unsigned long long pk2(float lo, float hi) {
    unsigned long long r;
    asm("mov.b64 %0, {%1, %2};" : "=l"(r) : "f"(lo), "f"(hi));
    return r;
}
__device__ __forceinline__ float2 upk(unsigned long long v) {
    float2 f;
    asm("mov.b64 {%0, %1}, %2;" : "=f"(f.x), "=f"(f.y) : "l"(v));
    return f;
}
#define FMA2(d, a, b) asm("fma.rn.f32x2 %0, %1, %2, %0;" : "+l"(d) : "l"(a), "l"(b))

__global__ __launch_bounds__(256) void kv2_kernel() {
    const int bh = blockIdx.x, jc = blockIdx.y;
    const int b = bh / NH, hoff = (bh % NH) * HD;
    const float* Kp = g_k + (size_t)b * SEQ * CH + hoff;
    const float* Vp = g_v + (size_t)b * SEQ * CH + hoff;
    __shared__ float Ks[16][132];
    __shared__ float Vs[16][132];
    const int tid = threadIdx.x;
    const int tx = tid & 15, ty = tid >> 4;

    unsigned long long acc[8][4];
#pragma unroll
    for (int r = 0; r < 8; r++)
#pragma unroll
        for (int c = 0; c < 4; c++) acc[r][c] = 0ull;

    const int jbase = jc * 512;
    for (int j0 = jbase; j0 < jbase + 512; j0 += 16) {
#pragma unroll
        for (int i = 0; i < 2; i++) {
            int f = tid + i * 256;
            int jj = f >> 5, cq = f & 31;
            float4 kv4 = *reinterpret_cast<const float4*>(&Kp[(size_t)(j0 + jj) * CH + cq * 4]);
            *reinterpret_cast<float4*>(&Ks[jj][cq * 4]) = kv4;
            float4 vv4 = *reinterpret_cast<const float4*>(&Vp[(size_t)(j0 + jj) * CH + cq * 4]);
            *reinterpret_cast<float4*>(&Vs[jj][cq * 4]) = vv4;
        }
        __syncthreads();
#pragma unroll
        for (int jj = 0; jj < 16; jj++) {
            float4 a0 = *reinterpret_cast<const float4*>(&Ks[jj][ty * 4]);
            float4 a1 = *reinterpret_cast<const float4*>(&Ks[jj][64 + ty * 4]);
            unsigned long long ad[8];
            ad[0] = pk2(a0.x, a0.x); ad[1] = pk2(a0.y, a0.y);
            ad[2] = pk2(a0.z, a0.z); ad[3] = pk2(a0.w, a0.w);
            ad[4] = pk2(a1.x, a1.x); ad[5] = pk2(a1.y, a1.y);
            ad[6] = pk2(a1.z, a1.z); ad[7] = pk2(a1.w, a1.w);
            const unsigned long long* b0 =
                reinterpret_cast<const unsigned long long*>(&Vs[jj][tx * 4]);
            const unsigned long long* b1 =
                reinterpret_cast<const unsigned long long*>(&Vs[jj][64 + tx * 4]);
            unsigned long long bb[4] = { b0[0], b0[1], b1[0], b1[1] };
#pragma unroll
            for (int r = 0; r < 8; r++)
#pragma unroll
                for (int c = 0; c < 4; c++) FMA2(acc[r][c], ad[r], bb[c]);
        }
        __syncthreads();
    }
    float* dst = g_kv2 + bh * HD * HD;
#pragma unroll
    for (int r = 0; r < 8; r++) {
        int cdx = (r < 4) ? (ty * 4 + r) : (64 + ty * 4 + r - 4);
#pragma unroll
        for (int c = 0; c < 4; c++) {
            int ddx = (c < 2) ? (tx * 4 + 2 * c) : (64 + tx * 4 + 2 * (c - 2));
            float2 v = upk(acc[r][c]);
            atomicAdd(&dst[cdx * HD + ddx], v.x);
            atomicAdd(&dst[cdx * HD + ddx + 1], v.y);
        }
    }
}

// kv2^T + bf16 split: [bh][c][d] fp32 -> [bh][d][c] hi/lo
__global__ __launch_bounds__(256) void kv2t_split() {
    const int bh = blockIdx.x;
    const int e = blockIdx.y * 256 + threadIdx.x;   // 0..16383
    const int d = e >> 7, c = e & 127;
    float v = g_kv2[bh * HD * HD + c * HD + d];
    __nv_bfloat16 h = __float2bfloat16_rn(v);
    __nv_bfloat16 l = __float2bfloat16_rn(v - __bfloat162float(h));
    g_k2h[bh * HD * HD + d * HD + c] = h;
    g_k2l[bh * HD * HD + d * HD + c] = l;
}

__global__ __launch_bounds__(256) void zrow_kernel() {
    const int gw = blockIdx.x * 8 + (threadIdx.x >> 5);
    const int lane = threadIdx.x & 31;
    const int bh = gw >> 12;
    const int i = gw & (SEQ - 1);
    const int b = bh / NH, hoff = (bh % NH) * HD;
    const size_t qb = (size_t)(b * SEQ + i) * CH + hoff;
    const float* ks = g_ksum + bh * HD;
    float s = 0.f;
#pragma unroll
    for (int t = 0; t < 4; t++) {
        int c = lane + 32 * t;
        float qv = __bfloat162float(g_qbh[qb + c]) + __bfloat162float(g_qbl[qb + c]);
        s += qv * ks[c];
    }
#pragma unroll
    for (int o = 16; o > 0; o >>= 1) s += __shfl_xor_sync(0xffffffffu, s, o);
    if (lane == 0) g_z[bh * SEQ + i] = 1.f / (s + 1e-6f);
}

// ---------------------------------------------------------------------------
__global__ __launch_bounds__(256) void conv_s(
    const float* __restrict__ w, const float* __restrict__ bias)
{
    extern __shared__ float sv[];
    const int bh = blockIdx.x, yt = blockIdx.y, dc = blockIdx.z;
    const int b = bh / NH, hoff = (bh % NH) * HD;
    const int tid = threadIdx.x;
    const int d = tid & 31;
    const int xg = tid >> 5;
    const float* vbase = g_v + (size_t)b * SEQ * CH + hoff + dc * 32;

    {
        int p = tid;
        int r = p >> 5, rest = p & 31;
        int xi = rest >> 3, d4 = rest & 7;
        int ix = (xi < 2) ? xi : (xi + 64);
        *reinterpret_cast<float4*>(&sv[(r * 68 + ix) * 32 + d4 * 4]) =
            make_float4(0.f, 0.f, 0.f, 0.f);
    }
    for (int p = tid; p < 8 * 512; p += 256) {
        int r = p >> 9, rest = p & 511;
        int x = rest >> 3, d4 = rest & 7;
        int y = yt * 4 - 2 + r;
        float4 val = make_float4(0.f, 0.f, 0.f, 0.f);
        if ((unsigned)y < 64u)
            val = *reinterpret_cast<const float4*>(
                &vbase[(size_t)(y * 64 + x) * CH + d4 * 4]);
        *reinterpret_cast<float4*>(&sv[(r * 68 + x + 2) * 32 + d4 * 4]) = val;
    }
    __syncthreads();

    float wr[25];
#pragma unroll
    for (int k = 0; k < 25; k++) wr[k] = __ldg(&w[(dc * 32 + d) * 25 + k]);
    const float bv = __ldg(&bias[dc * 32 + d]);

#pragma unroll
    for (int y = 0; y < 4; y++) {
#pragma unroll
        for (int xo = 0; xo < 8; xo++) {
            int x = xg * 8 + xo;
            float acc = bv;
#pragma unroll
            for (int ky = 0; ky < 5; ky++)
#pragma unroll
                for (int kx = 0; kx < 5; kx++)
                    acc += wr[ky * 5 + kx] * sv[((y + ky) * 68 + (x + kx)) * 32 + d];
            int oy = yt * 4 + y;
            g_x[(size_t)(b * SEQ + oy * 64 + x) * CH + hoff + dc * 32 + d] = acc;
        }
    }
}

// ---------------------------------------------------------------------------
extern "C" void kernel_launch(void* const* d_in, const int* in_sizes, int n_in,
                              void* d_out, int out_size)
{
    const float* x1    = (const float*)d_in[0];
    const float* x2    = (const float*)d_in[1];
    const float* Wq    = (const float*)d_in[2];
    const float* Wkv   = (const float*)d_in[3];
    const float* Wproj = (const float*)d_in[4];
    const float* bproj = (const float*)d_in[5];
    const float* dwc_w = (const float*)d_in[6];
    const float* dwc_b = (const float*)d_in[7];
    const float* scale = (const float*)d_in[8];
    const float* pos   = (const float*)d_in[9];
    float* out = (float*)d_out;

    __nv_bfloat16 *pah, *pal, *pa2h, *pa2l;
    cudaGetSymbolAddress((void**)&pah, g_abh);
    cudaGetSymbolAddress((void**)&pal, g_abl);
    cudaGetSymbolAddress((void**)&pa2h, g_a2h);
    cudaGetSymbolAddress((void**)&pa2l, g_a2l);

    cudaFuncSetAttribute(gemm_merged,
        cudaFuncAttributeMaxDynamicSharedMemorySize, SMEM_GB);
    cudaFuncSetAttribute(gemm_proj,
        cudaFuncAttributeMaxDynamicSharedMemorySize, SMEM_GB);
    cudaFuncSetAttribute(attn_gemm,
        cudaFuncAttributeMaxDynamicSharedMemorySize, SMEM_GB);
    cudaFuncSetAttribute(conv_s,
        cudaFuncAttributeMaxDynamicSharedMemorySize, 8 * 68 * 32 * 4);

    const int M = BATCH * SEQ;              // 32768
    const int XN4 = M * CH / 4;

    split_w<<<4 * CC / 1024, 256>>>(Wq, Wkv, Wproj);                  // 0
    softplus_kernel<<<3, 256>>>(scale);                               // 1
    split_x<<<XN4 / 256, 256>>>(x1, pah, pal, XN4);                   // 2
    split_x<<<XN4 / 256, 256>>>(x2, pa2h, pa2l, XN4);                 // 3
    gemm_merged<<<dim3(15, M / BMM), 256, SMEM_GB>>>();               // 4: v+k+q

    qknorm_kernel<<<M / 8, 256>>>(pos);
    zero_kernel<<<(BH * HD * HD + 255) / 256, 256>>>();
    ksum_kernel<<<dim3(BH, 32), 128>>>();
    kv2_kernel<<<dim3(BH, 8), 256>>>();
    kv2t_split<<<dim3(BH, 64), 256>>>();
    zrow_kernel<<<BH * SEQ / 8, 256>>>();
    conv_s<<<dim3(BH, 16, 4), 256, 8 * 68 * 32 * 4>>>(dwc_w, dwc_b);
    attn_gemm<<<BH * 32, 256, SMEM_GB>>>();

    gemm_proj<<<dim3(5, M / BMM), 256, SMEM_GB>>>(out, bproj);
}

// round 11
// speedup vs baseline: 1.7378x; 1.0140x over previous
#include <cuda_runtime.h>
#include <cuda_bf16.h>
#include <cstdint>
#include <cstddef>

// ---------------------------------------------------------------------------
// FocusedLinearAttention — round 11: resubmit of round 10 (infra retry)
//   ksum folded into kv2 (smem reuse) + z folded into attn_gemm.
//   ksum_kernel and zrow_kernel deleted (−252 MB HBM, −2 launches).
// ---------------------------------------------------------------------------

#define BATCH 8
#define SEQ   4096
#define CH    640
#define CC    (CH*CH)
#define NH    5
#define HD    128
#define BH    (BATCH*NH)   // 40

#define BMM 128
#define BNN 128
#define BKE 32
#define NCHB (CH/BKE)           // 20
#define RWB 80
#define BUFB (128*RWB)
#define OFFAH 0
#define OFFAL BUFB
#define OFFBH (2*BUFB)
#define OFFBL (3*BUFB)
#define STB   (4*BUFB)          // 40960 B
#define SMEM_GB (2*STB)         // 81920 B -> 2 CTAs/SM

__device__ float g_v[BATCH*SEQ*CH];
__device__ float g_q[BATCH*SEQ*CH];      // raw q (gemm out, qknorm in)
__device__ float g_k[BATCH*SEQ*CH];      // raw/focused k (fp32)
__device__ float g_x[BATCH*SEQ*CH];      // conv output
__device__ __nv_bfloat16 g_abh[BATCH*SEQ*CH];   // x1 split -> later proj input
__device__ __nv_bfloat16 g_abl[BATCH*SEQ*CH];
__device__ __nv_bfloat16 g_a2h[BATCH*SEQ*CH];   // x2 split
__device__ __nv_bfloat16 g_a2l[BATCH*SEQ*CH];
__device__ __nv_bfloat16 g_qbh[BATCH*SEQ*CH];   // focused q split
__device__ __nv_bfloat16 g_qbl[BATCH*SEQ*CH];
__device__ __nv_bfloat16 g_wbh[4*CC];
__device__ __nv_bfloat16 g_wbl[4*CC];
__device__ __nv_bfloat16 g_k2h[BH*HD*HD];       // kv2^T split [bh][d][c]
__device__ __nv_bfloat16 g_k2l[BH*HD*HD];
__device__ float g_kv2[BH*HD*HD];
__device__ float g_ksum[BH*HD];
__device__ float g_sc[CH];

// ---------------------------------------------------------------------------
__device__ __forceinline__ void cp16(uint32_t dst, const void* src) {
    asm volatile("cp.async.cg.shared.global [%0], [%1], 16;" :: "r"(dst), "l"(src));
}

#define LDM4(r0, r1, r2, r3, a) \
    asm volatile("ldmatrix.sync.aligned.m8n8.x4.shared.b16 {%0,%1,%2,%3}, [%4];" \
        : "=r"(r0), "=r"(r1), "=r"(r2), "=r"(r3) : "r"(a))

#define MMA_BF16(d, a, b) \
    asm volatile( \
        "mma.sync.aligned.m16n8k16.row.col.f32.bf16.bf16.f32 " \
        "{%0,%1,%2,%3}, {%4,%5,%6,%7}, {%8,%9}, {%0,%1,%2,%3};" \
        : "+f"((d)[0]), "+f"((d)[1]), "+f"((d)[2]), "+f"((d)[3]) \
        : "r"((a)[0]), "r"((a)[1]), "r"((a)[2]), "r"((a)[3]), \
          "r"((b)[0]), "r"((b)[1]))

// ---------------------------------------------------------------------------
__device__ __forceinline__ void split4(float4 v, __nv_bfloat16* hp, __nv_bfloat16* lp) {
    float f[4] = { v.x, v.y, v.z, v.w };
    __nv_bfloat16 h[4], l[4];
#pragma unroll
    for (int j = 0; j < 4; j++) {
        h[j] = __float2bfloat16_rn(f[j]);
        l[j] = __float2bfloat16_rn(f[j] - __bfloat162float(h[j]));
    }
    *reinterpret_cast<__nv_bfloat162*>(hp)     = { h[0], h[1] };
    *reinterpret_cast<__nv_bfloat162*>(hp + 2) = { h[2], h[3] };
    *reinterpret_cast<__nv_bfloat162*>(lp)     = { l[0], l[1] };
    *reinterpret_cast<__nv_bfloat162*>(lp + 2) = { l[2], l[3] };
}

__global__ __launch_bounds__(256) void split_x(
    const float* __restrict__ src, __nv_bfloat16* __restrict__ hi,
    __nv_bfloat16* __restrict__ lo, int n4)
{
    int i = blockIdx.x * 256 + threadIdx.x;
    if (i >= n4) return;
    split4(reinterpret_cast<const float4*>(src)[i], hi + 4 * i, lo + 4 * i);
}

__global__ __launch_bounds__(256) void split_w(
    const float* __restrict__ Wq, const float* __restrict__ Wkv,
    const float* __restrict__ Wproj)
{
    int i = blockIdx.x * 256 + threadIdx.x;
    int fi = i * 4;
    const float* src; int off;
    if (fi < CC)          { src = Wq;    off = 0; }
    else if (fi < 3 * CC) { src = Wkv;   off = CC; }
    else                  { src = Wproj; off = 3 * CC; }
    float4 v = *reinterpret_cast<const float4*>(&src[fi - off]);
    split4(v, g_wbh + fi, g_wbl + fi);
}

// ---------------------------------------------------------------------------
// common bf16x3 GEMM core (K = 640)
// ---------------------------------------------------------------------------
__device__ __forceinline__ void gemm_core(
    const __nv_bfloat16* __restrict__ Ah, const __nv_bfloat16* __restrict__ Al,
    const __nv_bfloat16* __restrict__ Bh, const __nv_bfloat16* __restrict__ Bl,
    float* __restrict__ Cout, const float* __restrict__ bias,
    int m0, int nb0, int n0, uint32_t sb)
{
    const int tid = threadIdx.x;
    const int lane = tid & 31;
    const int wid = tid >> 5;
    const int warp_m = wid >> 1;
    const int warp_n = wid & 1;
    const int gid = lane >> 2;
    const int tig = lane & 3;
    const int lr = (lane & 7) + ((lane >> 3) & 1) * 8;
    const uint32_t lc = (uint32_t)(((lane >> 4) & 1) * 16);

    float acc[2][8][4];
#pragma unroll
    for (int t = 0; t < 2; t++)
#pragma unroll
        for (int j = 0; j < 8; j++)
#pragma unroll
            for (int e = 0; e < 4; e++) acc[t][j][e] = 0.f;

    int r0f = tid >> 2, c0f = tid & 3;
    int r1f = (tid + 256) >> 2, c1f = (tid + 256) & 3;
    const uint32_t so0 = (uint32_t)(r0f * RWB + c0f * 16);
    const uint32_t so1 = (uint32_t)(r1f * RWB + c1f * 16);
    const size_t gA0 = (size_t)(m0 + r0f) * CH + c0f * 8;
    const size_t gA1 = (size_t)(m0 + r1f) * CH + c1f * 8;
    const size_t gB0 = (size_t)(nb0 + r0f) * CH + c0f * 8;
    const size_t gB1 = (size_t)(nb0 + r1f) * CH + c1f * 8;

    auto fill = [&](int stage, int chunk) {
        const int k0 = chunk * BKE;
        const uint32_t stb = sb + (uint32_t)(stage * STB);
        cp16(stb + OFFAH + so0, Ah + gA0 + k0);
        cp16(stb + OFFAL + so0, Al + gA0 + k0);
        cp16(stb + OFFBH + so0, Bh + gB0 + k0);
        cp16(stb + OFFBL + so0, Bl + gB0 + k0);
        cp16(stb + OFFAH + so1, Ah + gA1 + k0);
        cp16(stb + OFFAL + so1, Al + gA1 + k0);
        cp16(stb + OFFBH + so1, Bh + gB1 + k0);
        cp16(stb + OFFBL + so1, Bl + gB1 + k0);
        asm volatile("cp.async.commit_group;" ::: "memory");
    };

    const uint32_t raF = (uint32_t)((warp_m * 32 + lr) * RWB) + lc;
    const uint32_t rbF = (uint32_t)((warp_n * 64 + lr) * RWB) + lc;

    fill(0, 0);
    for (int i = 0; i < NCHB; i++) {
        if (i + 1 < NCHB) {
            fill((i + 1) & 1, i + 1);
            asm volatile("cp.async.wait_group 1;" ::: "memory");
        } else {
            asm volatile("cp.async.wait_group 0;" ::: "memory");
        }
        __syncthreads();

        const uint32_t stb = sb + (uint32_t)((i & 1) * STB);
#pragma unroll
        for (int ks = 0; ks < 2; ks++) {
            const uint32_t kofs = (uint32_t)(ks * 32);
            uint32_t ah[2][4], al[2][4];
#pragma unroll
            for (int t = 0; t < 2; t++) {
                uint32_t ra = stb + OFFAH + raF + (uint32_t)(t * 16 * RWB) + kofs;
                LDM4(ah[t][0], ah[t][1], ah[t][2], ah[t][3], ra);
                LDM4(al[t][0], al[t][1], al[t][2], al[t][3], ra + (OFFAL - OFFAH));
            }
#pragma unroll
            for (int g = 0; g < 4; g++) {
                uint32_t rb = stb + OFFBH + rbF + (uint32_t)(g * 16 * RWB) + kofs;
                uint32_t bh4[4], bl4[4];
                LDM4(bh4[0], bh4[1], bh4[2], bh4[3], rb);
                LDM4(bl4[0], bl4[1], bl4[2], bl4[3], rb + (OFFBL - OFFBH));
                uint32_t b0h[2] = { bh4[0], bh4[2] }, b1h[2] = { bh4[1], bh4[3] };
                uint32_t b0l[2] = { bl4[0], bl4[2] }, b1l[2] = { bl4[1], bl4[3] };
#pragma unroll
                for (int t = 0; t < 2; t++) {
                    MMA_BF16(acc[t][2*g],   ah[t], b0h);
                    MMA_BF16(acc[t][2*g+1], ah[t], b1h);
                }
#pragma unroll
                for (int t = 0; t < 2; t++) {
                    MMA_BF16(acc[t][2*g],   ah[t], b0l);
                    MMA_BF16(acc[t][2*g+1], ah[t], b1l);
                }
#pragma unroll
                for (int t = 0; t < 2; t++) {
                    MMA_BF16(acc[t][2*g],   al[t], b0h);
                    MMA_BF16(acc[t][2*g+1], al[t], b1h);
                }
            }
        }
        __syncthreads();
    }

#pragma unroll
    for (int t = 0; t < 2; t++) {
        int r0 = m0 + warp_m * 32 + t * 16 + gid;
#pragma unroll
        for (int j = 0; j < 8; j++) {
            int cc = n0 + warp_n * 64 + j * 8 + 2 * tig;
            float b0 = bias ? bias[cc] : 0.f;
            float b1 = bias ? bias[cc + 1] : 0.f;
            float2 v0 = make_float2(acc[t][j][0] + b0, acc[t][j][1] + b1);
            float2 v1 = make_float2(acc[t][j][2] + b0, acc[t][j][3] + b1);
            *reinterpret_cast<float2*>(&Cout[(size_t)r0 * CH + cc]) = v0;
            *reinterpret_cast<float2*>(&Cout[(size_t)(r0 + 8) * CH + cc]) = v1;
        }
    }
}

// merged v + kq GEMM: grid (15, 256)
__global__ __launch_bounds__(256, 2) void gemm_merged() {
    extern __shared__ char smem[];
    const uint32_t sb = (uint32_t)__cvta_generic_to_shared(smem);
    const int m0 = blockIdx.y * BMM;
    const int bx = blockIdx.x;
    if (bx < 5) {
        gemm_core(g_a2h, g_a2l, g_wbh, g_wbl, g_v, nullptr,
                  m0, bx * BNN, bx * BNN, sb);
    } else {
        int nb0 = (bx - 5) * BNN;
        if (nb0 < CH)
            gemm_core(g_abh, g_abl, g_wbh + CC, g_wbl + CC, g_k, nullptr,
                      m0, nb0, nb0, sb);
        else
            gemm_core(g_abh, g_abl, g_wbh + CC, g_wbl + CC, g_q, nullptr,
                      m0, nb0, nb0 - CH, sb);
    }
}

// proj GEMM: grid (5, 256)
__global__ __launch_bounds__(256, 2) void gemm_proj(
    float* __restrict__ out, const float* __restrict__ bias)
{
    extern __shared__ char smem[];
    const uint32_t sb = (uint32_t)__cvta_generic_to_shared(smem);
    gemm_core(g_abh, g_abl, g_wbh + 3 * CC, g_wbl + 3 * CC, out, bias,
              blockIdx.y * BMM, blockIdx.x * BNN, blockIdx.x * BNN, sb);
}

// ---------------------------------------------------------------------------
// attn GEMM with fused z: per head, D[i,d] = Q[i]·kv2T[d]; K=128 (4 chunks).
// z[i] = 1/(Q[i]·ksum + eps) computed from the SAME smem Q tiles.
// epilogue: val = g_x + z*D; split-write to g_abh/g_abl.
// ---------------------------------------------------------------------------
__global__ __launch_bounds__(256, 2) void attn_gemm() {
    extern __shared__ char smem[];
    const uint32_t sb = (uint32_t)__cvta_generic_to_shared(smem);
    const int bx = blockIdx.x;
    const int bh = bx >> 5;
    const int m0 = (bx & 31) * BMM;
    const int b = bh / NH, hoff = (bh % NH) * HD;
    const __nv_bfloat16* Ah = g_qbh + (size_t)b * SEQ * CH + hoff;
    const __nv_bfloat16* Al = g_qbl + (size_t)b * SEQ * CH + hoff;
    const __nv_bfloat16* Bh = g_k2h + (size_t)bh * HD * HD;
    const __nv_bfloat16* Bl = g_k2l + (size_t)bh * HD * HD;

    const int tid = threadIdx.x;
    const int lane = tid & 31;
    const int wid = tid >> 5;
    const int warp_m = wid >> 1;
    const int warp_n = wid & 1;
    const int gid = lane >> 2;
    const int tig = lane & 3;
    const int lr = (lane & 7) + ((lane >> 3) & 1) * 8;
    const uint32_t lc = (uint32_t)(((lane >> 4) & 1) * 16);

    float acc[2][8][4];
#pragma unroll
    for (int t = 0; t < 2; t++)
#pragma unroll
        for (int j = 0; j < 8; j++)
#pragma unroll
            for (int e = 0; e < 4; e++) acc[t][j][e] = 0.f;

    int r0f = tid >> 2, c0f = tid & 3;
    int r1f = (tid + 256) >> 2, c1f = (tid + 256) & 3;
    const uint32_t so0 = (uint32_t)(r0f * RWB + c0f * 16);
    const uint32_t so1 = (uint32_t)(r1f * RWB + c1f * 16);
    const size_t gA0 = (size_t)(m0 + r0f) * CH + c0f * 8;
    const size_t gA1 = (size_t)(m0 + r1f) * CH + c1f * 8;
    const size_t gB0 = (size_t)r0f * HD + c0f * 8;
    const size_t gB1 = (size_t)r1f * HD + c1f * 8;

    auto fill = [&](int stage, int chunk) {
        const int k0 = chunk * BKE;
        const uint32_t stb = sb + (uint32_t)(stage * STB);
        cp16(stb + OFFAH + so0, Ah + gA0 + k0);
        cp16(stb + OFFAL + so0, Al + gA0 + k0);
        cp16(stb + OFFBH + so0, Bh + gB0 + k0);
        cp16(stb + OFFBL + so0, Bl + gB0 + k0);
        cp16(stb + OFFAH + so1, Ah + gA1 + k0);
        cp16(stb + OFFAL + so1, Al + gA1 + k0);
        cp16(stb + OFFBH + so1, Bh + gB1 + k0);
        cp16(stb + OFFBL + so1, Bl + gB1 + k0);
        asm volatile("cp.async.commit_group;" ::: "memory");
    };

    const uint32_t raF = (uint32_t)((warp_m * 32 + lr) * RWB) + lc;
    const uint32_t rbF = (uint32_t)((warp_n * 64 + lr) * RWB) + lc;

    float zacc = 0.f;    // threads 0..127: q-row · ksum partial

    fill(0, 0);
#pragma unroll
    for (int i = 0; i < 4; i++) {
        if (i + 1 < 4) {
            fill((i + 1) & 1, i + 1);
            asm volatile("cp.async.wait_group 1;" ::: "memory");
        } else {
            asm volatile("cp.async.wait_group 0;" ::: "memory");
        }
        __syncthreads();

        const uint32_t stb = sb + (uint32_t)((i & 1) * STB);

        // fused z: thread t<128 handles local row t over this chunk's 32 c's
        if (tid < 128) {
            const uint32_t qh = stb + OFFAH + (uint32_t)(tid * RWB);
            const float* ksp = g_ksum + bh * HD + i * BKE;
#pragma unroll
            for (int cc = 0; cc < 32; cc += 2) {
                uint32_t hv, lv;
                asm("ld.shared.b32 %0, [%1];" : "=r"(hv) : "r"(qh + cc * 2));
                asm("ld.shared.b32 %0, [%1];" : "=r"(lv)
                    : "r"(qh + (OFFAL - OFFAH) + cc * 2));
                __nv_bfloat162 h2 = *reinterpret_cast<__nv_bfloat162*>(&hv);
                __nv_bfloat162 l2 = *reinterpret_cast<__nv_bfloat162*>(&lv);
                float q0 = __bfloat162float(h2.x) + __bfloat162float(l2.x);
                float q1 = __bfloat162float(h2.y) + __bfloat162float(l2.y);
                zacc += q0 * __ldg(ksp + cc) + q1 * __ldg(ksp + cc + 1);
            }
        }

#pragma unroll
        for (int ks = 0; ks < 2; ks++) {
            const uint32_t kofs = (uint32_t)(ks * 32);
            uint32_t ah[2][4], al[2][4];
#pragma unroll
            for (int t = 0; t < 2; t++) {
                uint32_t ra = stb + OFFAH + raF + (uint32_t)(t * 16 * RWB) + kofs;
                LDM4(ah[t][0], ah[t][1], ah[t][2], ah[t][3], ra);
                LDM4(al[t][0], al[t][1], al[t][2], al[t][3], ra + (OFFAL - OFFAH));
            }
#pragma unroll
            for (int g = 0; g < 4; g++) {
                uint32_t rb = stb + OFFBH + rbF + (uint32_t)(g * 16 * RWB) + kofs;
                uint32_t bh4[4], bl4[4];
                LDM4(bh4[0], bh4[1], bh4[2], bh4[3], rb);
                LDM4(bl4[0], bl4[1], bl4[2], bl4[3], rb + (OFFBL - OFFBH));
                uint32_t b0h[2] = { bh4[0], bh4[2] }, b1h[2] = { bh4[1], bh4[3] };
                uint32_t b0l[2] = { bl4[0], bl4[2] }, b1l[2] = { bl4[1], bl4[3] };
#pragma unroll
                for (int t = 0; t < 2; t++) {
                    MMA_BF16(acc[t][2*g],   ah[t], b0h);
                    MMA_BF16(acc[t][2*g+1], ah[t], b1h);
                }
#pragma unroll
                for (int t = 0; t < 2; t++) {
                    MMA_BF16(acc[t][2*g],   ah[t], b0l);
                    MMA_BF16(acc[t][2*g+1], ah[t], b1l);
                }
#pragma unroll
                for (int t = 0; t < 2; t++) {
                    MMA_BF16(acc[t][2*g],   al[t], b0h);
                    MMA_BF16(acc[t][2*g+1], al[t], b1h);
                }
            }
        }
        __syncthreads();
    }

    // exchange z through smem (stage 0 A-region is dead now)
    float* zs = reinterpret_cast<float*>(smem);
    if (tid < 128) zs[tid] = 1.f / (zacc + 1e-6f);
    __syncthreads();

    // epilogue: conv add + z scale + split write (proj input)
#pragma unroll
    for (int t = 0; t < 2; t++) {
        int lr0 = warp_m * 32 + t * 16 + gid;   // local row (0..127)
#pragma unroll
        for (int j = 0; j < 8; j++) {
            int d = warp_n * 64 + j * 8 + 2 * tig;
#pragma unroll
            for (int half = 0; half < 2; half++) {
                int lrow = lr0 + half * 8;
                int i = m0 + lrow;
                float zv = zs[lrow];
                size_t base = (size_t)(b * SEQ + i) * CH + hoff + d;
                float f0 = g_x[base]     + acc[t][j][half * 2]     * zv;
                float f1 = g_x[base + 1] + acc[t][j][half * 2 + 1] * zv;
                __nv_bfloat16 h0 = __float2bfloat16_rn(f0);
                __nv_bfloat16 h1 = __float2bfloat16_rn(f1);
                __nv_bfloat16 l0 = __float2bfloat16_rn(f0 - __bfloat162float(h0));
                __nv_bfloat16 l1 = __float2bfloat16_rn(f1 - __bfloat162float(h1));
                *reinterpret_cast<__nv_bfloat162*>(&g_abh[base]) = { h0, h1 };
                *reinterpret_cast<__nv_bfloat162*>(&g_abl[base]) = { l0, l1 };
            }
        }
    }
}

// ---------------------------------------------------------------------------
__global__ void softplus_kernel(const float* __restrict__ scale) {
    int c = blockIdx.x * 256 + threadIdx.x;
    if (c < CH) g_sc[c] = log1pf(expf(scale[c]));
}

// ---------------------------------------------------------------------------
__device__ __forceinline__ float warp_sum(float s) {
#pragma unroll
    for (int o = 16; o > 0; o >>= 1) s += __shfl_xor_sync(0xffffffffu, s, o);
    return s;
}

// qknorm: warp per row; q -> bf16 hi/lo; k -> fp32 in place.
__global__ __launch_bounds__(256) void qknorm_kernel(const float* __restrict__ pos) {
    const int w = blockIdx.x * 8 + (threadIdx.x >> 5);
    const int lane = threadIdx.x & 31;
    const size_t row = (size_t)w;
    const int n = w & (SEQ - 1);
    const float* qrow = g_q + row * CH;
    float* krow = g_k + row * CH;
    const float* prow = pos + (size_t)n * CH;

    float scv[20];
#pragma unroll
    for (int t = 0; t < 20; t++) scv[t] = g_sc[lane + 32 * t];

    {
        float v[20]; float s = 0.f;
#pragma unroll
        for (int t = 0; t < 20; t++) {
            float raw = qrow[lane + 32 * t];
            float val = (fmaxf(raw, 0.f) + 1e-6f) / scv[t];
            v[t] = val; s += val * val;
        }
        float n1 = sqrtf(warp_sum(s));
        s = 0.f;
#pragma unroll
        for (int t = 0; t < 20; t++) { float c3 = v[t]*v[t]*v[t]; v[t] = c3; s += c3*c3; }
        float sc2 = n1 / sqrtf(warp_sum(s));
#pragma unroll
        for (int t = 0; t < 20; t++) {
            float f = v[t] * sc2;
            __nv_bfloat16 h = __float2bfloat16_rn(f);
            __nv_bfloat16 l = __float2bfloat16_rn(f - __bfloat162float(h));
            g_qbh[row * CH + lane + 32 * t] = h;
            g_qbl[row * CH + lane + 32 * t] = l;
        }
    }
    {
        float v[20]; float s = 0.f;
#pragma unroll
        for (int t = 0; t < 20; t++) {
            float raw = krow[lane + 32 * t] + prow[lane + 32 * t];
            float val = (fmaxf(raw, 0.f) + 1e-6f) / scv[t];
            v[t] = val; s += val * val;
        }
        float n1 = sqrtf(warp_sum(s));
        s = 0.f;
#pragma unroll
        for (int t = 0; t < 20; t++) { float c3 = v[t]*v[t]*v[t]; v[t] = c3; s += c3*c3; }
        float sc2 = n1 / sqrtf(warp_sum(s));
#pragma unroll
        for (int t = 0; t < 20; t++) krow[lane + 32 * t] = v[t] * sc2;
    }
}

__global__ void zero_kernel() {
    int idx = blockIdx.x * 256 + threadIdx.x;
    if (idx < BH * HD * HD) g_kv2[idx] = 0.f;
    if (idx < BH * HD)      g_ksum[idx] = 0.f;
}

// ---- packed f32x2 helpers (kv2 only) ----
__device__ __forceinline__ unsigned long long pk2(float lo, float hi) {
    unsigned long long r;
    asm("mov.b64 %0, {%1, %2};" : "=l"(r) : "f"(lo), "f"(hi));
    return r;
}
__device__ __forceinline__ float2 upk(unsigned long long v) {
    float2 f;
    asm("mov.b64 {%0, %1}, %2;" : "=f"(f.x), "=f"(f.y) : "l"(v));
    return f;
}
#define FMA2(d, a, b) asm("fma.rn.f32x2 %0, %1, %2, %0;" : "+l"(d) : "l"(a), "l"(b))

// kv2 (+ fused ksum): per head c×d outer products over j; K tiles reused for
// ksum column sums (threads 0..127, conflict-free LDS).
__global__ __launch_bounds__(256) void kv2_kernel() {
    const int bh = blockIdx.x, jc = blockIdx.y;
    const int b = bh / NH, hoff = (bh % NH) * HD;
    const float* Kp = g_k + (size_t)b * SEQ * CH + hoff;
    const float* Vp = g_v + (size_t)b * SEQ * CH + hoff;
    __shared__ float Ks[16][132];
    __shared__ float Vs[16][132];
    const int tid = threadIdx.x;
    const int tx = tid & 15, ty = tid >> 4;

    unsigned long long acc[8][4];
#pragma unroll
    for (int r = 0; r < 8; r++)
#pragma unroll
        for (int c = 0; c < 4; c++) acc[r][c] = 0ull;

    float kacc = 0.f;   // threads 0..127: ksum partial for column tid

    const int jbase = jc * 512;
    for (int j0 = jbase; j0 < jbase + 512; j0 += 16) {
#pragma unroll
        for (int i = 0; i < 2; i++) {
            int f = tid + i * 256;
            int jj = f >> 5, cq = f & 31;
            float4 kv4 = *reinterpret_cast<const float4*>(&Kp[(size_t)(j0 + jj) * CH + cq * 4]);
            *reinterpret_cast<float4*>(&Ks[jj][cq * 4]) = kv4;
            float4 vv4 = *reinterpret_cast<const float4*>(&Vp[(size_t)(j0 + jj) * CH + cq * 4]);
            *reinterpret_cast<float4*>(&Vs[jj][cq * 4]) = vv4;
        }
        __syncthreads();

        if (tid < 128) {
            float s = 0.f;
#pragma unroll
            for (int jj = 0; jj < 16; jj++) s += Ks[jj][tid];
            kacc += s;
        }

#pragma unroll
        for (int jj = 0; jj < 16; jj++) {
            float4 a0 = *reinterpret_cast<const float4*>(&Ks[jj][ty * 4]);
            float4 a1 = *reinterpret_cast<const float4*>(&Ks[jj][64 + ty * 4]);
            unsigned long long ad[8];
            ad[0] = pk2(a0.x, a0.x); ad[1] = pk2(a0.y, a0.y);
            ad[2] = pk2(a0.z, a0.z); ad[3] = pk2(a0.w, a0.w);
            ad[4] = pk2(a1.x, a1.x); ad[5] = pk2(a1.y, a1.y);
            ad[6] = pk2(a1.z, a1.z); ad[7] = pk2(a1.w, a1.w);
            const unsigned long long* b0 =
                reinterpret_cast<const unsigned long long*>(&Vs[jj][tx * 4]);
            const unsigned long long* b1 =
                reinterpret_cast<const unsigned long long*>(&Vs[jj][64 + tx * 4]);
            unsigned long long bb[4] = { b0[0], b0[1], b1[0], b1[1] };
#pragma unroll
            for (int r = 0; r < 8; r++)
#pragma unroll
                for (int c = 0; c < 4; c++) FMA2(acc[r][c], ad[r], bb[c]);
        }
        __syncthreads();
    }

    if (tid < 128) atomicAdd(&g_ksum[bh * HD + tid], kacc);

    float* dst = g_kv2 + bh * HD * HD;
#pragma unroll
    for (int r = 0; r < 8; r++) {
        int cdx = (r < 4) ? (ty * 4 + r) : (64 + ty * 4 + r - 4);
#pragma unroll
        for (int c = 0; c < 4; c++) {
            int ddx = (c < 2) ? (tx * 4 + 2 * c) : (64 + tx * 4 + 2 * (c - 2));
            float2 v = upk(acc[r][c]);
            atomicAdd(&dst[cdx * HD + ddx], v.x);
            atomicAdd(&dst[cdx * HD + ddx + 1], v.y);
        }
    }
}

// kv2^T + bf16 split: [bh][c][d] fp32 -> [bh][d][c] hi/lo
__global__ __launch_bounds__(256) void kv2t_split() {
    const int bh = blockIdx.x;
    const int e = blockIdx.y * 256 + threadIdx.x;   // 0..16383
    const int d = e >> 7, c = e & 127;
    float v = g_kv2[bh * HD * HD + c * HD + d];
    __nv_bfloat16 h = __float2bfloat16_rn(v);
    __nv_bfloat16 l = __float2bfloat16_rn(v - __bfloat162float(h));
    g_k2h[bh * HD * HD + d * HD + c] = h;
    g_k2l[bh * HD * HD + d * HD + c] = l;
}

// ---------------------------------------------------------------------------
__global__ __launch_bounds__(256) void conv_s(
    const float* __restrict__ w, const float* __restrict__ bias)
{
    extern __shared__ float sv[];
    const int bh = blockIdx.x, yt = blockIdx.y, dc = blockIdx.z;
    const int b = bh / NH, hoff = (bh % NH) * HD;
    const int tid = threadIdx.x;
    const int d = tid & 31;
    const int xg = tid >> 5;
    const float* vbase = g_v + (size_t)b * SEQ * CH + hoff + dc * 32;

    {
        int p = tid;
        int r = p >> 5, rest = p & 31;
        int xi = rest >> 3, d4 = rest & 7;
        int ix = (xi < 2) ? xi : (xi + 64);
        *reinterpret_cast<float4*>(&sv[(r * 68 + ix) * 32 + d4 * 4]) =
            make_float4(0.f, 0.f, 0.f, 0.f);
    }
    for (int p = tid; p < 8 * 512; p += 256) {
        int r = p >> 9, rest = p & 511;
        int x = rest >> 3, d4 = rest & 7;
        int y = yt * 4 - 2 + r;
        float4 val = make_float4(0.f, 0.f, 0.f, 0.f);
        if ((unsigned)y < 64u)
            val = *reinterpret_cast<const float4*>(
                &vbase[(size_t)(y * 64 + x) * CH + d4 * 4]);
        *reinterpret_cast<float4*>(&sv[(r * 68 + x + 2) * 32 + d4 * 4]) = val;
    }
    __syncthreads();

    float wr[25];
#pragma unroll
    for (int k = 0; k < 25; k++) wr[k] = __ldg(&w[(dc * 32 + d) * 25 + k]);
    const float bv = __ldg(&bias[dc * 32 + d]);

#pragma unroll
    for (int y = 0; y < 4; y++) {
#pragma unroll
        for (int xo = 0; xo < 8; xo++) {
            int x = xg * 8 + xo;
            float acc = bv;
#pragma unroll
            for (int ky = 0; ky < 5; ky++)
#pragma unroll
                for (int kx = 0; kx < 5; kx++)
                    acc += wr[ky * 5 + kx] * sv[((y + ky) * 68 + (x + kx)) * 32 + d];
            int oy = yt * 4 + y;
            g_x[(size_t)(b * SEQ + oy * 64 + x) * CH + hoff + dc * 32 + d] = acc;
        }
    }
}

// ---------------------------------------------------------------------------
extern "C" void kernel_launch(void* const* d_in, const int* in_sizes, int n_in,
                              void* d_out, int out_size)
{
    const float* x1    = (const float*)d_in[0];
    const float* x2    = (const float*)d_in[1];
    const float* Wq    = (const float*)d_in[2];
    const float* Wkv   = (const float*)d_in[3];
    const float* Wproj = (const float*)d_in[4];
    const float* bproj = (const float*)d_in[5];
    const float* dwc_w = (const float*)d_in[6];
    const float* dwc_b = (const float*)d_in[7];
    const float* scale = (const float*)d_in[8];
    const float* pos   = (const float*)d_in[9];
    float* out = (float*)d_out;

    __nv_bfloat16 *pah, *pal, *pa2h, *pa2l;
    cudaGetSymbolAddress((void**)&pah, g_abh);
    cudaGetSymbolAddress((void**)&pal, g_abl);
    cudaGetSymbolAddress((void**)&pa2h, g_a2h);
    cudaGetSymbolAddress((void**)&pa2l, g_a2l);

    cudaFuncSetAttribute(gemm_merged,
        cudaFuncAttributeMaxDynamicSharedMemorySize, SMEM_GB);
    cudaFuncSetAttribute(gemm_proj,
        cudaFuncAttributeMaxDynamicSharedMemorySize, SMEM_GB);
    cudaFuncSetAttribute(attn_gemm,
        cudaFuncAttributeMaxDynamicSharedMemorySize, SMEM_GB);
    cudaFuncSetAttribute(conv_s,
        cudaFuncAttributeMaxDynamicSharedMemorySize, 8 * 68 * 32 * 4);

    const int M = BATCH * SEQ;              // 32768
    const int XN4 = M * CH / 4;

    split_w<<<4 * CC / 1024, 256>>>(Wq, Wkv, Wproj);                  // 0
    softplus_kernel<<<3, 256>>>(scale);                               // 1
    split_x<<<XN4 / 256, 256>>>(x1, pah, pal, XN4);                   // 2
    split_x<<<XN4 / 256, 256>>>(x2, pa2h, pa2l, XN4);                 // 3
    gemm_merged<<<dim3(15, M / BMM), 256, SMEM_GB>>>();               // 4: v+k+q

    qknorm_kernel<<<M / 8, 256>>>(pos);
    zero_kernel<<<(BH * HD * HD + 255) / 256, 256>>>();
    kv2_kernel<<<dim3(BH, 8), 256>>>();      // + fused ksum
    kv2t_split<<<dim3(BH, 64), 256>>>();
    conv_s<<<dim3(BH, 16, 4), 256, 8 * 68 * 32 * 4>>>(dwc_w, dwc_b);
    attn_gemm<<<BH * 32, 256, SMEM_GB>>>();  // + fused z

    gemm_proj<<<dim3(5, M / BMM), 256, SMEM_GB>>>(out, bproj);
}

// round 12
// speedup vs baseline: 1.7877x; 1.0287x over previous
#include <cuda_runtime.h>
#include <cuda_bf16.h>
#include <cstdint>
#include <cstddef>

// ---------------------------------------------------------------------------
// FocusedLinearAttention — round 12: kv2 on tensor pipe (bf16x3, ldmatrix.trans)
//   qknorm emits k as bf16 hi/lo; gemm v-epilogue emits v hi/lo;
//   f32x2 kv2 kernel deleted; ksum fold moves into kv2_mma.
// ---------------------------------------------------------------------------

#define BATCH 8
#define SEQ   4096
#define CH    640
#define CC    (CH*CH)
#define NH    5
#define HD    128
#define BH    (BATCH*NH)   // 40

#define BMM 128
#define BNN 128
#define BKE 32
#define NCHB (CH/BKE)           // 20
#define RWB 80
#define BUFB (128*RWB)
#define OFFAH 0
#define OFFAL BUFB
#define OFFBH (2*BUFB)
#define OFFBL (3*BUFB)
#define STB   (4*BUFB)          // 40960 B
#define SMEM_GB (2*STB)         // 81920 B -> 2 CTAs/SM

// kv2_mma tiles: 32 j-rows x 128 cols bf16, pitch 272B (16B rotation)
#define T2RW 272
#define T2BUF (32*T2RW)         // 8704
#define OKH 0
#define OKL T2BUF
#define OVH (2*T2BUF)
#define OVL (3*T2BUF)
#define T2ST (4*T2BUF)          // 34816
#define SMEM_KV2 (2*T2ST)       // 69632

__device__ float g_v[BATCH*SEQ*CH];
__device__ float g_q[BATCH*SEQ*CH];      // raw q
__device__ float g_k[BATCH*SEQ*CH];      // raw k
__device__ float g_x[BATCH*SEQ*CH];      // conv output
__device__ __nv_bfloat16 g_abh[BATCH*SEQ*CH];   // x1 split -> later proj input
__device__ __nv_bfloat16 g_abl[BATCH*SEQ*CH];
__device__ __nv_bfloat16 g_a2h[BATCH*SEQ*CH];   // x2 split
__device__ __nv_bfloat16 g_a2l[BATCH*SEQ*CH];
__device__ __nv_bfloat16 g_qbh[BATCH*SEQ*CH];   // focused q split
__device__ __nv_bfloat16 g_qbl[BATCH*SEQ*CH];
__device__ __nv_bfloat16 g_kbh[BATCH*SEQ*CH];   // focused k split
__device__ __nv_bfloat16 g_kbl[BATCH*SEQ*CH];
__device__ __nv_bfloat16 g_vbh[BATCH*SEQ*CH];   // v split (gemm epilogue)
__device__ __nv_bfloat16 g_vbl[BATCH*SEQ*CH];
__device__ __nv_bfloat16 g_wbh[4*CC];
__device__ __nv_bfloat16 g_wbl[4*CC];
__device__ __nv_bfloat16 g_k2h[BH*HD*HD];       // kv2^T split [bh][d][c]
__device__ __nv_bfloat16 g_k2l[BH*HD*HD];
__device__ float g_kv2[BH*HD*HD];
__device__ float g_ksum[BH*HD];
__device__ float g_sc[CH];

// ---------------------------------------------------------------------------
__device__ __forceinline__ void cp16(uint32_t dst, const void* src) {
    asm volatile("cp.async.cg.shared.global [%0], [%1], 16;" :: "r"(dst), "l"(src));
}

#define LDM4(r0, r1, r2, r3, a) \
    asm volatile("ldmatrix.sync.aligned.m8n8.x4.shared.b16 {%0,%1,%2,%3}, [%4];" \
        : "=r"(r0), "=r"(r1), "=r"(r2), "=r"(r3) : "r"(a))

#define LDM4T(r0, r1, r2, r3, a) \
    asm volatile("ldmatrix.sync.aligned.m8n8.x4.trans.shared.b16 {%0,%1,%2,%3}, [%4];" \
        : "=r"(r0), "=r"(r1), "=r"(r2), "=r"(r3) : "r"(a))

#define MMA_BF16(d, a, b) \
    asm volatile( \
        "mma.sync.aligned.m16n8k16.row.col.f32.bf16.bf16.f32 " \
        "{%0,%1,%2,%3}, {%4,%5,%6,%7}, {%8,%9}, {%0,%1,%2,%3};" \
        : "+f"((d)[0]), "+f"((d)[1]), "+f"((d)[2]), "+f"((d)[3]) \
        : "r"((a)[0]), "r"((a)[1]), "r"((a)[2]), "r"((a)[3]), \
          "r"((b)[0]), "r"((b)[1]))

// ---------------------------------------------------------------------------
__device__ __forceinline__ void split4(float4 v, __nv_bfloat16* hp, __nv_bfloat16* lp) {
    float f[4] = { v.x, v.y, v.z, v.w };
    __nv_bfloat16 h[4], l[4];
#pragma unroll
    for (int j = 0; j < 4; j++) {
        h[j] = __float2bfloat16_rn(f[j]);
        l[j] = __float2bfloat16_rn(f[j] - __bfloat162float(h[j]));
    }
    *reinterpret_cast<__nv_bfloat162*>(hp)     = { h[0], h[1] };
    *reinterpret_cast<__nv_bfloat162*>(hp + 2) = { h[2], h[3] };
    *reinterpret_cast<__nv_bfloat162*>(lp)     = { l[0], l[1] };
    *reinterpret_cast<__nv_bfloat162*>(lp + 2) = { l[2], l[3] };
}

__global__ __launch_bounds__(256) void split_x(
    const float* __restrict__ src, __nv_bfloat16* __restrict__ hi,
    __nv_bfloat16* __restrict__ lo, int n4)
{
    int i = blockIdx.x * 256 + threadIdx.x;
    if (i >= n4) return;
    split4(reinterpret_cast<const float4*>(src)[i], hi + 4 * i, lo + 4 * i);
}

__global__ __launch_bounds__(256) void split_w(
    const float* __restrict__ Wq, const float* __restrict__ Wkv,
    const float* __restrict__ Wproj)
{
    int i = blockIdx.x * 256 + threadIdx.x;
    int fi = i * 4;
    const float* src; int off;
    if (fi < CC)          { src = Wq;    off = 0; }
    else if (fi < 3 * CC) { src = Wkv;   off = CC; }
    else                  { src = Wproj; off = 3 * CC; }
    float4 v = *reinterpret_cast<const float4*>(&src[fi - off]);
    split4(v, g_wbh + fi, g_wbl + fi);
}

// ---------------------------------------------------------------------------
// common bf16x3 GEMM core (K = 640); optional bf16 split side-output
// ---------------------------------------------------------------------------
__device__ __forceinline__ void gemm_core(
    const __nv_bfloat16* __restrict__ Ah, const __nv_bfloat16* __restrict__ Al,
    const __nv_bfloat16* __restrict__ Bh, const __nv_bfloat16* __restrict__ Bl,
    float* __restrict__ Cout, const float* __restrict__ bias,
    __nv_bfloat16* __restrict__ Hsp, __nv_bfloat16* __restrict__ Lsp,
    int m0, int nb0, int n0, uint32_t sb)
{
    const int tid = threadIdx.x;
    const int lane = tid & 31;
    const int wid = tid >> 5;
    const int warp_m = wid >> 1;
    const int warp_n = wid & 1;
    const int gid = lane >> 2;
    const int tig = lane & 3;
    const int lr = (lane & 7) + ((lane >> 3) & 1) * 8;
    const uint32_t lc = (uint32_t)(((lane >> 4) & 1) * 16);

    float acc[2][8][4];
#pragma unroll
    for (int t = 0; t < 2; t++)
#pragma unroll
        for (int j = 0; j < 8; j++)
#pragma unroll
            for (int e = 0; e < 4; e++) acc[t][j][e] = 0.f;

    int r0f = tid >> 2, c0f = tid & 3;
    int r1f = (tid + 256) >> 2, c1f = (tid + 256) & 3;
    const uint32_t so0 = (uint32_t)(r0f * RWB + c0f * 16);
    const uint32_t so1 = (uint32_t)(r1f * RWB + c1f * 16);
    const size_t gA0 = (size_t)(m0 + r0f) * CH + c0f * 8;
    const size_t gA1 = (size_t)(m0 + r1f) * CH + c1f * 8;
    const size_t gB0 = (size_t)(nb0 + r0f) * CH + c0f * 8;
    const size_t gB1 = (size_t)(nb0 + r1f) * CH + c1f * 8;

    auto fill = [&](int stage, int chunk) {
        const int k0 = chunk * BKE;
        const uint32_t stb = sb + (uint32_t)(stage * STB);
        cp16(stb + OFFAH + so0, Ah + gA0 + k0);
        cp16(stb + OFFAL + so0, Al + gA0 + k0);
        cp16(stb + OFFBH + so0, Bh + gB0 + k0);
        cp16(stb + OFFBL + so0, Bl + gB0 + k0);
        cp16(stb + OFFAH + so1, Ah + gA1 + k0);
        cp16(stb + OFFAL + so1, Al + gA1 + k0);
        cp16(stb + OFFBH + so1, Bh + gB1 + k0);
        cp16(stb + OFFBL + so1, Bl + gB1 + k0);
        asm volatile("cp.async.commit_group;" ::: "memory");
    };

    const uint32_t raF = (uint32_t)((warp_m * 32 + lr) * RWB) + lc;
    const uint32_t rbF = (uint32_t)((warp_n * 64 + lr) * RWB) + lc;

    fill(0, 0);
    for (int i = 0; i < NCHB; i++) {
        if (i + 1 < NCHB) {
            fill((i + 1) & 1, i + 1);
            asm volatile("cp.async.wait_group 1;" ::: "memory");
        } else {
            asm volatile("cp.async.wait_group 0;" ::: "memory");
        }
        __syncthreads();

        const uint32_t stb = sb + (uint32_t)((i & 1) * STB);
#pragma unroll
        for (int ks = 0; ks < 2; ks++) {
            const uint32_t kofs = (uint32_t)(ks * 32);
            uint32_t ah[2][4], al[2][4];
#pragma unroll
            for (int t = 0; t < 2; t++) {
                uint32_t ra = stb + OFFAH + raF + (uint32_t)(t * 16 * RWB) + kofs;
                LDM4(ah[t][0], ah[t][1], ah[t][2], ah[t][3], ra);
                LDM4(al[t][0], al[t][1], al[t][2], al[t][3], ra + (OFFAL - OFFAH));
            }
#pragma unroll
            for (int g = 0; g < 4; g++) {
                uint32_t rb = stb + OFFBH + rbF + (uint32_t)(g * 16 * RWB) + kofs;
                uint32_t bh4[4], bl4[4];
                LDM4(bh4[0], bh4[1], bh4[2], bh4[3], rb);
                LDM4(bl4[0], bl4[1], bl4[2], bl4[3], rb + (OFFBL - OFFBH));
                uint32_t b0h[2] = { bh4[0], bh4[2] }, b1h[2] = { bh4[1], bh4[3] };
                uint32_t b0l[2] = { bl4[0], bl4[2] }, b1l[2] = { bl4[1], bl4[3] };
#pragma unroll
                for (int t = 0; t < 2; t++) {
                    MMA_BF16(acc[t][2*g],   ah[t], b0h);
                    MMA_BF16(acc[t][2*g+1], ah[t], b1h);
                }
#pragma unroll
                for (int t = 0; t < 2; t++) {
                    MMA_BF16(acc[t][2*g],   ah[t], b0l);
                    MMA_BF16(acc[t][2*g+1], ah[t], b1l);
                }
#pragma unroll
                for (int t = 0; t < 2; t++) {
                    MMA_BF16(acc[t][2*g],   al[t], b0h);
                    MMA_BF16(acc[t][2*g+1], al[t], b1h);
                }
            }
        }
        __syncthreads();
    }

#pragma unroll
    for (int t = 0; t < 2; t++) {
        int r0 = m0 + warp_m * 32 + t * 16 + gid;
#pragma unroll
        for (int j = 0; j < 8; j++) {
            int cc = n0 + warp_n * 64 + j * 8 + 2 * tig;
            float b0 = bias ? bias[cc] : 0.f;
            float b1 = bias ? bias[cc + 1] : 0.f;
            float f00 = acc[t][j][0] + b0, f01 = acc[t][j][1] + b1;
            float f10 = acc[t][j][2] + b0, f11 = acc[t][j][3] + b1;
            *reinterpret_cast<float2*>(&Cout[(size_t)r0 * CH + cc]) =
                make_float2(f00, f01);
            *reinterpret_cast<float2*>(&Cout[(size_t)(r0 + 8) * CH + cc]) =
                make_float2(f10, f11);
            if (Hsp) {
                __nv_bfloat16 h0 = __float2bfloat16_rn(f00);
                __nv_bfloat16 h1 = __float2bfloat16_rn(f01);
                __nv_bfloat16 h2 = __float2bfloat16_rn(f10);
                __nv_bfloat16 h3 = __float2bfloat16_rn(f11);
                __nv_bfloat16 l0 = __float2bfloat16_rn(f00 - __bfloat162float(h0));
                __nv_bfloat16 l1 = __float2bfloat16_rn(f01 - __bfloat162float(h1));
                __nv_bfloat16 l2 = __float2bfloat16_rn(f10 - __bfloat162float(h2));
                __nv_bfloat16 l3 = __float2bfloat16_rn(f11 - __bfloat162float(h3));
                *reinterpret_cast<__nv_bfloat162*>(&Hsp[(size_t)r0 * CH + cc]) = { h0, h1 };
                *reinterpret_cast<__nv_bfloat162*>(&Hsp[(size_t)(r0 + 8) * CH + cc]) = { h2, h3 };
                *reinterpret_cast<__nv_bfloat162*>(&Lsp[(size_t)r0 * CH + cc]) = { l0, l1 };
                *reinterpret_cast<__nv_bfloat162*>(&Lsp[(size_t)(r0 + 8) * CH + cc]) = { l2, l3 };
            }
        }
    }
}

// merged v + kq GEMM: grid (15, 256)
__global__ __launch_bounds__(256, 2) void gemm_merged() {
    extern __shared__ char smem[];
    const uint32_t sb = (uint32_t)__cvta_generic_to_shared(smem);
    const int m0 = blockIdx.y * BMM;
    const int bx = blockIdx.x;
    if (bx < 5) {
        gemm_core(g_a2h, g_a2l, g_wbh, g_wbl, g_v, nullptr,
                  g_vbh, g_vbl, m0, bx * BNN, bx * BNN, sb);
    } else {
        int nb0 = (bx - 5) * BNN;
        if (nb0 < CH)
            gemm_core(g_abh, g_abl, g_wbh + CC, g_wbl + CC, g_k, nullptr,
                      nullptr, nullptr, m0, nb0, nb0, sb);
        else
            gemm_core(g_abh, g_abl, g_wbh + CC, g_wbl + CC, g_q, nullptr,
                      nullptr, nullptr, m0, nb0, nb0 - CH, sb);
    }
}

// proj GEMM: grid (5, 256)
__global__ __launch_bounds__(256, 2) void gemm_proj(
    float* __restrict__ out, const float* __restrict__ bias)
{
    extern __shared__ char smem[];
    const uint32_t sb = (uint32_t)__cvta_generic_to_shared(smem);
    gemm_core(g_abh, g_abl, g_wbh + 3 * CC, g_wbl + 3 * CC, out, bias,
              nullptr, nullptr,
              blockIdx.y * BMM, blockIdx.x * BNN, blockIdx.x * BNN, sb);
}

// ---------------------------------------------------------------------------
// kv2 on tensor pipe: per (head, j-chunk of 512), accumulate
//   kv2[c][d] += sum_j K[j][c]·V[j][d]  via bf16x3 mma with ldmatrix.trans.
// Also folds ksum (column sums of K tiles). Atomic fp32 epilogue.
// ---------------------------------------------------------------------------
__global__ __launch_bounds__(256, 2) void kv2_mma() {
    extern __shared__ char smem[];
    const uint32_t sb = (uint32_t)__cvta_generic_to_shared(smem);
    const int bh = blockIdx.x, jc = blockIdx.y;   // jc 0..7
    const int b = bh / NH, hoff = (bh % NH) * HD;
    const __nv_bfloat16* Kh = g_kbh + (size_t)b * SEQ * CH + hoff;
    const __nv_bfloat16* Kl = g_kbl + (size_t)b * SEQ * CH + hoff;
    const __nv_bfloat16* Vh = g_vbh + (size_t)b * SEQ * CH + hoff;
    const __nv_bfloat16* Vl = g_vbl + (size_t)b * SEQ * CH + hoff;

    const int tid = threadIdx.x;
    const int lane = tid & 31;
    const int wid = tid >> 5;
    const int warp_m = wid >> 1;        // c-tile 0..3 (32 each)
    const int warp_n = wid & 1;         // d-tile 0..1 (64 each)
    const int gid = lane >> 2;
    const int tig = lane & 3;
    const int grp = lane >> 3;          // ldmatrix group 0..3
    const int l8 = lane & 7;

    float acc[2][8][4];
#pragma unroll
    for (int t = 0; t < 2; t++)
#pragma unroll
        for (int j = 0; j < 8; j++)
#pragma unroll
            for (int e = 0; e < 4; e++) acc[t][j][e] = 0.f;

    float kacc = 0.f;

    // fill: 32 j-rows x 256B per buffer = 512 x 16B; 2 per thread per buffer
    auto fill = [&](int stage, int it) {
        const int j0 = jc * 512 + it * 32;
        const uint32_t stb = sb + (uint32_t)(stage * T2ST);
#pragma unroll
        for (int t = 0; t < 2; t++) {
            int u = tid + t * 256;
            int row = u >> 4, col = u & 15;
            uint32_t off = (uint32_t)(row * T2RW + col * 16);
            size_t g = (size_t)(j0 + row) * CH + col * 8;
            cp16(stb + OKH + off, Kh + g);
            cp16(stb + OKL + off, Kl + g);
            cp16(stb + OVH + off, Vh + g);
            cp16(stb + OVL + off, Vl + g);
        }
        asm volatile("cp.async.commit_group;" ::: "memory");
    };

    fill(0, 0);
    for (int it = 0; it < 16; it++) {
        if (it + 1 < 16) {
            fill((it + 1) & 1, it + 1);
            asm volatile("cp.async.wait_group 1;" ::: "memory");
        } else {
            asm volatile("cp.async.wait_group 0;" ::: "memory");
        }
        __syncthreads();

        const uint32_t stb = sb + (uint32_t)((it & 1) * T2ST);

        // fused ksum: thread t<128 sums column t (hi+lo) over 32 j-rows
        if (tid < 128) {
            const __nv_bfloat16* KhS = reinterpret_cast<const __nv_bfloat16*>(
                smem + (it & 1) * T2ST + OKH);
            const __nv_bfloat16* KlS = reinterpret_cast<const __nv_bfloat16*>(
                smem + (it & 1) * T2ST + OKL);
#pragma unroll
            for (int j = 0; j < 32; j++)
                kacc += __bfloat162float(KhS[j * (T2RW / 2) + tid]) +
                        __bfloat162float(KlS[j * (T2RW / 2) + tid]);
        }

#pragma unroll
        for (int ks = 0; ks < 2; ks++) {
            // A frags (c x j) via trans: groups {j0-7/m0, j0-7/m8, j8-15/m0, j8-15/m8}
            const uint32_t aj = (uint32_t)(ks * 16 + ((grp >> 1) & 1) * 8 + l8);
            uint32_t ah[2][4], al[2][4];
#pragma unroll
            for (int t = 0; t < 2; t++) {
                uint32_t ac = (uint32_t)(warp_m * 32 + t * 16 + (grp & 1) * 8);
                uint32_t ra = stb + OKH + aj * T2RW + ac * 2;
                LDM4T(ah[t][0], ah[t][1], ah[t][2], ah[t][3], ra);
                LDM4T(al[t][0], al[t][1], al[t][2], al[t][3], ra + (OKL - OKH));
            }
            // B frags (d x j) via trans: groups {j0-7/d0, j8-15/d0, j0-7/d8, j8-15/d8}
            const uint32_t bj = (uint32_t)(ks * 16 + (grp & 1) * 8 + l8);
#pragma unroll
            for (int g = 0; g < 4; g++) {
                uint32_t bd = (uint32_t)(warp_n * 64 + g * 16 + ((grp >> 1) & 1) * 8);
                uint32_t rb = stb + OVH + bj * T2RW + bd * 2;
                uint32_t bh4[4], bl4[4];
                LDM4T(bh4[0], bh4[1], bh4[2], bh4[3], rb);
                LDM4T(bl4[0], bl4[1], bl4[2], bl4[3], rb + (OVL - OVH));
                uint32_t b0h[2] = { bh4[0], bh4[1] }, b1h[2] = { bh4[2], bh4[3] };
                uint32_t b0l[2] = { bl4[0], bl4[1] }, b1l[2] = { bl4[2], bl4[3] };
#pragma unroll
                for (int t = 0; t < 2; t++) {
                    MMA_BF16(acc[t][2*g],   ah[t], b0h);
                    MMA_BF16(acc[t][2*g+1], ah[t], b1h);
                }
#pragma unroll
                for (int t = 0; t < 2; t++) {
                    MMA_BF16(acc[t][2*g],   ah[t], b0l);
                    MMA_BF16(acc[t][2*g+1], ah[t], b1l);
                }
#pragma unroll
                for (int t = 0; t < 2; t++) {
                    MMA_BF16(acc[t][2*g],   al[t], b0h);
                    MMA_BF16(acc[t][2*g+1], al[t], b1h);
                }
            }
        }
        __syncthreads();
    }

    if (tid < 128) atomicAdd(&g_ksum[bh * HD + tid], kacc);

    float* dst = g_kv2 + bh * HD * HD;
#pragma unroll
    for (int t = 0; t < 2; t++) {
        int c0 = warp_m * 32 + t * 16 + gid;
#pragma unroll
        for (int j = 0; j < 8; j++) {
            int d = warp_n * 64 + j * 8 + 2 * tig;
            atomicAdd(&dst[c0 * HD + d],           acc[t][j][0]);
            atomicAdd(&dst[c0 * HD + d + 1],       acc[t][j][1]);
            atomicAdd(&dst[(c0 + 8) * HD + d],     acc[t][j][2]);
            atomicAdd(&dst[(c0 + 8) * HD + d + 1], acc[t][j][3]);
        }
    }
}

// ---------------------------------------------------------------------------
// attn GEMM with fused z (unchanged from round 11)
// ---------------------------------------------------------------------------
__global__ __launch_bounds__(256, 2) void attn_gemm() {
    extern __shared__ char smem[];
    const uint32_t sb = (uint32_t)__cvta_generic_to_shared(smem);
    const int bx = blockIdx.x;
    const int bh = bx >> 5;
    const int m0 = (bx & 31) * BMM;
    const int b = bh / NH, hoff = (bh % NH) * HD;
    const __nv_bfloat16* Ah = g_qbh + (size_t)b * SEQ * CH + hoff;
    const __nv_bfloat16* Al = g_qbl + (size_t)b * SEQ * CH + hoff;
    const __nv_bfloat16* Bh = g_k2h + (size_t)bh * HD * HD;
    const __nv_bfloat16* Bl = g_k2l + (size_t)bh * HD * HD;

    const int tid = threadIdx.x;
    const int lane = tid & 31;
    const int wid = tid >> 5;
    const int warp_m = wid >> 1;
    const int warp_n = wid & 1;
    const int gid = lane >> 2;
    const int tig = lane & 3;
    const int lr = (lane & 7) + ((lane >> 3) & 1) * 8;
    const uint32_t lc = (uint32_t)(((lane >> 4) & 1) * 16);

    float acc[2][8][4];
#pragma unroll
    for (int t = 0; t < 2; t++)
#pragma unroll
        for (int j = 0; j < 8; j++)
#pragma unroll
            for (int e = 0; e < 4; e++) acc[t][j][e] = 0.f;

    int r0f = tid >> 2, c0f = tid & 3;
    int r1f = (tid + 256) >> 2, c1f = (tid + 256) & 3;
    const uint32_t so0 = (uint32_t)(r0f * RWB + c0f * 16);
    const uint32_t so1 = (uint32_t)(r1f * RWB + c1f * 16);
    const size_t gA0 = (size_t)(m0 + r0f) * CH + c0f * 8;
    const size_t gA1 = (size_t)(m0 + r1f) * CH + c1f * 8;
    const size_t gB0 = (size_t)r0f * HD + c0f * 8;
    const size_t gB1 = (size_t)r1f * HD + c1f * 8;

    auto fill = [&](int stage, int chunk) {
        const int k0 = chunk * BKE;
        const uint32_t stb = sb + (uint32_t)(stage * STB);
        cp16(stb + OFFAH + so0, Ah + gA0 + k0);
        cp16(stb + OFFAL + so0, Al + gA0 + k0);
        cp16(stb + OFFBH + so0, Bh + gB0 + k0);
        cp16(stb + OFFBL + so0, Bl + gB0 + k0);
        cp16(stb + OFFAH + so1, Ah + gA1 + k0);
        cp16(stb + OFFAL + so1, Al + gA1 + k0);
        cp16(stb + OFFBH + so1, Bh + gB1 + k0);
        cp16(stb + OFFBL + so1, Bl + gB1 + k0);
        asm volatile("cp.async.commit_group;" ::: "memory");
    };

    const uint32_t raF = (uint32_t)((warp_m * 32 + lr) * RWB) + lc;
    const uint32_t rbF = (uint32_t)((warp_n * 64 + lr) * RWB) + lc;

    float zacc = 0.f;

    fill(0, 0);
#pragma unroll
    for (int i = 0; i < 4; i++) {
        if (i + 1 < 4) {
            fill((i + 1) & 1, i + 1);
            asm volatile("cp.async.wait_group 1;" ::: "memory");
        } else {
            asm volatile("cp.async.wait_group 0;" ::: "memory");
        }
        __syncthreads();

        const uint32_t stb = sb + (uint32_t)((i & 1) * STB);

        if (tid < 128) {
            const uint32_t qh = stb + OFFAH + (uint32_t)(tid * RWB);
            const float* ksp = g_ksum + bh * HD + i * BKE;
#pragma unroll
            for (int cc = 0; cc < 32; cc += 2) {
                uint32_t hv, lv;
                asm("ld.shared.b32 %0, [%1];" : "=r"(hv) : "r"(qh + cc * 2));
                asm("ld.shared.b32 %0, [%1];" : "=r"(lv)
                    : "r"(qh + (OFFAL - OFFAH) + cc * 2));
                __nv_bfloat162 h2 = *reinterpret_cast<__nv_bfloat162*>(&hv);
                __nv_bfloat162 l2 = *reinterpret_cast<__nv_bfloat162*>(&lv);
                float q0 = __bfloat162float(h2.x) + __bfloat162float(l2.x);
                float q1 = __bfloat162float(h2.y) + __bfloat162float(l2.y);
                zacc += q0 * __ldg(ksp + cc) + q1 * __ldg(ksp + cc + 1);
            }
        }

#pragma unroll
        for (int ks = 0; ks < 2; ks++) {
            const uint32_t kofs = (uint32_t)(ks * 32);
            uint32_t ah[2][4], al[2][4];
#pragma unroll
            for (int t = 0; t < 2; t++) {
                uint32_t ra = stb + OFFAH + raF + (uint32_t)(t * 16 * RWB) + kofs;
                LDM4(ah[t][0], ah[t][1], ah[t][2], ah[t][3], ra);
                LDM4(al[t][0], al[t][1], al[t][2], al[t][3], ra + (OFFAL - OFFAH));
            }
#pragma unroll
            for (int g = 0; g < 4; g++) {
                uint32_t rb = stb + OFFBH + rbF + (uint32_t)(g * 16 * RWB) + kofs;
                uint32_t bh4[4], bl4[4];
                LDM4(bh4[0], bh4[1], bh4[2], bh4[3], rb);
                LDM4(bl4[0], bl4[1], bl4[2], bl4[3], rb + (OFFBL - OFFBH));
                uint32_t b0h[2] = { bh4[0], bh4[2] }, b1h[2] = { bh4[1], bh4[3] };
                uint32_t b0l[2] = { bl4[0], bl4[2] }, b1l[2] = { bl4[1], bl4[3] };
#pragma unroll
                for (int t = 0; t < 2; t++) {
                    MMA_BF16(acc[t][2*g],   ah[t], b0h);
                    MMA_BF16(acc[t][2*g+1], ah[t], b1h);
                }
#pragma unroll
                for (int t = 0; t < 2; t++) {
                    MMA_BF16(acc[t][2*g],   ah[t], b0l);
                    MMA_BF16(acc[t][2*g+1], ah[t], b1l);
                }
#pragma unroll
                for (int t = 0; t < 2; t++) {
                    MMA_BF16(acc[t][2*g],   al[t], b0h);
                    MMA_BF16(acc[t][2*g+1], al[t], b1h);
                }
            }
        }
        __syncthreads();
    }

    float* zs = reinterpret_cast<float*>(smem);
    if (tid < 128) zs[tid] = 1.f / (zacc + 1e-6f);
    __syncthreads();

#pragma unroll
    for (int t = 0; t < 2; t++) {
        int lr0 = warp_m * 32 + t * 16 + gid;
#pragma unroll
        for (int j = 0; j < 8; j++) {
            int d = warp_n * 64 + j * 8 + 2 * tig;
#pragma unroll
            for (int half = 0; half < 2; half++) {
                int lrow = lr0 + half * 8;
                int i = m0 + lrow;
                float zv = zs[lrow];
                size_t base = (size_t)(b * SEQ + i) * CH + hoff + d;
                float f0 = g_x[base]     + acc[t][j][half * 2]     * zv;
                float f1 = g_x[base + 1] + acc[t][j][half * 2 + 1] * zv;
                __nv_bfloat16 h0 = __float2bfloat16_rn(f0);
                __nv_bfloat16 h1 = __float2bfloat16_rn(f1);
                __nv_bfloat16 l0 = __float2bfloat16_rn(f0 - __bfloat162float(h0));
                __nv_bfloat16 l1 = __float2bfloat16_rn(f1 - __bfloat162float(h1));
                *reinterpret_cast<__nv_bfloat162*>(&g_abh[base]) = { h0, h1 };
                *reinterpret_cast<__nv_bfloat162*>(&g_abl[base]) = { l0, l1 };
            }
        }
    }
}

// ---------------------------------------------------------------------------
__global__ void softplus_kernel(const float* __restrict__ scale) {
    int c = blockIdx.x * 256 + threadIdx.x;
    if (c < CH) g_sc[c] = log1pf(expf(scale[c]));
}

// ---------------------------------------------------------------------------
__device__ __forceinline__ float warp_sum(float s) {
#pragma unroll
    for (int o = 16; o > 0; o >>= 1) s += __shfl_xor_sync(0xffffffffu, s, o);
    return s;
}

// qknorm: warp per row; q and k both -> bf16 hi/lo.
__global__ __launch_bounds__(256) void qknorm_kernel(const float* __restrict__ pos) {
    const int w = blockIdx.x * 8 + (threadIdx.x >> 5);
    const int lane = threadIdx.x & 31;
    const size_t row = (size_t)w;
    const int n = w & (SEQ - 1);
    const float* qrow = g_q + row * CH;
    const float* krow = g_k + row * CH;
    const float* prow = pos + (size_t)n * CH;

    float scv[20];
#pragma unroll
    for (int t = 0; t < 20; t++) scv[t] = g_sc[lane + 32 * t];

    {
        float v[20]; float s = 0.f;
#pragma unroll
        for (int t = 0; t < 20; t++) {
            float raw = qrow[lane + 32 * t];
            float val = (fmaxf(raw, 0.f) + 1e-6f) / scv[t];
            v[t] = val; s += val * val;
        }
        float n1 = sqrtf(warp_sum(s));
        s = 0.f;
#pragma unroll
        for (int t = 0; t < 20; t++) { float c3 = v[t]*v[t]*v[t]; v[t] = c3; s += c3*c3; }
        float sc2 = n1 / sqrtf(warp_sum(s));
#pragma unroll
        for (int t = 0; t < 20; t++) {
            float f = v[t] * sc2;
            __nv_bfloat16 h = __float2bfloat16_rn(f);
            __nv_bfloat16 l = __float2bfloat16_rn(f - __bfloat162float(h));
            g_qbh[row * CH + lane + 32 * t] = h;
            g_qbl[row * CH + lane + 32 * t] = l;
        }
    }
    {
        float v[20]; float s = 0.f;
#pragma unroll
        for (int t = 0; t < 20; t++) {
            float raw = krow[lane + 32 * t] + prow[lane + 32 * t];
            float val = (fmaxf(raw, 0.f) + 1e-6f) / scv[t];
            v[t] = val; s += val * val;
        }
        float n1 = sqrtf(warp_sum(s));
        s = 0.f;
#pragma unroll
        for (int t = 0; t < 20; t++) { float c3 = v[t]*v[t]*v[t]; v[t] = c3; s += c3*c3; }
        float sc2 = n1 / sqrtf(warp_sum(s));
#pragma unroll
        for (int t = 0; t < 20; t++) {
            float f = v[t] * sc2;
            __nv_bfloat16 h = __float2bfloat16_rn(f);
            __nv_bfloat16 l = __float2bfloat16_rn(f - __bfloat162float(h));
            g_kbh[row * CH + lane + 32 * t] = h;
            g_kbl[row * CH + lane + 32 * t] = l;
        }
    }
}

__global__ void zero_kernel() {
    int idx = blockIdx.x * 256 + threadIdx.x;
    if (idx < BH * HD * HD) g_kv2[idx] = 0.f;
    if (idx < BH * HD)      g_ksum[idx] = 0.f;
}

// kv2^T + bf16 split: [bh][c][d] fp32 -> [bh][d][c] hi/lo
__global__ __launch_bounds__(256) void kv2t_split() {
    const int bh = blockIdx.x;
    const int e = blockIdx.y * 256 + threadIdx.x;
    const int d = e >> 7, c = e & 127;
    float v = g_kv2[bh * HD * HD + c * HD + d];
    __nv_bfloat16 h = __float2bfloat16_rn(v);
    __nv_bfloat16 l = __float2bfloat16_rn(v - __bfloat162float(h));
    g_k2h[bh * HD * HD + d * HD + c] = h;
    g_k2l[bh * HD * HD + d * HD + c] = l;
}

// ---------------------------------------------------------------------------
__global__ __launch_bounds__(256) void conv_s(
    const float* __restrict__ w, const float* __restrict__ bias)
{
    extern __shared__ float sv[];
    const int bh = blockIdx.x, yt = blockIdx.y, dc = blockIdx.z;
    const int b = bh / NH, hoff = (bh % NH) * HD;
    const int tid = threadIdx.x;
    const int d = tid & 31;
    const int xg = tid >> 5;
    const float* vbase = g_v + (size_t)b * SEQ * CH + hoff + dc * 32;

    {
        int p = tid;
        int r = p >> 5, rest = p & 31;
        int xi = rest >> 3, d4 = rest & 7;
        int ix = (xi < 2) ? xi : (xi + 64);
        *reinterpret_cast<float4*>(&sv[(r * 68 + ix) * 32 + d4 * 4]) =
            make_float4(0.f, 0.f, 0.f, 0.f);
    }
    for (int p = tid; p < 8 * 512; p += 256) {
        int r = p >> 9, rest = p & 511;
        int x = rest >> 3, d4 = rest & 7;
        int y = yt * 4 - 2 + r;
        float4 val = make_float4(0.f, 0.f, 0.f, 0.f);
        if ((unsigned)y < 64u)
            val = *reinterpret_cast<const float4*>(
                &vbase[(size_t)(y * 64 + x) * CH + d4 * 4]);
        *reinterpret_cast<float4*>(&sv[(r * 68 + x + 2) * 32 + d4 * 4]) = val;
    }
    __syncthreads();

    float wr[25];
#pragma unroll
    for (int k = 0; k < 25; k++) wr[k] = __ldg(&w[(dc * 32 + d) * 25 + k]);
    const float bv = __ldg(&bias[dc * 32 + d]);

#pragma unroll
    for (int y = 0; y < 4; y++) {
#pragma unroll
        for (int xo = 0; xo < 8; xo++) {
            int x = xg * 8 + xo;
            float acc = bv;
#pragma unroll
            for (int ky = 0; ky < 5; ky++)
#pragma unroll
                for (int kx = 0; kx < 5; kx++)
                    acc += wr[ky * 5 + kx] * sv[((y + ky) * 68 + (x + kx)) * 32 + d];
            int oy = yt * 4 + y;
            g_x[(size_t)(b * SEQ + oy * 64 + x) * CH + hoff + dc * 32 + d] = acc;
        }
    }
}

// ---------------------------------------------------------------------------
extern "C" void kernel_launch(void* const* d_in, const int* in_sizes, int n_in,
                              void* d_out, int out_size)
{
    const float* x1    = (const float*)d_in[0];
    const float* x2    = (const float*)d_in[1];
    const float* Wq    = (const float*)d_in[2];
    const float* Wkv   = (const float*)d_in[3];
    const float* Wproj = (const float*)d_in[4];
    const float* bproj = (const float*)d_in[5];
    const float* dwc_w = (const float*)d_in[6];
    const float* dwc_b = (const float*)d_in[7];
    const float* scale = (const float*)d_in[8];
    const float* pos   = (const float*)d_in[9];
    float* out = (float*)d_out;

    __nv_bfloat16 *pah, *pal, *pa2h, *pa2l;
    cudaGetSymbolAddress((void**)&pah, g_abh);
    cudaGetSymbolAddress((void**)&pal, g_abl);
    cudaGetSymbolAddress((void**)&pa2h, g_a2h);
    cudaGetSymbolAddress((void**)&pa2l, g_a2l);

    cudaFuncSetAttribute(gemm_merged,
        cudaFuncAttributeMaxDynamicSharedMemorySize, SMEM_GB);
    cudaFuncSetAttribute(gemm_proj,
        cudaFuncAttributeMaxDynamicSharedMemorySize, SMEM_GB);
    cudaFuncSetAttribute(attn_gemm,
        cudaFuncAttributeMaxDynamicSharedMemorySize, SMEM_GB);
    cudaFuncSetAttribute(kv2_mma,
        cudaFuncAttributeMaxDynamicSharedMemorySize, SMEM_KV2);
    cudaFuncSetAttribute(conv_s,
        cudaFuncAttributeMaxDynamicSharedMemorySize, 8 * 68 * 32 * 4);

    const int M = BATCH * SEQ;              // 32768
    const int XN4 = M * CH / 4;

    split_w<<<4 * CC / 1024, 256>>>(Wq, Wkv, Wproj);                  // 0
    softplus_kernel<<<3, 256>>>(scale);                               // 1
    split_x<<<XN4 / 256, 256>>>(x1, pah, pal, XN4);                   // 2
    split_x<<<XN4 / 256, 256>>>(x2, pa2h, pa2l, XN4);                 // 3
    gemm_merged<<<dim3(15, M / BMM), 256, SMEM_GB>>>();               // 4: v+k+q (+v split)

    qknorm_kernel<<<M / 8, 256>>>(pos);
    zero_kernel<<<(BH * HD * HD + 255) / 256, 256>>>();
    kv2_mma<<<dim3(BH, 8), 256, SMEM_KV2>>>();   // tensor-pipe kv2 + ksum
    kv2t_split<<<dim3(BH, 64), 256>>>();
    conv_s<<<dim3(BH, 16, 4), 256, 8 * 68 * 32 * 4>>>(dwc_w, dwc_b);
    attn_gemm<<<BH * 32, 256, SMEM_GB>>>();      // + fused z

    gemm_proj<<<dim3(5, M / BMM), 256, SMEM_GB>>>(out, bproj);
}

// round 13
// speedup vs baseline: 1.8402x; 1.0294x over previous
#include <cuda_runtime.h>
#include <cuda_bf16.h>
#include <cstdint>
#include <cstddef>

// ---------------------------------------------------------------------------
// FocusedLinearAttention — round 13:
//   fp32 g_v removed (conv reads v hi/lo splits); bl4 ldmatrix staggered
//   after hi*hi MMAs in both GEMM cores.
// ---------------------------------------------------------------------------

#define BATCH 8
#define SEQ   4096
#define CH    640
#define CC    (CH*CH)
#define NH    5
#define HD    128
#define BH    (BATCH*NH)   // 40

#define BMM 128
#define BNN 128
#define BKE 32
#define NCHB (CH/BKE)           // 20
#define RWB 80
#define BUFB (128*RWB)
#define OFFAH 0
#define OFFAL BUFB
#define OFFBH (2*BUFB)
#define OFFBL (3*BUFB)
#define STB   (4*BUFB)          // 40960 B
#define SMEM_GB (2*STB)         // 81920 B -> 2 CTAs/SM

// kv2_mma tiles: 32 j-rows x 128 cols bf16, pitch 272B
#define T2RW 272
#define T2BUF (32*T2RW)
#define OKH 0
#define OKL T2BUF
#define OVH (2*T2BUF)
#define OVL (3*T2BUF)
#define T2ST (4*T2BUF)          // 34816
#define SMEM_KV2 (2*T2ST)       // 69632

__device__ float g_q[BATCH*SEQ*CH];      // raw q
__device__ float g_k[BATCH*SEQ*CH];      // raw k
__device__ float g_x[BATCH*SEQ*CH];      // conv output
__device__ __nv_bfloat16 g_abh[BATCH*SEQ*CH];   // x1 split -> later proj input
__device__ __nv_bfloat16 g_abl[BATCH*SEQ*CH];
__device__ __nv_bfloat16 g_a2h[BATCH*SEQ*CH];   // x2 split
__device__ __nv_bfloat16 g_a2l[BATCH*SEQ*CH];
__device__ __nv_bfloat16 g_qbh[BATCH*SEQ*CH];   // focused q split
__device__ __nv_bfloat16 g_qbl[BATCH*SEQ*CH];
__device__ __nv_bfloat16 g_kbh[BATCH*SEQ*CH];   // focused k split
__device__ __nv_bfloat16 g_kbl[BATCH*SEQ*CH];
__device__ __nv_bfloat16 g_vbh[BATCH*SEQ*CH];   // v split (gemm epilogue)
__device__ __nv_bfloat16 g_vbl[BATCH*SEQ*CH];
__device__ __nv_bfloat16 g_wbh[4*CC];
__device__ __nv_bfloat16 g_wbl[4*CC];
__device__ __nv_bfloat16 g_k2h[BH*HD*HD];       // kv2^T split [bh][d][c]
__device__ __nv_bfloat16 g_k2l[BH*HD*HD];
__device__ float g_kv2[BH*HD*HD];
__device__ float g_ksum[BH*HD];
__device__ float g_sc[CH];

// ---------------------------------------------------------------------------
__device__ __forceinline__ void cp16(uint32_t dst, const void* src) {
    asm volatile("cp.async.cg.shared.global [%0], [%1], 16;" :: "r"(dst), "l"(src));
}

#define LDM4(r0, r1, r2, r3, a) \
    asm volatile("ldmatrix.sync.aligned.m8n8.x4.shared.b16 {%0,%1,%2,%3}, [%4];" \
        : "=r"(r0), "=r"(r1), "=r"(r2), "=r"(r3) : "r"(a))

#define LDM4T(r0, r1, r2, r3, a) \
    asm volatile("ldmatrix.sync.aligned.m8n8.x4.trans.shared.b16 {%0,%1,%2,%3}, [%4];" \
        : "=r"(r0), "=r"(r1), "=r"(r2), "=r"(r3) : "r"(a))

#define MMA_BF16(d, a, b) \
    asm volatile( \
        "mma.sync.aligned.m16n8k16.row.col.f32.bf16.bf16.f32 " \
        "{%0,%1,%2,%3}, {%4,%5,%6,%7}, {%8,%9}, {%0,%1,%2,%3};" \
        : "+f"((d)[0]), "+f"((d)[1]), "+f"((d)[2]), "+f"((d)[3]) \
        : "r"((a)[0]), "r"((a)[1]), "r"((a)[2]), "r"((a)[3]), \
          "r"((b)[0]), "r"((b)[1]))

// ---------------------------------------------------------------------------
__device__ __forceinline__ void split4(float4 v, __nv_bfloat16* hp, __nv_bfloat16* lp) {
    float f[4] = { v.x, v.y, v.z, v.w };
    __nv_bfloat16 h[4], l[4];
#pragma unroll
    for (int j = 0; j < 4; j++) {
        h[j] = __float2bfloat16_rn(f[j]);
        l[j] = __float2bfloat16_rn(f[j] - __bfloat162float(h[j]));
    }
    *reinterpret_cast<__nv_bfloat162*>(hp)     = { h[0], h[1] };
    *reinterpret_cast<__nv_bfloat162*>(hp + 2) = { h[2], h[3] };
    *reinterpret_cast<__nv_bfloat162*>(lp)     = { l[0], l[1] };
    *reinterpret_cast<__nv_bfloat162*>(lp + 2) = { l[2], l[3] };
}

__global__ __launch_bounds__(256) void split_x(
    const float* __restrict__ src, __nv_bfloat16* __restrict__ hi,
    __nv_bfloat16* __restrict__ lo, int n4)
{
    int i = blockIdx.x * 256 + threadIdx.x;
    if (i >= n4) return;
    split4(reinterpret_cast<const float4*>(src)[i], hi + 4 * i, lo + 4 * i);
}

__global__ __launch_bounds__(256) void split_w(
    const float* __restrict__ Wq, const float* __restrict__ Wkv,
    const float* __restrict__ Wproj)
{
    int i = blockIdx.x * 256 + threadIdx.x;
    int fi = i * 4;
    const float* src; int off;
    if (fi < CC)          { src = Wq;    off = 0; }
    else if (fi < 3 * CC) { src = Wkv;   off = CC; }
    else                  { src = Wproj; off = 3 * CC; }
    float4 v = *reinterpret_cast<const float4*>(&src[fi - off]);
    split4(v, g_wbh + fi, g_wbl + fi);
}

// ---------------------------------------------------------------------------
// common bf16x3 GEMM core (K = 640); Cout optional; bf16 split side-output opt.
// ---------------------------------------------------------------------------
__device__ __forceinline__ void gemm_core(
    const __nv_bfloat16* __restrict__ Ah, const __nv_bfloat16* __restrict__ Al,
    const __nv_bfloat16* __restrict__ Bh, const __nv_bfloat16* __restrict__ Bl,
    float* __restrict__ Cout, const float* __restrict__ bias,
    __nv_bfloat16* __restrict__ Hsp, __nv_bfloat16* __restrict__ Lsp,
    int m0, int nb0, int n0, uint32_t sb)
{
    const int tid = threadIdx.x;
    const int lane = tid & 31;
    const int wid = tid >> 5;
    const int warp_m = wid >> 1;
    const int warp_n = wid & 1;
    const int gid = lane >> 2;
    const int tig = lane & 3;
    const int lr = (lane & 7) + ((lane >> 3) & 1) * 8;
    const uint32_t lc = (uint32_t)(((lane >> 4) & 1) * 16);

    float acc[2][8][4];
#pragma unroll
    for (int t = 0; t < 2; t++)
#pragma unroll
        for (int j = 0; j < 8; j++)
#pragma unroll
            for (int e = 0; e < 4; e++) acc[t][j][e] = 0.f;

    int r0f = tid >> 2, c0f = tid & 3;
    int r1f = (tid + 256) >> 2, c1f = (tid + 256) & 3;
    const uint32_t so0 = (uint32_t)(r0f * RWB + c0f * 16);
    const uint32_t so1 = (uint32_t)(r1f * RWB + c1f * 16);
    const size_t gA0 = (size_t)(m0 + r0f) * CH + c0f * 8;
    const size_t gA1 = (size_t)(m0 + r1f) * CH + c1f * 8;
    const size_t gB0 = (size_t)(nb0 + r0f) * CH + c0f * 8;
    const size_t gB1 = (size_t)(nb0 + r1f) * CH + c1f * 8;

    auto fill = [&](int stage, int chunk) {
        const int k0 = chunk * BKE;
        const uint32_t stb = sb + (uint32_t)(stage * STB);
        cp16(stb + OFFAH + so0, Ah + gA0 + k0);
        cp16(stb + OFFAL + so0, Al + gA0 + k0);
        cp16(stb + OFFBH + so0, Bh + gB0 + k0);
        cp16(stb + OFFBL + so0, Bl + gB0 + k0);
        cp16(stb + OFFAH + so1, Ah + gA1 + k0);
        cp16(stb + OFFAL + so1, Al + gA1 + k0);
        cp16(stb + OFFBH + so1, Bh + gB1 + k0);
        cp16(stb + OFFBL + so1, Bl + gB1 + k0);
        asm volatile("cp.async.commit_group;" ::: "memory");
    };

    const uint32_t raF = (uint32_t)((warp_m * 32 + lr) * RWB) + lc;
    const uint32_t rbF = (uint32_t)((warp_n * 64 + lr) * RWB) + lc;

    fill(0, 0);
    for (int i = 0; i < NCHB; i++) {
        if (i + 1 < NCHB) {
            fill((i + 1) & 1, i + 1);
            asm volatile("cp.async.wait_group 1;" ::: "memory");
        } else {
            asm volatile("cp.async.wait_group 0;" ::: "memory");
        }
        __syncthreads();

        const uint32_t stb = sb + (uint32_t)((i & 1) * STB);
#pragma unroll
        for (int ks = 0; ks < 2; ks++) {
            const uint32_t kofs = (uint32_t)(ks * 32);
            uint32_t ah[2][4], al[2][4];
#pragma unroll
            for (int t = 0; t < 2; t++) {
                uint32_t ra = stb + OFFAH + raF + (uint32_t)(t * 16 * RWB) + kofs;
                LDM4(ah[t][0], ah[t][1], ah[t][2], ah[t][3], ra);
                LDM4(al[t][0], al[t][1], al[t][2], al[t][3], ra + (OFFAL - OFFAH));
            }
#pragma unroll
            for (int g = 0; g < 4; g++) {
                uint32_t rb = stb + OFFBH + rbF + (uint32_t)(g * 16 * RWB) + kofs;
                uint32_t bh4[4], bl4[4];
                LDM4(bh4[0], bh4[1], bh4[2], bh4[3], rb);
                uint32_t b0h[2] = { bh4[0], bh4[2] }, b1h[2] = { bh4[1], bh4[3] };
                // hi*hi first so the bl4 ldmatrix latency hides behind them
#pragma unroll
                for (int t = 0; t < 2; t++) {
                    MMA_BF16(acc[t][2*g],   ah[t], b0h);
                    MMA_BF16(acc[t][2*g+1], ah[t], b1h);
                }
                LDM4(bl4[0], bl4[1], bl4[2], bl4[3], rb + (OFFBL - OFFBH));
                uint32_t b0l[2] = { bl4[0], bl4[2] }, b1l[2] = { bl4[1], bl4[3] };
#pragma unroll
                for (int t = 0; t < 2; t++) {
                    MMA_BF16(acc[t][2*g],   al[t], b0h);
                    MMA_BF16(acc[t][2*g+1], al[t], b1h);
                }
#pragma unroll
                for (int t = 0; t < 2; t++) {
                    MMA_BF16(acc[t][2*g],   ah[t], b0l);
                    MMA_BF16(acc[t][2*g+1], ah[t], b1l);
                }
            }
        }
        __syncthreads();
    }

#pragma unroll
    for (int t = 0; t < 2; t++) {
        int r0 = m0 + warp_m * 32 + t * 16 + gid;
#pragma unroll
        for (int j = 0; j < 8; j++) {
            int cc = n0 + warp_n * 64 + j * 8 + 2 * tig;
            float b0 = bias ? bias[cc] : 0.f;
            float b1 = bias ? bias[cc + 1] : 0.f;
            float f00 = acc[t][j][0] + b0, f01 = acc[t][j][1] + b1;
            float f10 = acc[t][j][2] + b0, f11 = acc[t][j][3] + b1;
            if (Cout) {
                *reinterpret_cast<float2*>(&Cout[(size_t)r0 * CH + cc]) =
                    make_float2(f00, f01);
                *reinterpret_cast<float2*>(&Cout[(size_t)(r0 + 8) * CH + cc]) =
                    make_float2(f10, f11);
            }
            if (Hsp) {
                __nv_bfloat16 h0 = __float2bfloat16_rn(f00);
                __nv_bfloat16 h1 = __float2bfloat16_rn(f01);
                __nv_bfloat16 h2 = __float2bfloat16_rn(f10);
                __nv_bfloat16 h3 = __float2bfloat16_rn(f11);
                __nv_bfloat16 l0 = __float2bfloat16_rn(f00 - __bfloat162float(h0));
                __nv_bfloat16 l1 = __float2bfloat16_rn(f01 - __bfloat162float(h1));
                __nv_bfloat16 l2 = __float2bfloat16_rn(f10 - __bfloat162float(h2));
                __nv_bfloat16 l3 = __float2bfloat16_rn(f11 - __bfloat162float(h3));
                *reinterpret_cast<__nv_bfloat162*>(&Hsp[(size_t)r0 * CH + cc]) = { h0, h1 };
                *reinterpret_cast<__nv_bfloat162*>(&Hsp[(size_t)(r0 + 8) * CH + cc]) = { h2, h3 };
                *reinterpret_cast<__nv_bfloat162*>(&Lsp[(size_t)r0 * CH + cc]) = { l0, l1 };
                *reinterpret_cast<__nv_bfloat162*>(&Lsp[(size_t)(r0 + 8) * CH + cc]) = { l2, l3 };
            }
        }
    }
}

// merged v + kq GEMM: grid (15, 256); v -> split-only output
__global__ __launch_bounds__(256, 2) void gemm_merged() {
    extern __shared__ char smem[];
    const uint32_t sb = (uint32_t)__cvta_generic_to_shared(smem);
    const int m0 = blockIdx.y * BMM;
    const int bx = blockIdx.x;
    if (bx < 5) {
        gemm_core(g_a2h, g_a2l, g_wbh, g_wbl, nullptr, nullptr,
                  g_vbh, g_vbl, m0, bx * BNN, bx * BNN, sb);
    } else {
        int nb0 = (bx - 5) * BNN;
        if (nb0 < CH)
            gemm_core(g_abh, g_abl, g_wbh + CC, g_wbl + CC, g_k, nullptr,
                      nullptr, nullptr, m0, nb0, nb0, sb);
        else
            gemm_core(g_abh, g_abl, g_wbh + CC, g_wbl + CC, g_q, nullptr,
                      nullptr, nullptr, m0, nb0, nb0 - CH, sb);
    }
}

// proj GEMM: grid (5, 256)
__global__ __launch_bounds__(256, 2) void gemm_proj(
    float* __restrict__ out, const float* __restrict__ bias)
{
    extern __shared__ char smem[];
    const uint32_t sb = (uint32_t)__cvta_generic_to_shared(smem);
    gemm_core(g_abh, g_abl, g_wbh + 3 * CC, g_wbl + 3 * CC, out, bias,
              nullptr, nullptr,
              blockIdx.y * BMM, blockIdx.x * BNN, blockIdx.x * BNN, sb);
}

// ---------------------------------------------------------------------------
// kv2 on tensor pipe (bf16x3, ldmatrix.trans) + fused ksum
// ---------------------------------------------------------------------------
__global__ __launch_bounds__(256, 2) void kv2_mma() {
    extern __shared__ char smem[];
    const uint32_t sb = (uint32_t)__cvta_generic_to_shared(smem);
    const int bh = blockIdx.x, jc = blockIdx.y;
    const int b = bh / NH, hoff = (bh % NH) * HD;
    const __nv_bfloat16* Kh = g_kbh + (size_t)b * SEQ * CH + hoff;
    const __nv_bfloat16* Kl = g_kbl + (size_t)b * SEQ * CH + hoff;
    const __nv_bfloat16* Vh = g_vbh + (size_t)b * SEQ * CH + hoff;
    const __nv_bfloat16* Vl = g_vbl + (size_t)b * SEQ * CH + hoff;

    const int tid = threadIdx.x;
    const int lane = tid & 31;
    const int wid = tid >> 5;
    const int warp_m = wid >> 1;
    const int warp_n = wid & 1;
    const int gid = lane >> 2;
    const int tig = lane & 3;
    const int grp = lane >> 3;
    const int l8 = lane & 7;

    float acc[2][8][4];
#pragma unroll
    for (int t = 0; t < 2; t++)
#pragma unroll
        for (int j = 0; j < 8; j++)
#pragma unroll
            for (int e = 0; e < 4; e++) acc[t][j][e] = 0.f;

    float kacc = 0.f;

    auto fill = [&](int stage, int it) {
        const int j0 = jc * 512 + it * 32;
        const uint32_t stb = sb + (uint32_t)(stage * T2ST);
#pragma unroll
        for (int t = 0; t < 2; t++) {
            int u = tid + t * 256;
            int row = u >> 4, col = u & 15;
            uint32_t off = (uint32_t)(row * T2RW + col * 16);
            size_t g = (size_t)(j0 + row) * CH + col * 8;
            cp16(stb + OKH + off, Kh + g);
            cp16(stb + OKL + off, Kl + g);
            cp16(stb + OVH + off, Vh + g);
            cp16(stb + OVL + off, Vl + g);
        }
        asm volatile("cp.async.commit_group;" ::: "memory");
    };

    fill(0, 0);
    for (int it = 0; it < 16; it++) {
        if (it + 1 < 16) {
            fill((it + 1) & 1, it + 1);
            asm volatile("cp.async.wait_group 1;" ::: "memory");
        } else {
            asm volatile("cp.async.wait_group 0;" ::: "memory");
        }
        __syncthreads();

        const uint32_t stb = sb + (uint32_t)((it & 1) * T2ST);

        if (tid < 128) {
            const __nv_bfloat16* KhS = reinterpret_cast<const __nv_bfloat16*>(
                smem + (it & 1) * T2ST + OKH);
            const __nv_bfloat16* KlS = reinterpret_cast<const __nv_bfloat16*>(
                smem + (it & 1) * T2ST + OKL);
#pragma unroll
            for (int j = 0; j < 32; j++)
                kacc += __bfloat162float(KhS[j * (T2RW / 2) + tid]) +
                        __bfloat162float(KlS[j * (T2RW / 2) + tid]);
        }

#pragma unroll
        for (int ks = 0; ks < 2; ks++) {
            const uint32_t aj = (uint32_t)(ks * 16 + ((grp >> 1) & 1) * 8 + l8);
            uint32_t ah[2][4], al[2][4];
#pragma unroll
            for (int t = 0; t < 2; t++) {
                uint32_t ac = (uint32_t)(warp_m * 32 + t * 16 + (grp & 1) * 8);
                uint32_t ra = stb + OKH + aj * T2RW + ac * 2;
                LDM4T(ah[t][0], ah[t][1], ah[t][2], ah[t][3], ra);
                LDM4T(al[t][0], al[t][1], al[t][2], al[t][3], ra + (OKL - OKH));
            }
            const uint32_t bj = (uint32_t)(ks * 16 + (grp & 1) * 8 + l8);
#pragma unroll
            for (int g = 0; g < 4; g++) {
                uint32_t bd = (uint32_t)(warp_n * 64 + g * 16 + ((grp >> 1) & 1) * 8);
                uint32_t rb = stb + OVH + bj * T2RW + bd * 2;
                uint32_t bh4[4], bl4[4];
                LDM4T(bh4[0], bh4[1], bh4[2], bh4[3], rb);
                uint32_t b0h[2] = { bh4[0], bh4[1] }, b1h[2] = { bh4[2], bh4[3] };
#pragma unroll
                for (int t = 0; t < 2; t++) {
                    MMA_BF16(acc[t][2*g],   ah[t], b0h);
                    MMA_BF16(acc[t][2*g+1], ah[t], b1h);
                }
                LDM4T(bl4[0], bl4[1], bl4[2], bl4[3], rb + (OVL - OVH));
                uint32_t b0l[2] = { bl4[0], bl4[1] }, b1l[2] = { bl4[2], bl4[3] };
#pragma unroll
                for (int t = 0; t < 2; t++) {
                    MMA_BF16(acc[t][2*g],   al[t], b0h);
                    MMA_BF16(acc[t][2*g+1], al[t], b1h);
                }
#pragma unroll
                for (int t = 0; t < 2; t++) {
                    MMA_BF16(acc[t][2*g],   ah[t], b0l);
                    MMA_BF16(acc[t][2*g+1], ah[t], b1l);
                }
            }
        }
        __syncthreads();
    }

    if (tid < 128) atomicAdd(&g_ksum[bh * HD + tid], kacc);

    float* dst = g_kv2 + bh * HD * HD;
#pragma unroll
    for (int t = 0; t < 2; t++) {
        int c0 = warp_m * 32 + t * 16 + gid;
#pragma unroll
        for (int j = 0; j < 8; j++) {
            int d = warp_n * 64 + j * 8 + 2 * tig;
            atomicAdd(&dst[c0 * HD + d],           acc[t][j][0]);
            atomicAdd(&dst[c0 * HD + d + 1],       acc[t][j][1]);
            atomicAdd(&dst[(c0 + 8) * HD + d],     acc[t][j][2]);
            atomicAdd(&dst[(c0 + 8) * HD + d + 1], acc[t][j][3]);
        }
    }
}

// ---------------------------------------------------------------------------
// attn GEMM with fused z (K=128, 4 chunks); epilogue conv-add + z + split
// ---------------------------------------------------------------------------
__global__ __launch_bounds__(256, 2) void attn_gemm() {
    extern __shared__ char smem[];
    const uint32_t sb = (uint32_t)__cvta_generic_to_shared(smem);
    const int bx = blockIdx.x;
    const int bh = bx >> 5;
    const int m0 = (bx & 31) * BMM;
    const int b = bh / NH, hoff = (bh % NH) * HD;
    const __nv_bfloat16* Ah = g_qbh + (size_t)b * SEQ * CH + hoff;
    const __nv_bfloat16* Al = g_qbl + (size_t)b * SEQ * CH + hoff;
    const __nv_bfloat16* Bh = g_k2h + (size_t)bh * HD * HD;
    const __nv_bfloat16* Bl = g_k2l + (size_t)bh * HD * HD;

    const int tid = threadIdx.x;
    const int lane = tid & 31;
    const int wid = tid >> 5;
    const int warp_m = wid >> 1;
    const int warp_n = wid & 1;
    const int gid = lane >> 2;
    const int tig = lane & 3;
    const int lr = (lane & 7) + ((lane >> 3) & 1) * 8;
    const uint32_t lc = (uint32_t)(((lane >> 4) & 1) * 16);

    float acc[2][8][4];
#pragma unroll
    for (int t = 0; t < 2; t++)
#pragma unroll
        for (int j = 0; j < 8; j++)
#pragma unroll
            for (int e = 0; e < 4; e++) acc[t][j][e] = 0.f;

    int r0f = tid >> 2, c0f = tid & 3;
    int r1f = (tid + 256) >> 2, c1f = (tid + 256) & 3;
    const uint32_t so0 = (uint32_t)(r0f * RWB + c0f * 16);
    const uint32_t so1 = (uint32_t)(r1f * RWB + c1f * 16);
    const size_t gA0 = (size_t)(m0 + r0f) * CH + c0f * 8;
    const size_t gA1 = (size_t)(m0 + r1f) * CH + c1f * 8;
    const size_t gB0 = (size_t)r0f * HD + c0f * 8;
    const size_t gB1 = (size_t)r1f * HD + c1f * 8;

    auto fill = [&](int stage, int chunk) {
        const int k0 = chunk * BKE;
        const uint32_t stb = sb + (uint32_t)(stage * STB);
        cp16(stb + OFFAH + so0, Ah + gA0 + k0);
        cp16(stb + OFFAL + so0, Al + gA0 + k0);
        cp16(stb + OFFBH + so0, Bh + gB0 + k0);
        cp16(stb + OFFBL + so0, Bl + gB0 + k0);
        cp16(stb + OFFAH + so1, Ah + gA1 + k0);
        cp16(stb + OFFAL + so1, Al + gA1 + k0);
        cp16(stb + OFFBH + so1, Bh + gB1 + k0);
        cp16(stb + OFFBL + so1, Bl + gB1 + k0);
        asm volatile("cp.async.commit_group;" ::: "memory");
    };

    const uint32_t raF = (uint32_t)((warp_m * 32 + lr) * RWB) + lc;
    const uint32_t rbF = (uint32_t)((warp_n * 64 + lr) * RWB) + lc;

    float zacc = 0.f;

    fill(0, 0);
#pragma unroll
    for (int i = 0; i < 4; i++) {
        if (i + 1 < 4) {
            fill((i + 1) & 1, i + 1);
            asm volatile("cp.async.wait_group 1;" ::: "memory");
        } else {
            asm volatile("cp.async.wait_group 0;" ::: "memory");
        }
        __syncthreads();

        const uint32_t stb = sb + (uint32_t)((i & 1) * STB);

        if (tid < 128) {
            const uint32_t qh = stb + OFFAH + (uint32_t)(tid * RWB);
            const float* ksp = g_ksum + bh * HD + i * BKE;
#pragma unroll
            for (int cc = 0; cc < 32; cc += 2) {
                uint32_t hv, lv;
                asm("ld.shared.b32 %0, [%1];" : "=r"(hv) : "r"(qh + cc * 2));
                asm("ld.shared.b32 %0, [%1];" : "=r"(lv)
                    : "r"(qh + (OFFAL - OFFAH) + cc * 2));
                __nv_bfloat162 h2 = *reinterpret_cast<__nv_bfloat162*>(&hv);
                __nv_bfloat162 l2 = *reinterpret_cast<__nv_bfloat162*>(&lv);
                float q0 = __bfloat162float(h2.x) + __bfloat162float(l2.x);
                float q1 = __bfloat162float(h2.y) + __bfloat162float(l2.y);
                zacc += q0 * __ldg(ksp + cc) + q1 * __ldg(ksp + cc + 1);
            }
        }

#pragma unroll
        for (int ks = 0; ks < 2; ks++) {
            const uint32_t kofs = (uint32_t)(ks * 32);
            uint32_t ah[2][4], al[2][4];
#pragma unroll
            for (int t = 0; t < 2; t++) {
                uint32_t ra = stb + OFFAH + raF + (uint32_t)(t * 16 * RWB) + kofs;
                LDM4(ah[t][0], ah[t][1], ah[t][2], ah[t][3], ra);
                LDM4(al[t][0], al[t][1], al[t][2], al[t][3], ra + (OFFAL - OFFAH));
            }
#pragma unroll
            for (int g = 0; g < 4; g++) {
                uint32_t rb = stb + OFFBH + rbF + (uint32_t)(g * 16 * RWB) + kofs;
                uint32_t bh4[4], bl4[4];
                LDM4(bh4[0], bh4[1], bh4[2], bh4[3], rb);
                uint32_t b0h[2] = { bh4[0], bh4[2] }, b1h[2] = { bh4[1], bh4[3] };
#pragma unroll
                for (int t = 0; t < 2; t++) {
                    MMA_BF16(acc[t][2*g],   ah[t], b0h);
                    MMA_BF16(acc[t][2*g+1], ah[t], b1h);
                }
                LDM4(bl4[0], bl4[1], bl4[2], bl4[3], rb + (OFFBL - OFFBH));
                uint32_t b0l[2] = { bl4[0], bl4[2] }, b1l[2] = { bl4[1], bl4[3] };
#pragma unroll
                for (int t = 0; t < 2; t++) {
                    MMA_BF16(acc[t][2*g],   al[t], b0h);
                    MMA_BF16(acc[t][2*g+1], al[t], b1h);
                }
#pragma unroll
                for (int t = 0; t < 2; t++) {
                    MMA_BF16(acc[t][2*g],   ah[t], b0l);
                    MMA_BF16(acc[t][2*g+1], ah[t], b1l);
                }
            }
        }
        __syncthreads();
    }

    float* zs = reinterpret_cast<float*>(smem);
    if (tid < 128) zs[tid] = 1.f / (zacc + 1e-6f);
    __syncthreads();

#pragma unroll
    for (int t = 0; t < 2; t++) {
        int lr0 = warp_m * 32 + t * 16 + gid;
#pragma unroll
        for (int j = 0; j < 8; j++) {
            int d = warp_n * 64 + j * 8 + 2 * tig;
#pragma unroll
            for (int half = 0; half < 2; half++) {
                int lrow = lr0 + half * 8;
                int i = m0 + lrow;
                float zv = zs[lrow];
                size_t base = (size_t)(b * SEQ + i) * CH + hoff + d;
                float f0 = g_x[base]     + acc[t][j][half * 2]     * zv;
                float f1 = g_x[base + 1] + acc[t][j][half * 2 + 1] * zv;
                __nv_bfloat16 h0 = __float2bfloat16_rn(f0);
                __nv_bfloat16 h1 = __float2bfloat16_rn(f1);
                __nv_bfloat16 l0 = __float2bfloat16_rn(f0 - __bfloat162float(h0));
                __nv_bfloat16 l1 = __float2bfloat16_rn(f1 - __bfloat162float(h1));
                *reinterpret_cast<__nv_bfloat162*>(&g_abh[base]) = { h0, h1 };
                *reinterpret_cast<__nv_bfloat162*>(&g_abl[base]) = { l0, l1 };
            }
        }
    }
}

// ---------------------------------------------------------------------------
__global__ void softplus_kernel(const float* __restrict__ scale) {
    int c = blockIdx.x * 256 + threadIdx.x;
    if (c < CH) g_sc[c] = log1pf(expf(scale[c]));
}

// ---------------------------------------------------------------------------
__device__ __forceinline__ float warp_sum(float s) {
#pragma unroll
    for (int o = 16; o > 0; o >>= 1) s += __shfl_xor_sync(0xffffffffu, s, o);
    return s;
}

// qknorm: warp per row; q and k both -> bf16 hi/lo.
__global__ __launch_bounds__(256) void qknorm_kernel(const float* __restrict__ pos) {
    const int w = blockIdx.x * 8 + (threadIdx.x >> 5);
    const int lane = threadIdx.x & 31;
    const size_t row = (size_t)w;
    const int n = w & (SEQ - 1);
    const float* qrow = g_q + row * CH;
    const float* krow = g_k + row * CH;
    const float* prow = pos + (size_t)n * CH;

    float scv[20];
#pragma unroll
    for (int t = 0; t < 20; t++) scv[t] = g_sc[lane + 32 * t];

    {
        float v[20]; float s = 0.f;
#pragma unroll
        for (int t = 0; t < 20; t++) {
            float raw = qrow[lane + 32 * t];
            float val = (fmaxf(raw, 0.f) + 1e-6f) / scv[t];
            v[t] = val; s += val * val;
        }
        float n1 = sqrtf(warp_sum(s));
        s = 0.f;
#pragma unroll
        for (int t = 0; t < 20; t++) { float c3 = v[t]*v[t]*v[t]; v[t] = c3; s += c3*c3; }
        float sc2 = n1 / sqrtf(warp_sum(s));
#pragma unroll
        for (int t = 0; t < 20; t++) {
            float f = v[t] * sc2;
            __nv_bfloat16 h = __float2bfloat16_rn(f);
            __nv_bfloat16 l = __float2bfloat16_rn(f - __bfloat162float(h));
            g_qbh[row * CH + lane + 32 * t] = h;
            g_qbl[row * CH + lane + 32 * t] = l;
        }
    }
    {
        float v[20]; float s = 0.f;
#pragma unroll
        for (int t = 0; t < 20; t++) {
            float raw = krow[lane + 32 * t] + prow[lane + 32 * t];
            float val = (fmaxf(raw, 0.f) + 1e-6f) / scv[t];
            v[t] = val; s += val * val;
        }
        float n1 = sqrtf(warp_sum(s));
        s = 0.f;
#pragma unroll
        for (int t = 0; t < 20; t++) { float c3 = v[t]*v[t]*v[t]; v[t] = c3; s += c3*c3; }
        float sc2 = n1 / sqrtf(warp_sum(s));
#pragma unroll
        for (int t = 0; t < 20; t++) {
            float f = v[t] * sc2;
            __nv_bfloat16 h = __float2bfloat16_rn(f);
            __nv_bfloat16 l = __float2bfloat16_rn(f - __bfloat162float(h));
            g_kbh[row * CH + lane + 32 * t] = h;
            g_kbl[row * CH + lane + 32 * t] = l;
        }
    }
}

__global__ void zero_kernel() {
    int idx = blockIdx.x * 256 + threadIdx.x;
    if (idx < BH * HD * HD) g_kv2[idx] = 0.f;
    if (idx < BH * HD)      g_ksum[idx] = 0.f;
}

// kv2^T + bf16 split: [bh][c][d] fp32 -> [bh][d][c] hi/lo
__global__ __launch_bounds__(256) void kv2t_split() {
    const int bh = blockIdx.x;
    const int e = blockIdx.y * 256 + threadIdx.x;
    const int d = e >> 7, c = e & 127;
    float v = g_kv2[bh * HD * HD + c * HD + d];
    __nv_bfloat16 h = __float2bfloat16_rn(v);
    __nv_bfloat16 l = __float2bfloat16_rn(v - __bfloat162float(h));
    g_k2h[bh * HD * HD + d * HD + c] = h;
    g_k2l[bh * HD * HD + d * HD + c] = l;
}

// ---------------------------------------------------------------------------
// depthwise conv reading v hi/lo splits (reconstruct in smem)
// ---------------------------------------------------------------------------
__global__ __launch_bounds__(256) void conv_s(
    const float* __restrict__ w, const float* __restrict__ bias)
{
    extern __shared__ float sv[];   // [8][68][32]
    const int bh = blockIdx.x, yt = blockIdx.y, dc = blockIdx.z;
    const int b = bh / NH, hoff = (bh % NH) * HD;
    const int tid = threadIdx.x;
    const int d = tid & 31;
    const int xg = tid >> 5;
    const __nv_bfloat16* vh = g_vbh + (size_t)b * SEQ * CH + hoff + dc * 32;
    const __nv_bfloat16* vl = g_vbl + (size_t)b * SEQ * CH + hoff + dc * 32;

    {
        int p = tid;
        int r = p >> 5, rest = p & 31;
        int xi = rest >> 3, d4 = rest & 7;
        int ix = (xi < 2) ? xi : (xi + 64);
        *reinterpret_cast<float4*>(&sv[(r * 68 + ix) * 32 + d4 * 4]) =
            make_float4(0.f, 0.f, 0.f, 0.f);
    }
    // 8 rows x 64 x x 4 d-octets = 2048 iterations of 8 elems
    for (int p = tid; p < 2048; p += 256) {
        int r = p >> 8, rest = p & 255;
        int x = rest >> 2, d8 = rest & 3;
        int y = yt * 4 - 2 + r;
        float f[8];
        if ((unsigned)y < 64u) {
            uint4 hv = *reinterpret_cast<const uint4*>(
                &vh[(size_t)(y * 64 + x) * CH + d8 * 8]);
            uint4 lv = *reinterpret_cast<const uint4*>(
                &vl[(size_t)(y * 64 + x) * CH + d8 * 8]);
            const __nv_bfloat162* h2 = reinterpret_cast<const __nv_bfloat162*>(&hv);
            const __nv_bfloat162* l2 = reinterpret_cast<const __nv_bfloat162*>(&lv);
#pragma unroll
            for (int j = 0; j < 4; j++) {
                f[2*j]   = __bfloat162float(h2[j].x) + __bfloat162float(l2[j].x);
                f[2*j+1] = __bfloat162float(h2[j].y) + __bfloat162float(l2[j].y);
            }
        } else {
#pragma unroll
            for (int j = 0; j < 8; j++) f[j] = 0.f;
        }
        float* dst = &sv[(r * 68 + x + 2) * 32 + d8 * 8];
        *reinterpret_cast<float4*>(dst)     = make_float4(f[0], f[1], f[2], f[3]);
        *reinterpret_cast<float4*>(dst + 4) = make_float4(f[4], f[5], f[6], f[7]);
    }
    __syncthreads();

    float wr[25];
#pragma unroll
    for (int k = 0; k < 25; k++) wr[k] = __ldg(&w[(dc * 32 + d) * 25 + k]);
    const float bv = __ldg(&bias[dc * 32 + d]);

#pragma unroll
    for (int y = 0; y < 4; y++) {
#pragma unroll
        for (int xo = 0; xo < 8; xo++) {
            int x = xg * 8 + xo;
            float acc = bv;
#pragma unroll
            for (int ky = 0; ky < 5; ky++)
#pragma unroll
                for (int kx = 0; kx < 5; kx++)
                    acc += wr[ky * 5 + kx] * sv[((y + ky) * 68 + (x + kx)) * 32 + d];
            int oy = yt * 4 + y;
            g_x[(size_t)(b * SEQ + oy * 64 + x) * CH + hoff + dc * 32 + d] = acc;
        }
    }
}

// ---------------------------------------------------------------------------
extern "C" void kernel_launch(void* const* d_in, const int* in_sizes, int n_in,
                              void* d_out, int out_size)
{
    const float* x1    = (const float*)d_in[0];
    const float* x2    = (const float*)d_in[1];
    const float* Wq    = (const float*)d_in[2];
    const float* Wkv   = (const float*)d_in[3];
    const float* Wproj = (const float*)d_in[4];
    const float* bproj = (const float*)d_in[5];
    const float* dwc_w = (const float*)d_in[6];
    const float* dwc_b = (const float*)d_in[7];
    const float* scale = (const float*)d_in[8];
    const float* pos   = (const float*)d_in[9];
    float* out = (float*)d_out;

    __nv_bfloat16 *pah, *pal, *pa2h, *pa2l;
    cudaGetSymbolAddress((void**)&pah, g_abh);
    cudaGetSymbolAddress((void**)&pal, g_abl);
    cudaGetSymbolAddress((void**)&pa2h, g_a2h);
    cudaGetSymbolAddress((void**)&pa2l, g_a2l);

    cudaFuncSetAttribute(gemm_merged,
        cudaFuncAttributeMaxDynamicSharedMemorySize, SMEM_GB);
    cudaFuncSetAttribute(gemm_proj,
        cudaFuncAttributeMaxDynamicSharedMemorySize, SMEM_GB);
    cudaFuncSetAttribute(attn_gemm,
        cudaFuncAttributeMaxDynamicSharedMemorySize, SMEM_GB);
    cudaFuncSetAttribute(kv2_mma,
        cudaFuncAttributeMaxDynamicSharedMemorySize, SMEM_KV2);
    cudaFuncSetAttribute(conv_s,
        cudaFuncAttributeMaxDynamicSharedMemorySize, 8 * 68 * 32 * 4);

    const int M = BATCH * SEQ;              // 32768
    const int XN4 = M * CH / 4;

    split_w<<<4 * CC / 1024, 256>>>(Wq, Wkv, Wproj);                  // 0
    softplus_kernel<<<3, 256>>>(scale);                               // 1
    split_x<<<XN4 / 256, 256>>>(x1, pah, pal, XN4);                   // 2
    split_x<<<XN4 / 256, 256>>>(x2, pa2h, pa2l, XN4);                 // 3
    gemm_merged<<<dim3(15, M / BMM), 256, SMEM_GB>>>();               // 4: v+k+q

    qknorm_kernel<<<M / 8, 256>>>(pos);
    zero_kernel<<<(BH * HD * HD + 255) / 256, 256>>>();
    kv2_mma<<<dim3(BH, 8), 256, SMEM_KV2>>>();   // tensor-pipe kv2 + ksum
    kv2t_split<<<dim3(BH, 64), 256>>>();
    conv_s<<<dim3(BH, 16, 4), 256, 8 * 68 * 32 * 4>>>(dwc_w, dwc_b);
    attn_gemm<<<BH * 32, 256, SMEM_GB>>>();      // + fused z

    gemm_proj<<<dim3(5, M / BMM), 256, SMEM_GB>>>(out, bproj);
}

// round 14
// speedup vs baseline: 1.8542x; 1.0076x over previous
#include <cuda_runtime.h>
#include <cuda_bf16.h>
#include <cstdint>
#include <cstddef>

// ---------------------------------------------------------------------------
// FocusedLinearAttention — round 14:
//   single-__syncthreads pipelined mainloops (fill after barrier, wait_group 0)
//   in gemm_core / kv2_mma / attn_gemm. Barriers per chunk: 2 -> 1.
// ---------------------------------------------------------------------------

#define BATCH 8
#define SEQ   4096
#define CH    640
#define CC    (CH*CH)
#define NH    5
#define HD    128
#define BH    (BATCH*NH)   // 40

#define BMM 128
#define BNN 128
#define BKE 32
#define NCHB (CH/BKE)           // 20
#define RWB 80
#define BUFB (128*RWB)
#define OFFAH 0
#define OFFAL BUFB
#define OFFBH (2*BUFB)
#define OFFBL (3*BUFB)
#define STB   (4*BUFB)          // 40960 B
#define SMEM_GB (2*STB)         // 81920 B -> 2 CTAs/SM

#define T2RW 272
#define T2BUF (32*T2RW)
#define OKH 0
#define OKL T2BUF
#define OVH (2*T2BUF)
#define OVL (3*T2BUF)
#define T2ST (4*T2BUF)          // 34816
#define SMEM_KV2 (2*T2ST)       // 69632

__device__ float g_q[BATCH*SEQ*CH];
__device__ float g_k[BATCH*SEQ*CH];
__device__ float g_x[BATCH*SEQ*CH];
__device__ __nv_bfloat16 g_abh[BATCH*SEQ*CH];
__device__ __nv_bfloat16 g_abl[BATCH*SEQ*CH];
__device__ __nv_bfloat16 g_a2h[BATCH*SEQ*CH];
__device__ __nv_bfloat16 g_a2l[BATCH*SEQ*CH];
__device__ __nv_bfloat16 g_qbh[BATCH*SEQ*CH];
__device__ __nv_bfloat16 g_qbl[BATCH*SEQ*CH];
__device__ __nv_bfloat16 g_kbh[BATCH*SEQ*CH];
__device__ __nv_bfloat16 g_kbl[BATCH*SEQ*CH];
__device__ __nv_bfloat16 g_vbh[BATCH*SEQ*CH];
__device__ __nv_bfloat16 g_vbl[BATCH*SEQ*CH];
__device__ __nv_bfloat16 g_wbh[4*CC];
__device__ __nv_bfloat16 g_wbl[4*CC];
__device__ __nv_bfloat16 g_k2h[BH*HD*HD];
__device__ __nv_bfloat16 g_k2l[BH*HD*HD];
__device__ float g_kv2[BH*HD*HD];
__device__ float g_ksum[BH*HD];
__device__ float g_sc[CH];

// ---------------------------------------------------------------------------
__device__ __forceinline__ void cp16(uint32_t dst, const void* src) {
    asm volatile("cp.async.cg.shared.global [%0], [%1], 16;" :: "r"(dst), "l"(src));
}

#define LDM4(r0, r1, r2, r3, a) \
    asm volatile("ldmatrix.sync.aligned.m8n8.x4.shared.b16 {%0,%1,%2,%3}, [%4];" \
        : "=r"(r0), "=r"(r1), "=r"(r2), "=r"(r3) : "r"(a))

#define LDM4T(r0, r1, r2, r3, a) \
    asm volatile("ldmatrix.sync.aligned.m8n8.x4.trans.shared.b16 {%0,%1,%2,%3}, [%4];" \
        : "=r"(r0), "=r"(r1), "=r"(r2), "=r"(r3) : "r"(a))

#define MMA_BF16(d, a, b) \
    asm volatile( \
        "mma.sync.aligned.m16n8k16.row.col.f32.bf16.bf16.f32 " \
        "{%0,%1,%2,%3}, {%4,%5,%6,%7}, {%8,%9}, {%0,%1,%2,%3};" \
        : "+f"((d)[0]), "+f"((d)[1]), "+f"((d)[2]), "+f"((d)[3]) \
        : "r"((a)[0]), "r"((a)[1]), "r"((a)[2]), "r"((a)[3]), \
          "r"((b)[0]), "r"((b)[1]))

// ---------------------------------------------------------------------------
__device__ __forceinline__ void split4(float4 v, __nv_bfloat16* hp, __nv_bfloat16* lp) {
    float f[4] = { v.x, v.y, v.z, v.w };
    __nv_bfloat16 h[4], l[4];
#pragma unroll
    for (int j = 0; j < 4; j++) {
        h[j] = __float2bfloat16_rn(f[j]);
        l[j] = __float2bfloat16_rn(f[j] - __bfloat162float(h[j]));
    }
    *reinterpret_cast<__nv_bfloat162*>(hp)     = { h[0], h[1] };
    *reinterpret_cast<__nv_bfloat162*>(hp + 2) = { h[2], h[3] };
    *reinterpret_cast<__nv_bfloat162*>(lp)     = { l[0], l[1] };
    *reinterpret_cast<__nv_bfloat162*>(lp + 2) = { l[2], l[3] };
}

__global__ __launch_bounds__(256) void split_x(
    const float* __restrict__ src, __nv_bfloat16* __restrict__ hi,
    __nv_bfloat16* __restrict__ lo, int n4)
{
    int i = blockIdx.x * 256 + threadIdx.x;
    if (i >= n4) return;
    split4(reinterpret_cast<const float4*>(src)[i], hi + 4 * i, lo + 4 * i);
}

__global__ __launch_bounds__(256) void split_w(
    const float* __restrict__ Wq, const float* __restrict__ Wkv,
    const float* __restrict__ Wproj)
{
    int i = blockIdx.x * 256 + threadIdx.x;
    int fi = i * 4;
    const float* src; int off;
    if (fi < CC)          { src = Wq;    off = 0; }
    else if (fi < 3 * CC) { src = Wkv;   off = CC; }
    else                  { src = Wproj; off = 3 * CC; }
    float4 v = *reinterpret_cast<const float4*>(&src[fi - off]);
    split4(v, g_wbh + fi, g_wbl + fi);
}

// ---------------------------------------------------------------------------
// common bf16x3 GEMM core (K = 640); single-sync pipelined mainloop
// ---------------------------------------------------------------------------
__device__ __forceinline__ void gemm_core(
    const __nv_bfloat16* __restrict__ Ah, const __nv_bfloat16* __restrict__ Al,
    const __nv_bfloat16* __restrict__ Bh, const __nv_bfloat16* __restrict__ Bl,
    float* __restrict__ Cout, const float* __restrict__ bias,
    __nv_bfloat16* __restrict__ Hsp, __nv_bfloat16* __restrict__ Lsp,
    int m0, int nb0, int n0, uint32_t sb)
{
    const int tid = threadIdx.x;
    const int lane = tid & 31;
    const int wid = tid >> 5;
    const int warp_m = wid >> 1;
    const int warp_n = wid & 1;
    const int gid = lane >> 2;
    const int tig = lane & 3;
    const int lr = (lane & 7) + ((lane >> 3) & 1) * 8;
    const uint32_t lc = (uint32_t)(((lane >> 4) & 1) * 16);

    float acc[2][8][4];
#pragma unroll
    for (int t = 0; t < 2; t++)
#pragma unroll
        for (int j = 0; j < 8; j++)
#pragma unroll
            for (int e = 0; e < 4; e++) acc[t][j][e] = 0.f;

    int r0f = tid >> 2, c0f = tid & 3;
    int r1f = (tid + 256) >> 2, c1f = (tid + 256) & 3;
    const uint32_t so0 = (uint32_t)(r0f * RWB + c0f * 16);
    const uint32_t so1 = (uint32_t)(r1f * RWB + c1f * 16);
    const size_t gA0 = (size_t)(m0 + r0f) * CH + c0f * 8;
    const size_t gA1 = (size_t)(m0 + r1f) * CH + c1f * 8;
    const size_t gB0 = (size_t)(nb0 + r0f) * CH + c0f * 8;
    const size_t gB1 = (size_t)(nb0 + r1f) * CH + c1f * 8;

    auto fill = [&](int stage, int chunk) {
        const int k0 = chunk * BKE;
        const uint32_t stb = sb + (uint32_t)(stage * STB);
        cp16(stb + OFFAH + so0, Ah + gA0 + k0);
        cp16(stb + OFFAL + so0, Al + gA0 + k0);
        cp16(stb + OFFBH + so0, Bh + gB0 + k0);
        cp16(stb + OFFBL + so0, Bl + gB0 + k0);
        cp16(stb + OFFAH + so1, Ah + gA1 + k0);
        cp16(stb + OFFAL + so1, Al + gA1 + k0);
        cp16(stb + OFFBH + so1, Bh + gB1 + k0);
        cp16(stb + OFFBL + so1, Bl + gB1 + k0);
        asm volatile("cp.async.commit_group;" ::: "memory");
    };

    const uint32_t raF = (uint32_t)((warp_m * 32 + lr) * RWB) + lc;
    const uint32_t rbF = (uint32_t)((warp_n * 64 + lr) * RWB) + lc;

    fill(0, 0);
    for (int i = 0; i < NCHB; i++) {
        asm volatile("cp.async.wait_group 0;" ::: "memory");
        __syncthreads();
        if (i + 1 < NCHB) fill((i + 1) & 1, i + 1);

        const uint32_t stb = sb + (uint32_t)((i & 1) * STB);
#pragma unroll
        for (int ks = 0; ks < 2; ks++) {
            const uint32_t kofs = (uint32_t)(ks * 32);
            uint32_t ah[2][4], al[2][4];
#pragma unroll
            for (int t = 0; t < 2; t++) {
                uint32_t ra = stb + OFFAH + raF + (uint32_t)(t * 16 * RWB) + kofs;
                LDM4(ah[t][0], ah[t][1], ah[t][2], ah[t][3], ra);
                LDM4(al[t][0], al[t][1], al[t][2], al[t][3], ra + (OFFAL - OFFAH));
            }
#pragma unroll
            for (int g = 0; g < 4; g++) {
                uint32_t rb = stb + OFFBH + rbF + (uint32_t)(g * 16 * RWB) + kofs;
                uint32_t bh4[4], bl4[4];
                LDM4(bh4[0], bh4[1], bh4[2], bh4[3], rb);
                uint32_t b0h[2] = { bh4[0], bh4[2] }, b1h[2] = { bh4[1], bh4[3] };
#pragma unroll
                for (int t = 0; t < 2; t++) {
                    MMA_BF16(acc[t][2*g],   ah[t], b0h);
                    MMA_BF16(acc[t][2*g+1], ah[t], b1h);
                }
                LDM4(bl4[0], bl4[1], bl4[2], bl4[3], rb + (OFFBL - OFFBH));
                uint32_t b0l[2] = { bl4[0], bl4[2] }, b1l[2] = { bl4[1], bl4[3] };
#pragma unroll
                for (int t = 0; t < 2; t++) {
                    MMA_BF16(acc[t][2*g],   al[t], b0h);
                    MMA_BF16(acc[t][2*g+1], al[t], b1h);
                }
#pragma unroll
                for (int t = 0; t < 2; t++) {
                    MMA_BF16(acc[t][2*g],   ah[t], b0l);
                    MMA_BF16(acc[t][2*g+1], ah[t], b1l);
                }
            }
        }
    }

#pragma unroll
    for (int t = 0; t < 2; t++) {
        int r0 = m0 + warp_m * 32 + t * 16 + gid;
#pragma unroll
        for (int j = 0; j < 8; j++) {
            int cc = n0 + warp_n * 64 + j * 8 + 2 * tig;
            float b0 = bias ? bias[cc] : 0.f;
            float b1 = bias ? bias[cc + 1] : 0.f;
            float f00 = acc[t][j][0] + b0, f01 = acc[t][j][1] + b1;
            float f10 = acc[t][j][2] + b0, f11 = acc[t][j][3] + b1;
            if (Cout) {
                *reinterpret_cast<float2*>(&Cout[(size_t)r0 * CH + cc]) =
                    make_float2(f00, f01);
                *reinterpret_cast<float2*>(&Cout[(size_t)(r0 + 8) * CH + cc]) =
                    make_float2(f10, f11);
            }
            if (Hsp) {
                __nv_bfloat16 h0 = __float2bfloat16_rn(f00);
                __nv_bfloat16 h1 = __float2bfloat16_rn(f01);
                __nv_bfloat16 h2 = __float2bfloat16_rn(f10);
                __nv_bfloat16 h3 = __float2bfloat16_rn(f11);
                __nv_bfloat16 l0 = __float2bfloat16_rn(f00 - __bfloat162float(h0));
                __nv_bfloat16 l1 = __float2bfloat16_rn(f01 - __bfloat162float(h1));
                __nv_bfloat16 l2 = __float2bfloat16_rn(f10 - __bfloat162float(h2));
                __nv_bfloat16 l3 = __float2bfloat16_rn(f11 - __bfloat162float(h3));
                *reinterpret_cast<__nv_bfloat162*>(&Hsp[(size_t)r0 * CH + cc]) = { h0, h1 };
                *reinterpret_cast<__nv_bfloat162*>(&Hsp[(size_t)(r0 + 8) * CH + cc]) = { h2, h3 };
                *reinterpret_cast<__nv_bfloat162*>(&Lsp[(size_t)r0 * CH + cc]) = { l0, l1 };
                *reinterpret_cast<__nv_bfloat162*>(&Lsp[(size_t)(r0 + 8) * CH + cc]) = { l2, l3 };
            }
        }
    }
}

// merged v + kq GEMM: grid (15, 256); v -> split-only output
__global__ __launch_bounds__(256, 2) void gemm_merged() {
    extern __shared__ char smem[];
    const uint32_t sb = (uint32_t)__cvta_generic_to_shared(smem);
    const int m0 = blockIdx.y * BMM;
    const int bx = blockIdx.x;
    if (bx < 5) {
        gemm_core(g_a2h, g_a2l, g_wbh, g_wbl, nullptr, nullptr,
                  g_vbh, g_vbl, m0, bx * BNN, bx * BNN, sb);
    } else {
        int nb0 = (bx - 5) * BNN;
        if (nb0 < CH)
            gemm_core(g_abh, g_abl, g_wbh + CC, g_wbl + CC, g_k, nullptr,
                      nullptr, nullptr, m0, nb0, nb0, sb);
        else
            gemm_core(g_abh, g_abl, g_wbh + CC, g_wbl + CC, g_q, nullptr,
                      nullptr, nullptr, m0, nb0, nb0 - CH, sb);
    }
}

// proj GEMM: grid (5, 256)
__global__ __launch_bounds__(256, 2) void gemm_proj(
    float* __restrict__ out, const float* __restrict__ bias)
{
    extern __shared__ char smem[];
    const uint32_t sb = (uint32_t)__cvta_generic_to_shared(smem);
    gemm_core(g_abh, g_abl, g_wbh + 3 * CC, g_wbl + 3 * CC, out, bias,
              nullptr, nullptr,
              blockIdx.y * BMM, blockIdx.x * BNN, blockIdx.x * BNN, sb);
}

// ---------------------------------------------------------------------------
// kv2 on tensor pipe (bf16x3, ldmatrix.trans) + fused ksum; single-sync loop
// ---------------------------------------------------------------------------
__global__ __launch_bounds__(256, 2) void kv2_mma() {
    extern __shared__ char smem[];
    const uint32_t sb = (uint32_t)__cvta_generic_to_shared(smem);
    const int bh = blockIdx.x, jc = blockIdx.y;
    const int b = bh / NH, hoff = (bh % NH) * HD;
    const __nv_bfloat16* Kh = g_kbh + (size_t)b * SEQ * CH + hoff;
    const __nv_bfloat16* Kl = g_kbl + (size_t)b * SEQ * CH + hoff;
    const __nv_bfloat16* Vh = g_vbh + (size_t)b * SEQ * CH + hoff;
    const __nv_bfloat16* Vl = g_vbl + (size_t)b * SEQ * CH + hoff;

    const int tid = threadIdx.x;
    const int lane = tid & 31;
    const int wid = tid >> 5;
    const int warp_m = wid >> 1;
    const int warp_n = wid & 1;
    const int gid = lane >> 2;
    const int tig = lane & 3;
    const int grp = lane >> 3;
    const int l8 = lane & 7;

    float acc[2][8][4];
#pragma unroll
    for (int t = 0; t < 2; t++)
#pragma unroll
        for (int j = 0; j < 8; j++)
#pragma unroll
            for (int e = 0; e < 4; e++) acc[t][j][e] = 0.f;

    float kacc = 0.f;

    auto fill = [&](int stage, int it) {
        const int j0 = jc * 512 + it * 32;
        const uint32_t stb = sb + (uint32_t)(stage * T2ST);
#pragma unroll
        for (int t = 0; t < 2; t++) {
            int u = tid + t * 256;
            int row = u >> 4, col = u & 15;
            uint32_t off = (uint32_t)(row * T2RW + col * 16);
            size_t g = (size_t)(j0 + row) * CH + col * 8;
            cp16(stb + OKH + off, Kh + g);
            cp16(stb + OKL + off, Kl + g);
            cp16(stb + OVH + off, Vh + g);
            cp16(stb + OVL + off, Vl + g);
        }
        asm volatile("cp.async.commit_group;" ::: "memory");
    };

    fill(0, 0);
    for (int it = 0; it < 16; it++) {
        asm volatile("cp.async.wait_group 0;" ::: "memory");
        __syncthreads();
        if (it + 1 < 16) fill((it + 1) & 1, it + 1);

        const uint32_t stb = sb + (uint32_t)((it & 1) * T2ST);

        if (tid < 128) {
            const __nv_bfloat16* KhS = reinterpret_cast<const __nv_bfloat16*>(
                smem + (it & 1) * T2ST + OKH);
            const __nv_bfloat16* KlS = reinterpret_cast<const __nv_bfloat16*>(
                smem + (it & 1) * T2ST + OKL);
#pragma unroll
            for (int j = 0; j < 32; j++)
                kacc += __bfloat162float(KhS[j * (T2RW / 2) + tid]) +
                        __bfloat162float(KlS[j * (T2RW / 2) + tid]);
        }

#pragma unroll
        for (int ks = 0; ks < 2; ks++) {
            const uint32_t aj = (uint32_t)(ks * 16 + ((grp >> 1) & 1) * 8 + l8);
            uint32_t ah[2][4], al[2][4];
#pragma unroll
            for (int t = 0; t < 2; t++) {
                uint32_t ac = (uint32_t)(warp_m * 32 + t * 16 + (grp & 1) * 8);
                uint32_t ra = stb + OKH + aj * T2RW + ac * 2;
                LDM4T(ah[t][0], ah[t][1], ah[t][2], ah[t][3], ra);
                LDM4T(al[t][0], al[t][1], al[t][2], al[t][3], ra + (OKL - OKH));
            }
            const uint32_t bj = (uint32_t)(ks * 16 + (grp & 1) * 8 + l8);
#pragma unroll
            for (int g = 0; g < 4; g++) {
                uint32_t bd = (uint32_t)(warp_n * 64 + g * 16 + ((grp >> 1) & 1) * 8);
                uint32_t rb = stb + OVH + bj * T2RW + bd * 2;
                uint32_t bh4[4], bl4[4];
                LDM4T(bh4[0], bh4[1], bh4[2], bh4[3], rb);
                uint32_t b0h[2] = { bh4[0], bh4[1] }, b1h[2] = { bh4[2], bh4[3] };
#pragma unroll
                for (int t = 0; t < 2; t++) {
                    MMA_BF16(acc[t][2*g],   ah[t], b0h);
                    MMA_BF16(acc[t][2*g+1], ah[t], b1h);
                }
                LDM4T(bl4[0], bl4[1], bl4[2], bl4[3], rb + (OVL - OVH));
                uint32_t b0l[2] = { bl4[0], bl4[1] }, b1l[2] = { bl4[2], bl4[3] };
#pragma unroll
                for (int t = 0; t < 2; t++) {
                    MMA_BF16(acc[t][2*g],   al[t], b0h);
                    MMA_BF16(acc[t][2*g+1], al[t], b1h);
                }
#pragma unroll
                for (int t = 0; t < 2; t++) {
                    MMA_BF16(acc[t][2*g],   ah[t], b0l);
                    MMA_BF16(acc[t][2*g+1], ah[t], b1l);
                }
            }
        }
    }

    if (tid < 128) atomicAdd(&g_ksum[bh * HD + tid], kacc);

    float* dst = g_kv2 + bh * HD * HD;
#pragma unroll
    for (int t = 0; t < 2; t++) {
        int c0 = warp_m * 32 + t * 16 + gid;
#pragma unroll
        for (int j = 0; j < 8; j++) {
            int d = warp_n * 64 + j * 8 + 2 * tig;
            atomicAdd(&dst[c0 * HD + d],           acc[t][j][0]);
            atomicAdd(&dst[c0 * HD + d + 1],       acc[t][j][1]);
            atomicAdd(&dst[(c0 + 8) * HD + d],     acc[t][j][2]);
            atomicAdd(&dst[(c0 + 8) * HD + d + 1], acc[t][j][3]);
        }
    }
}

// ---------------------------------------------------------------------------
// attn GEMM with fused z (K=128, 4 chunks); single-sync loop;
// epilogue conv-add + z + split
// ---------------------------------------------------------------------------
__global__ __launch_bounds__(256, 2) void attn_gemm() {
    extern __shared__ char smem[];
    const uint32_t sb = (uint32_t)__cvta_generic_to_shared(smem);
    const int bx = blockIdx.x;
    const int bh = bx >> 5;
    const int m0 = (bx & 31) * BMM;
    const int b = bh / NH, hoff = (bh % NH) * HD;
    const __nv_bfloat16* Ah = g_qbh + (size_t)b * SEQ * CH + hoff;
    const __nv_bfloat16* Al = g_qbl + (size_t)b * SEQ * CH + hoff;
    const __nv_bfloat16* Bh = g_k2h + (size_t)bh * HD * HD;
    const __nv_bfloat16* Bl = g_k2l + (size_t)bh * HD * HD;

    const int tid = threadIdx.x;
    const int lane = tid & 31;
    const int wid = tid >> 5;
    const int warp_m = wid >> 1;
    const int warp_n = wid & 1;
    const int gid = lane >> 2;
    const int tig = lane & 3;
    const int lr = (lane & 7) + ((lane >> 3) & 1) * 8;
    const uint32_t lc = (uint32_t)(((lane >> 4) & 1) * 16);

    float acc[2][8][4];
#pragma unroll
    for (int t = 0; t < 2; t++)
#pragma unroll
        for (int j = 0; j < 8; j++)
#pragma unroll
            for (int e = 0; e < 4; e++) acc[t][j][e] = 0.f;

    int r0f = tid >> 2, c0f = tid & 3;
    int r1f = (tid + 256) >> 2, c1f = (tid + 256) & 3;
    const uint32_t so0 = (uint32_t)(r0f * RWB + c0f * 16);
    const uint32_t so1 = (uint32_t)(r1f * RWB + c1f * 16);
    const size_t gA0 = (size_t)(m0 + r0f) * CH + c0f * 8;
    const size_t gA1 = (size_t)(m0 + r1f) * CH + c1f * 8;
    const size_t gB0 = (size_t)r0f * HD + c0f * 8;
    const size_t gB1 = (size_t)r1f * HD + c1f * 8;

    auto fill = [&](int stage, int chunk) {
        const int k0 = chunk * BKE;
        const uint32_t stb = sb + (uint32_t)(stage * STB);
        cp16(stb + OFFAH + so0, Ah + gA0 + k0);
        cp16(stb + OFFAL + so0, Al + gA0 + k0);
        cp16(stb + OFFBH + so0, Bh + gB0 + k0);
        cp16(stb + OFFBL + so0, Bl + gB0 + k0);
        cp16(stb + OFFAH + so1, Ah + gA1 + k0);
        cp16(stb + OFFAL + so1, Al + gA1 + k0);
        cp16(stb + OFFBH + so1, Bh + gB1 + k0);
        cp16(stb + OFFBL + so1, Bl + gB1 + k0);
        asm volatile("cp.async.commit_group;" ::: "memory");
    };

    const uint32_t raF = (uint32_t)((warp_m * 32 + lr) * RWB) + lc;
    const uint32_t rbF = (uint32_t)((warp_n * 64 + lr) * RWB) + lc;

    float zacc = 0.f;

    fill(0, 0);
#pragma unroll
    for (int i = 0; i < 4; i++) {
        asm volatile("cp.async.wait_group 0;" ::: "memory");
        __syncthreads();
        if (i + 1 < 4) fill((i + 1) & 1, i + 1);

        const uint32_t stb = sb + (uint32_t)((i & 1) * STB);

        if (tid < 128) {
            const uint32_t qh = stb + OFFAH + (uint32_t)(tid * RWB);
            const float* ksp = g_ksum + bh * HD + i * BKE;
#pragma unroll
            for (int cc = 0; cc < 32; cc += 2) {
                uint32_t hv, lv;
                asm("ld.shared.b32 %0, [%1];" : "=r"(hv) : "r"(qh + cc * 2));
                asm("ld.shared.b32 %0, [%1];" : "=r"(lv)
                    : "r"(qh + (OFFAL - OFFAH) + cc * 2));
                __nv_bfloat162 h2 = *reinterpret_cast<__nv_bfloat162*>(&hv);
                __nv_bfloat162 l2 = *reinterpret_cast<__nv_bfloat162*>(&lv);
                float q0 = __bfloat162float(h2.x) + __bfloat162float(l2.x);
                float q1 = __bfloat162float(h2.y) + __bfloat162float(l2.y);
                zacc += q0 * __ldg(ksp + cc) + q1 * __ldg(ksp + cc + 1);
            }
        }

#pragma unroll
        for (int ks = 0; ks < 2; ks++) {
            const uint32_t kofs = (uint32_t)(ks * 32);
            uint32_t ah[2][4], al[2][4];
#pragma unroll
            for (int t = 0; t < 2; t++) {
                uint32_t ra = stb + OFFAH + raF + (uint32_t)(t * 16 * RWB) + kofs;
                LDM4(ah[t][0], ah[t][1], ah[t][2], ah[t][3], ra);
                LDM4(al[t][0], al[t][1], al[t][2], al[t][3], ra + (OFFAL - OFFAH));
            }
#pragma unroll
            for (int g = 0; g < 4; g++) {
                uint32_t rb = stb + OFFBH + rbF + (uint32_t)(g * 16 * RWB) + kofs;
                uint32_t bh4[4], bl4[4];
                LDM4(bh4[0], bh4[1], bh4[2], bh4[3], rb);
                uint32_t b0h[2] = { bh4[0], bh4[2] }, b1h[2] = { bh4[1], bh4[3] };
#pragma unroll
                for (int t = 0; t < 2; t++) {
                    MMA_BF16(acc[t][2*g],   ah[t], b0h);
                    MMA_BF16(acc[t][2*g+1], ah[t], b1h);
                }
                LDM4(bl4[0], bl4[1], bl4[2], bl4[3], rb + (OFFBL - OFFBH));
                uint32_t b0l[2] = { bl4[0], bl4[2] }, b1l[2] = { bl4[1], bl4[3] };
#pragma unroll
                for (int t = 0; t < 2; t++) {
                    MMA_BF16(acc[t][2*g],   al[t], b0h);
                    MMA_BF16(acc[t][2*g+1], al[t], b1h);
                }
#pragma unroll
                for (int t = 0; t < 2; t++) {
                    MMA_BF16(acc[t][2*g],   ah[t], b0l);
                    MMA_BF16(acc[t][2*g+1], ah[t], b1l);
                }
            }
        }
    }

    __syncthreads();
    float* zs = reinterpret_cast<float*>(smem);
    if (tid < 128) zs[tid] = 1.f / (zacc + 1e-6f);
    __syncthreads();

#pragma unroll
    for (int t = 0; t < 2; t++) {
        int lr0 = warp_m * 32 + t * 16 + gid;
#pragma unroll
        for (int j = 0; j < 8; j++) {
            int d = warp_n * 64 + j * 8 + 2 * tig;
#pragma unroll
            for (int half = 0; half < 2; half++) {
                int lrow = lr0 + half * 8;
                int i = m0 + lrow;
                float zv = zs[lrow];
                size_t base = (size_t)(b * SEQ + i) * CH + hoff + d;
                float f0 = g_x[base]     + acc[t][j][half * 2]     * zv;
                float f1 = g_x[base + 1] + acc[t][j][half * 2 + 1] * zv;
                __nv_bfloat16 h0 = __float2bfloat16_rn(f0);
                __nv_bfloat16 h1 = __float2bfloat16_rn(f1);
                __nv_bfloat16 l0 = __float2bfloat16_rn(f0 - __bfloat162float(h0));
                __nv_bfloat16 l1 = __float2bfloat16_rn(f1 - __bfloat162float(h1));
                *reinterpret_cast<__nv_bfloat162*>(&g_abh[base]) = { h0, h1 };
                *reinterpret_cast<__nv_bfloat162*>(&g_abl[base]) = { l0, l1 };
            }
        }
    }
}

// ---------------------------------------------------------------------------
__global__ void softplus_kernel(const float* __restrict__ scale) {
    int c = blockIdx.x * 256 + threadIdx.x;
    if (c < CH) g_sc[c] = log1pf(expf(scale[c]));
}

// ---------------------------------------------------------------------------
__device__ __forceinline__ float warp_sum(float s) {
#pragma unroll
    for (int o = 16; o > 0; o >>= 1) s += __shfl_xor_sync(0xffffffffu, s, o);
    return s;
}

// qknorm: warp per row; q and k both -> bf16 hi/lo.
__global__ __launch_bounds__(256) void qknorm_kernel(const float* __restrict__ pos) {
    const int w = blockIdx.x * 8 + (threadIdx.x >> 5);
    const int lane = threadIdx.x & 31;
    const size_t row = (size_t)w;
    const int n = w & (SEQ - 1);
    const float* qrow = g_q + row * CH;
    const float* krow = g_k + row * CH;
    const float* prow = pos + (size_t)n * CH;

    float scv[20];
#pragma unroll
    for (int t = 0; t < 20; t++) scv[t] = g_sc[lane + 32 * t];

    {
        float v[20]; float s = 0.f;
#pragma unroll
        for (int t = 0; t < 20; t++) {
            float raw = qrow[lane + 32 * t];
            float val = (fmaxf(raw, 0.f) + 1e-6f) / scv[t];
            v[t] = val; s += val * val;
        }
        float n1 = sqrtf(warp_sum(s));
        s = 0.f;
#pragma unroll
        for (int t = 0; t < 20; t++) { float c3 = v[t]*v[t]*v[t]; v[t] = c3; s += c3*c3; }
        float sc2 = n1 / sqrtf(warp_sum(s));
#pragma unroll
        for (int t = 0; t < 20; t++) {
            float f = v[t] * sc2;
            __nv_bfloat16 h = __float2bfloat16_rn(f);
            __nv_bfloat16 l = __float2bfloat16_rn(f - __bfloat162float(h));
            g_qbh[row * CH + lane + 32 * t] = h;
            g_qbl[row * CH + lane + 32 * t] = l;
        }
    }
    {
        float v[20]; float s = 0.f;
#pragma unroll
        for (int t = 0; t < 20; t++) {
            float raw = krow[lane + 32 * t] + prow[lane + 32 * t];
            float val = (fmaxf(raw, 0.f) + 1e-6f) / scv[t];
            v[t] = val; s += val * val;
        }
        float n1 = sqrtf(warp_sum(s));
        s = 0.f;
#pragma unroll
        for (int t = 0; t < 20; t++) { float c3 = v[t]*v[t]*v[t]; v[t] = c3; s += c3*c3; }
        float sc2 = n1 / sqrtf(warp_sum(s));
#pragma unroll
        for (int t = 0; t < 20; t++) {
            float f = v[t] * sc2;
            __nv_bfloat16 h = __float2bfloat16_rn(f);
            __nv_bfloat16 l = __float2bfloat16_rn(f - __bfloat162float(h));
            g_kbh[row * CH + lane + 32 * t] = h;
            g_kbl[row * CH + lane + 32 * t] = l;
        }
    }
}

__global__ void zero_kernel() {
    int idx = blockIdx.x * 256 + threadIdx.x;
    if (idx < BH * HD * HD) g_kv2[idx] = 0.f;
    if (idx < BH * HD)      g_ksum[idx] = 0.f;
}

// kv2^T + bf16 split: [bh][c][d] fp32 -> [bh][d][c] hi/lo
__global__ __launch_bounds__(256) void kv2t_split() {
    const int bh = blockIdx.x;
    const int e = blockIdx.y * 256 + threadIdx.x;
    const int d = e >> 7, c = e & 127;
    float v = g_kv2[bh * HD * HD + c * HD + d];
    __nv_bfloat16 h = __float2bfloat16_rn(v);
    __nv_bfloat16 l = __float2bfloat16_rn(v - __bfloat162float(h));
    g_k2h[bh * HD * HD + d * HD + c] = h;
    g_k2l[bh * HD * HD + d * HD + c] = l;
}

// ---------------------------------------------------------------------------
// depthwise conv reading v hi/lo splits
// ---------------------------------------------------------------------------
__global__ __launch_bounds__(256) void conv_s(
    const float* __restrict__ w, const float* __restrict__ bias)
{
    extern __shared__ float sv[];   // [8][68][32]
    const int bh = blockIdx.x, yt = blockIdx.y, dc = blockIdx.z;
    const int b = bh / NH, hoff = (bh % NH) * HD;
    const int tid = threadIdx.x;
    const int d = tid & 31;
    const int xg = tid >> 5;
    const __nv_bfloat16* vh = g_vbh + (size_t)b * SEQ * CH + hoff + dc * 32;
    const __nv_bfloat16* vl = g_vbl + (size_t)b * SEQ * CH + hoff + dc * 32;

    {
        int p = tid;
        int r = p >> 5, rest = p & 31;
        int xi = rest >> 3, d4 = rest & 7;
        int ix = (xi < 2) ? xi : (xi + 64);
        *reinterpret_cast<float4*>(&sv[(r * 68 + ix) * 32 + d4 * 4]) =
            make_float4(0.f, 0.f, 0.f, 0.f);
    }
    for (int p = tid; p < 2048; p += 256) {
        int r = p >> 8, rest = p & 255;
        int x = rest >> 2, d8 = rest & 3;
        int y = yt * 4 - 2 + r;
        float f[8];
        if ((unsigned)y < 64u) {
            uint4 hv = *reinterpret_cast<const uint4*>(
                &vh[(size_t)(y * 64 + x) * CH + d8 * 8]);
            uint4 lv = *reinterpret_cast<const uint4*>(
                &vl[(size_t)(y * 64 + x) * CH + d8 * 8]);
            const __nv_bfloat162* h2 = reinterpret_cast<const __nv_bfloat162*>(&hv);
            const __nv_bfloat162* l2 = reinterpret_cast<const __nv_bfloat162*>(&lv);
#pragma unroll
            for (int j = 0; j < 4; j++) {
                f[2*j]   = __bfloat162float(h2[j].x) + __bfloat162float(l2[j].x);
                f[2*j+1] = __bfloat162float(h2[j].y) + __bfloat162float(l2[j].y);
            }
        } else {
#pragma unroll
            for (int j = 0; j < 8; j++) f[j] = 0.f;
        }
        float* dst = &sv[(r * 68 + x + 2) * 32 + d8 * 8];
        *reinterpret_cast<float4*>(dst)     = make_float4(f[0], f[1], f[2], f[3]);
        *reinterpret_cast<float4*>(dst + 4) = make_float4(f[4], f[5], f[6], f[7]);
    }
    __syncthreads();

    float wr[25];
#pragma unroll
    for (int k = 0; k < 25; k++) wr[k] = __ldg(&w[(dc * 32 + d) * 25 + k]);
    const float bv = __ldg(&bias[dc * 32 + d]);

#pragma unroll
    for (int y = 0; y < 4; y++) {
#pragma unroll
        for (int xo = 0; xo < 8; xo++) {
            int x = xg * 8 + xo;
            float acc = bv;
#pragma unroll
            for (int ky = 0; ky < 5; ky++)
#pragma unroll
                for (int kx = 0; kx < 5; kx++)
                    acc += wr[ky * 5 + kx] * sv[((y + ky) * 68 + (x + kx)) * 32 + d];
            int oy = yt * 4 + y;
            g_x[(size_t)(b * SEQ + oy * 64 + x) * CH + hoff + dc * 32 + d] = acc;
        }
    }
}

// ---------------------------------------------------------------------------
extern "C" void kernel_launch(void* const* d_in, const int* in_sizes, int n_in,
                              void* d_out, int out_size)
{
    const float* x1    = (const float*)d_in[0];
    const float* x2    = (const float*)d_in[1];
    const float* Wq    = (const float*)d_in[2];
    const float* Wkv   = (const float*)d_in[3];
    const float* Wproj = (const float*)d_in[4];
    const float* bproj = (const float*)d_in[5];
    const float* dwc_w = (const float*)d_in[6];
    const float* dwc_b = (const float*)d_in[7];
    const float* scale = (const float*)d_in[8];
    const float* pos   = (const float*)d_in[9];
    float* out = (float*)d_out;

    __nv_bfloat16 *pah, *pal, *pa2h, *pa2l;
    cudaGetSymbolAddress((void**)&pah, g_abh);
    cudaGetSymbolAddress((void**)&pal, g_abl);
    cudaGetSymbolAddress((void**)&pa2h, g_a2h);
    cudaGetSymbolAddress((void**)&pa2l, g_a2l);

    cudaFuncSetAttribute(gemm_merged,
        cudaFuncAttributeMaxDynamicSharedMemorySize, SMEM_GB);
    cudaFuncSetAttribute(gemm_proj,
        cudaFuncAttributeMaxDynamicSharedMemorySize, SMEM_GB);
    cudaFuncSetAttribute(attn_gemm,
        cudaFuncAttributeMaxDynamicSharedMemorySize, SMEM_GB);
    cudaFuncSetAttribute(kv2_mma,
        cudaFuncAttributeMaxDynamicSharedMemorySize, SMEM_KV2);
    cudaFuncSetAttribute(conv_s,
        cudaFuncAttributeMaxDynamicSharedMemorySize, 8 * 68 * 32 * 4);

    const int M = BATCH * SEQ;              // 32768
    const int XN4 = M * CH / 4;

    split_w<<<4 * CC / 1024, 256>>>(Wq, Wkv, Wproj);                  // 0
    softplus_kernel<<<3, 256>>>(scale);                               // 1
    split_x<<<XN4 / 256, 256>>>(x1, pah, pal, XN4);                   // 2
    split_x<<<XN4 / 256, 256>>>(x2, pa2h, pa2l, XN4);                 // 3
    gemm_merged<<<dim3(15, M / BMM), 256, SMEM_GB>>>();               // 4: v+k+q

    qknorm_kernel<<<M / 8, 256>>>(pos);
    zero_kernel<<<(BH * HD * HD + 255) / 256, 256>>>();
    kv2_mma<<<dim3(BH, 8), 256, SMEM_KV2>>>();   // tensor-pipe kv2 + ksum
    kv2t_split<<<dim3(BH, 64), 256>>>();
    conv_s<<<dim3(BH, 16, 4), 256, 8 * 68 * 32 * 4>>>(dwc_w, dwc_b);
    attn_gemm<<<BH * 32, 256, SMEM_GB>>>();      // + fused z

    gemm_proj<<<dim3(5, M / BMM), 256, SMEM_GB>>>(out, bproj);
}

// round 15
// speedup vs baseline: 1.8589x; 1.0025x over previous
#include <cuda_runtime.h>
#include <cuda_bf16.h>
#include <cstdint>
#include <cstddef>

// ---------------------------------------------------------------------------
// FocusedLinearAttention — round 15:
//   conv_s forked onto a side stream (overlaps qknorm/kv2_mma chain);
//   split_x1+x2 merged into one launch; zero_kernel hoisted before gemm.
// ---------------------------------------------------------------------------

#define BATCH 8
#define SEQ   4096
#define CH    640
#define CC    (CH*CH)
#define NH    5
#define HD    128
#define BH    (BATCH*NH)   // 40

#define BMM 128
#define BNN 128
#define BKE 32
#define NCHB (CH/BKE)           // 20
#define RWB 80
#define BUFB (128*RWB)
#define OFFAH 0
#define OFFAL BUFB
#define OFFBH (2*BUFB)
#define OFFBL (3*BUFB)
#define STB   (4*BUFB)          // 40960 B
#define SMEM_GB (2*STB)         // 81920 B -> 2 CTAs/SM

#define T2RW 272
#define T2BUF (32*T2RW)
#define OKH 0
#define OKL T2BUF
#define OVH (2*T2BUF)
#define OVL (3*T2BUF)
#define T2ST (4*T2BUF)          // 34816
#define SMEM_KV2 (2*T2ST)       // 69632

__device__ float g_q[BATCH*SEQ*CH];
__device__ float g_k[BATCH*SEQ*CH];
__device__ float g_x[BATCH*SEQ*CH];
__device__ __nv_bfloat16 g_abh[BATCH*SEQ*CH];
__device__ __nv_bfloat16 g_abl[BATCH*SEQ*CH];
__device__ __nv_bfloat16 g_a2h[BATCH*SEQ*CH];
__device__ __nv_bfloat16 g_a2l[BATCH*SEQ*CH];
__device__ __nv_bfloat16 g_qbh[BATCH*SEQ*CH];
__device__ __nv_bfloat16 g_qbl[BATCH*SEQ*CH];
__device__ __nv_bfloat16 g_kbh[BATCH*SEQ*CH];
__device__ __nv_bfloat16 g_kbl[BATCH*SEQ*CH];
__device__ __nv_bfloat16 g_vbh[BATCH*SEQ*CH];
__device__ __nv_bfloat16 g_vbl[BATCH*SEQ*CH];
__device__ __nv_bfloat16 g_wbh[4*CC];
__device__ __nv_bfloat16 g_wbl[4*CC];
__device__ __nv_bfloat16 g_k2h[BH*HD*HD];
__device__ __nv_bfloat16 g_k2l[BH*HD*HD];
__device__ float g_kv2[BH*HD*HD];
__device__ float g_ksum[BH*HD];
__device__ float g_sc[CH];

// ---------------------------------------------------------------------------
__device__ __forceinline__ void cp16(uint32_t dst, const void* src) {
    asm volatile("cp.async.cg.shared.global [%0], [%1], 16;" :: "r"(dst), "l"(src));
}

#define LDM4(r0, r1, r2, r3, a) \
    asm volatile("ldmatrix.sync.aligned.m8n8.x4.shared.b16 {%0,%1,%2,%3}, [%4];" \
        : "=r"(r0), "=r"(r1), "=r"(r2), "=r"(r3) : "r"(a))

#define LDM4T(r0, r1, r2, r3, a) \
    asm volatile("ldmatrix.sync.aligned.m8n8.x4.trans.shared.b16 {%0,%1,%2,%3}, [%4];" \
        : "=r"(r0), "=r"(r1), "=r"(r2), "=r"(r3) : "r"(a))

#define MMA_BF16(d, a, b) \
    asm volatile( \
        "mma.sync.aligned.m16n8k16.row.col.f32.bf16.bf16.f32 " \
        "{%0,%1,%2,%3}, {%4,%5,%6,%7}, {%8,%9}, {%0,%1,%2,%3};" \
        : "+f"((d)[0]), "+f"((d)[1]), "+f"((d)[2]), "+f"((d)[3]) \
        : "r"((a)[0]), "r"((a)[1]), "r"((a)[2]), "r"((a)[3]), \
          "r"((b)[0]), "r"((b)[1]))

// ---------------------------------------------------------------------------
__device__ __forceinline__ void split4(float4 v, __nv_bfloat16* hp, __nv_bfloat16* lp) {
    float f[4] = { v.x, v.y, v.z, v.w };
    __nv_bfloat16 h[4], l[4];
#pragma unroll
    for (int j = 0; j < 4; j++) {
        h[j] = __float2bfloat16_rn(f[j]);
        l[j] = __float2bfloat16_rn(f[j] - __bfloat162float(h[j]));
    }
    *reinterpret_cast<__nv_bfloat162*>(hp)     = { h[0], h[1] };
    *reinterpret_cast<__nv_bfloat162*>(hp + 2) = { h[2], h[3] };
    *reinterpret_cast<__nv_bfloat162*>(lp)     = { l[0], l[1] };
    *reinterpret_cast<__nv_bfloat162*>(lp + 2) = { l[2], l[3] };
}

// merged x1+x2 split: blocks [0, nb) -> x1, [nb, 2nb) -> x2
__global__ __launch_bounds__(256) void split_x12(
    const float* __restrict__ x1, const float* __restrict__ x2, int n4)
{
    int nb = gridDim.x >> 1;
    const float* src; __nv_bfloat16 *hi, *lo;
    int bi = blockIdx.x;
    if (bi < nb) { src = x1; hi = g_abh; lo = g_abl; }
    else         { src = x2; hi = g_a2h; lo = g_a2l; bi -= nb; }
    int i = bi * 256 + threadIdx.x;
    if (i >= n4) return;
    split4(reinterpret_cast<const float4*>(src)[i], hi + 4 * i, lo + 4 * i);
}

__global__ __launch_bounds__(256) void split_w(
    const float* __restrict__ Wq, const float* __restrict__ Wkv,
    const float* __restrict__ Wproj)
{
    int i = blockIdx.x * 256 + threadIdx.x;
    int fi = i * 4;
    const float* src; int off;
    if (fi < CC)          { src = Wq;    off = 0; }
    else if (fi < 3 * CC) { src = Wkv;   off = CC; }
    else                  { src = Wproj; off = 3 * CC; }
    float4 v = *reinterpret_cast<const float4*>(&src[fi - off]);
    split4(v, g_wbh + fi, g_wbl + fi);
}

// ---------------------------------------------------------------------------
// common bf16x3 GEMM core (K = 640); single-sync pipelined mainloop
// ---------------------------------------------------------------------------
__device__ __forceinline__ void gemm_core(
    const __nv_bfloat16* __restrict__ Ah, const __nv_bfloat16* __restrict__ Al,
    const __nv_bfloat16* __restrict__ Bh, const __nv_bfloat16* __restrict__ Bl,
    float* __restrict__ Cout, const float* __restrict__ bias,
    __nv_bfloat16* __restrict__ Hsp, __nv_bfloat16* __restrict__ Lsp,
    int m0, int nb0, int n0, uint32_t sb)
{
    const int tid = threadIdx.x;
    const int lane = tid & 31;
    const int wid = tid >> 5;
    const int warp_m = wid >> 1;
    const int warp_n = wid & 1;
    const int gid = lane >> 2;
    const int tig = lane & 3;
    const int lr = (lane & 7) + ((lane >> 3) & 1) * 8;
    const uint32_t lc = (uint32_t)(((lane >> 4) & 1) * 16);

    float acc[2][8][4];
#pragma unroll
    for (int t = 0; t < 2; t++)
#pragma unroll
        for (int j = 0; j < 8; j++)
#pragma unroll
            for (int e = 0; e < 4; e++) acc[t][j][e] = 0.f;

    int r0f = tid >> 2, c0f = tid & 3;
    int r1f = (tid + 256) >> 2, c1f = (tid + 256) & 3;
    const uint32_t so0 = (uint32_t)(r0f * RWB + c0f * 16);
    const uint32_t so1 = (uint32_t)(r1f * RWB + c1f * 16);
    const size_t gA0 = (size_t)(m0 + r0f) * CH + c0f * 8;
    const size_t gA1 = (size_t)(m0 + r1f) * CH + c1f * 8;
    const size_t gB0 = (size_t)(nb0 + r0f) * CH + c0f * 8;
    const size_t gB1 = (size_t)(nb0 + r1f) * CH + c1f * 8;

    auto fill = [&](int stage, int chunk) {
        const int k0 = chunk * BKE;
        const uint32_t stb = sb + (uint32_t)(stage * STB);
        cp16(stb + OFFAH + so0, Ah + gA0 + k0);
        cp16(stb + OFFAL + so0, Al + gA0 + k0);
        cp16(stb + OFFBH + so0, Bh + gB0 + k0);
        cp16(stb + OFFBL + so0, Bl + gB0 + k0);
        cp16(stb + OFFAH + so1, Ah + gA1 + k0);
        cp16(stb + OFFAL + so1, Al + gA1 + k0);
        cp16(stb + OFFBH + so1, Bh + gB1 + k0);
        cp16(stb + OFFBL + so1, Bl + gB1 + k0);
        asm volatile("cp.async.commit_group;" ::: "memory");
    };

    const uint32_t raF = (uint32_t)((warp_m * 32 + lr) * RWB) + lc;
    const uint32_t rbF = (uint32_t)((warp_n * 64 + lr) * RWB) + lc;

    fill(0, 0);
    for (int i = 0; i < NCHB; i++) {
        asm volatile("cp.async.wait_group 0;" ::: "memory");
        __syncthreads();
        if (i + 1 < NCHB) fill((i + 1) & 1, i + 1);

        const uint32_t stb = sb + (uint32_t)((i & 1) * STB);
#pragma unroll
        for (int ks = 0; ks < 2; ks++) {
            const uint32_t kofs = (uint32_t)(ks * 32);
            uint32_t ah[2][4], al[2][4];
#pragma unroll
            for (int t = 0; t < 2; t++) {
                uint32_t ra = stb + OFFAH + raF + (uint32_t)(t * 16 * RWB) + kofs;
                LDM4(ah[t][0], ah[t][1], ah[t][2], ah[t][3], ra);
                LDM4(al[t][0], al[t][1], al[t][2], al[t][3], ra + (OFFAL - OFFAH));
            }
#pragma unroll
            for (int g = 0; g < 4; g++) {
                uint32_t rb = stb + OFFBH + rbF + (uint32_t)(g * 16 * RWB) + kofs;
                uint32_t bh4[4], bl4[4];
                LDM4(bh4[0], bh4[1], bh4[2], bh4[3], rb);
                uint32_t b0h[2] = { bh4[0], bh4[2] }, b1h[2] = { bh4[1], bh4[3] };
#pragma unroll
                for (int t = 0; t < 2; t++) {
                    MMA_BF16(acc[t][2*g],   ah[t], b0h);
                    MMA_BF16(acc[t][2*g+1], ah[t], b1h);
                }
                LDM4(bl4[0], bl4[1], bl4[2], bl4[3], rb + (OFFBL - OFFBH));
                uint32_t b0l[2] = { bl4[0], bl4[2] }, b1l[2] = { bl4[1], bl4[3] };
#pragma unroll
                for (int t = 0; t < 2; t++) {
                    MMA_BF16(acc[t][2*g],   al[t], b0h);
                    MMA_BF16(acc[t][2*g+1], al[t], b1h);
                }
#pragma unroll
                for (int t = 0; t < 2; t++) {
                    MMA_BF16(acc[t][2*g],   ah[t], b0l);
                    MMA_BF16(acc[t][2*g+1], ah[t], b1l);
                }
            }
        }
    }

#pragma unroll
    for (int t = 0; t < 2; t++) {
        int r0 = m0 + warp_m * 32 + t * 16 + gid;
#pragma unroll
        for (int j = 0; j < 8; j++) {
            int cc = n0 + warp_n * 64 + j * 8 + 2 * tig;
            float b0 = bias ? bias[cc] : 0.f;
            float b1 = bias ? bias[cc + 1] : 0.f;
            float f00 = acc[t][j][0] + b0, f01 = acc[t][j][1] + b1;
            float f10 = acc[t][j][2] + b0, f11 = acc[t][j][3] + b1;
            if (Cout) {
                *reinterpret_cast<float2*>(&Cout[(size_t)r0 * CH + cc]) =
                    make_float2(f00, f01);
                *reinterpret_cast<float2*>(&Cout[(size_t)(r0 + 8) * CH + cc]) =
                    make_float2(f10, f11);
            }
            if (Hsp) {
                __nv_bfloat16 h0 = __float2bfloat16_rn(f00);
                __nv_bfloat16 h1 = __float2bfloat16_rn(f01);
                __nv_bfloat16 h2 = __float2bfloat16_rn(f10);
                __nv_bfloat16 h3 = __float2bfloat16_rn(f11);
                __nv_bfloat16 l0 = __float2bfloat16_rn(f00 - __bfloat162float(h0));
                __nv_bfloat16 l1 = __float2bfloat16_rn(f01 - __bfloat162float(h1));
                __nv_bfloat16 l2 = __float2bfloat16_rn(f10 - __bfloat162float(h2));
                __nv_bfloat16 l3 = __float2bfloat16_rn(f11 - __bfloat162float(h3));
                *reinterpret_cast<__nv_bfloat162*>(&Hsp[(size_t)r0 * CH + cc]) = { h0, h1 };
                *reinterpret_cast<__nv_bfloat162*>(&Hsp[(size_t)(r0 + 8) * CH + cc]) = { h2, h3 };
                *reinterpret_cast<__nv_bfloat162*>(&Lsp[(size_t)r0 * CH + cc]) = { l0, l1 };
                *reinterpret_cast<__nv_bfloat162*>(&Lsp[(size_t)(r0 + 8) * CH + cc]) = { l2, l3 };
            }
        }
    }
}

// merged v + kq GEMM: grid (15, 256); v -> split-only output
__global__ __launch_bounds__(256, 2) void gemm_merged() {
    extern __shared__ char smem[];
    const uint32_t sb = (uint32_t)__cvta_generic_to_shared(smem);
    const int m0 = blockIdx.y * BMM;
    const int bx = blockIdx.x;
    if (bx < 5) {
        gemm_core(g_a2h, g_a2l, g_wbh, g_wbl, nullptr, nullptr,
                  g_vbh, g_vbl, m0, bx * BNN, bx * BNN, sb);
    } else {
        int nb0 = (bx - 5) * BNN;
        if (nb0 < CH)
            gemm_core(g_abh, g_abl, g_wbh + CC, g_wbl + CC, g_k, nullptr,
                      nullptr, nullptr, m0, nb0, nb0, sb);
        else
            gemm_core(g_abh, g_abl, g_wbh + CC, g_wbl + CC, g_q, nullptr,
                      nullptr, nullptr, m0, nb0, nb0 - CH, sb);
    }
}

// proj GEMM: grid (5, 256)
__global__ __launch_bounds__(256, 2) void gemm_proj(
    float* __restrict__ out, const float* __restrict__ bias)
{
    extern __shared__ char smem[];
    const uint32_t sb = (uint32_t)__cvta_generic_to_shared(smem);
    gemm_core(g_abh, g_abl, g_wbh + 3 * CC, g_wbl + 3 * CC, out, bias,
              nullptr, nullptr,
              blockIdx.y * BMM, blockIdx.x * BNN, blockIdx.x * BNN, sb);
}

// ---------------------------------------------------------------------------
// kv2 on tensor pipe (bf16x3, ldmatrix.trans) + fused ksum; single-sync loop
// ---------------------------------------------------------------------------
__global__ __launch_bounds__(256, 2) void kv2_mma() {
    extern __shared__ char smem[];
    const uint32_t sb = (uint32_t)__cvta_generic_to_shared(smem);
    const int bh = blockIdx.x, jc = blockIdx.y;
    const int b = bh / NH, hoff = (bh % NH) * HD;
    const __nv_bfloat16* Kh = g_kbh + (size_t)b * SEQ * CH + hoff;
    const __nv_bfloat16* Kl = g_kbl + (size_t)b * SEQ * CH + hoff;
    const __nv_bfloat16* Vh = g_vbh + (size_t)b * SEQ * CH + hoff;
    const __nv_bfloat16* Vl = g_vbl + (size_t)b * SEQ * CH + hoff;

    const int tid = threadIdx.x;
    const int lane = tid & 31;
    const int wid = tid >> 5;
    const int warp_m = wid >> 1;
    const int warp_n = wid & 1;
    const int gid = lane >> 2;
    const int tig = lane & 3;
    const int grp = lane >> 3;
    const int l8 = lane & 7;

    float acc[2][8][4];
#pragma unroll
    for (int t = 0; t < 2; t++)
#pragma unroll
        for (int j = 0; j < 8; j++)
#pragma unroll
            for (int e = 0; e < 4; e++) acc[t][j][e] = 0.f;

    float kacc = 0.f;

    auto fill = [&](int stage, int it) {
        const int j0 = jc * 512 + it * 32;
        const uint32_t stb = sb + (uint32_t)(stage * T2ST);
#pragma unroll
        for (int t = 0; t < 2; t++) {
            int u = tid + t * 256;
            int row = u >> 4, col = u & 15;
            uint32_t off = (uint32_t)(row * T2RW + col * 16);
            size_t g = (size_t)(j0 + row) * CH + col * 8;
            cp16(stb + OKH + off, Kh + g);
            cp16(stb + OKL + off, Kl + g);
            cp16(stb + OVH + off, Vh + g);
            cp16(stb + OVL + off, Vl + g);
        }
        asm volatile("cp.async.commit_group;" ::: "memory");
    };

    fill(0, 0);
    for (int it = 0; it < 16; it++) {
        asm volatile("cp.async.wait_group 0;" ::: "memory");
        __syncthreads();
        if (it + 1 < 16) fill((it + 1) & 1, it + 1);

        const uint32_t stb = sb + (uint32_t)((it & 1) * T2ST);

        if (tid < 128) {
            const __nv_bfloat16* KhS = reinterpret_cast<const __nv_bfloat16*>(
                smem + (it & 1) * T2ST + OKH);
            const __nv_bfloat16* KlS = reinterpret_cast<const __nv_bfloat16*>(
                smem + (it & 1) * T2ST + OKL);
#pragma unroll
            for (int j = 0; j < 32; j++)
                kacc += __bfloat162float(KhS[j * (T2RW / 2) + tid]) +
                        __bfloat162float(KlS[j * (T2RW / 2) + tid]);
        }

#pragma unroll
        for (int ks = 0; ks < 2; ks++) {
            const uint32_t aj = (uint32_t)(ks * 16 + ((grp >> 1) & 1) * 8 + l8);
            uint32_t ah[2][4], al[2][4];
#pragma unroll
            for (int t = 0; t < 2; t++) {
                uint32_t ac = (uint32_t)(warp_m * 32 + t * 16 + (grp & 1) * 8);
                uint32_t ra = stb + OKH + aj * T2RW + ac * 2;
                LDM4T(ah[t][0], ah[t][1], ah[t][2], ah[t][3], ra);
                LDM4T(al[t][0], al[t][1], al[t][2], al[t][3], ra + (OKL - OKH));
            }
            const uint32_t bj = (uint32_t)(ks * 16 + (grp & 1) * 8 + l8);
#pragma unroll
            for (int g = 0; g < 4; g++) {
                uint32_t bd = (uint32_t)(warp_n * 64 + g * 16 + ((grp >> 1) & 1) * 8);
                uint32_t rb = stb + OVH + bj * T2RW + bd * 2;
                uint32_t bh4[4], bl4[4];
                LDM4T(bh4[0], bh4[1], bh4[2], bh4[3], rb);
                uint32_t b0h[2] = { bh4[0], bh4[1] }, b1h[2] = { bh4[2], bh4[3] };
#pragma unroll
                for (int t = 0; t < 2; t++) {
                    MMA_BF16(acc[t][2*g],   ah[t], b0h);
                    MMA_BF16(acc[t][2*g+1], ah[t], b1h);
                }
                LDM4T(bl4[0], bl4[1], bl4[2], bl4[3], rb + (OVL - OVH));
                uint32_t b0l[2] = { bl4[0], bl4[1] }, b1l[2] = { bl4[2], bl4[3] };
#pragma unroll
                for (int t = 0; t < 2; t++) {
                    MMA_BF16(acc[t][2*g],   al[t], b0h);
                    MMA_BF16(acc[t][2*g+1], al[t], b1h);
                }
#pragma unroll
                for (int t = 0; t < 2; t++) {
                    MMA_BF16(acc[t][2*g],   ah[t], b0l);
                    MMA_BF16(acc[t][2*g+1], ah[t], b1l);
                }
            }
        }
    }

    if (tid < 128) atomicAdd(&g_ksum[bh * HD + tid], kacc);

    float* dst = g_kv2 + bh * HD * HD;
#pragma unroll
    for (int t = 0; t < 2; t++) {
        int c0 = warp_m * 32 + t * 16 + gid;
#pragma unroll
        for (int j = 0; j < 8; j++) {
            int d = warp_n * 64 + j * 8 + 2 * tig;
            atomicAdd(&dst[c0 * HD + d],           acc[t][j][0]);
            atomicAdd(&dst[c0 * HD + d + 1],       acc[t][j][1]);
            atomicAdd(&dst[(c0 + 8) * HD + d],     acc[t][j][2]);
            atomicAdd(&dst[(c0 + 8) * HD + d + 1], acc[t][j][3]);
        }
    }
}

// ---------------------------------------------------------------------------
// attn GEMM with fused z (K=128, 4 chunks); single-sync loop
// ---------------------------------------------------------------------------
__global__ __launch_bounds__(256, 2) void attn_gemm() {
    extern __shared__ char smem[];
    const uint32_t sb = (uint32_t)__cvta_generic_to_shared(smem);
    const int bx = blockIdx.x;
    const int bh = bx >> 5;
    const int m0 = (bx & 31) * BMM;
    const int b = bh / NH, hoff = (bh % NH) * HD;
    const __nv_bfloat16* Ah = g_qbh + (size_t)b * SEQ * CH + hoff;
    const __nv_bfloat16* Al = g_qbl + (size_t)b * SEQ * CH + hoff;
    const __nv_bfloat16* Bh = g_k2h + (size_t)bh * HD * HD;
    const __nv_bfloat16* Bl = g_k2l + (size_t)bh * HD * HD;

    const int tid = threadIdx.x;
    const int lane = tid & 31;
    const int wid = tid >> 5;
    const int warp_m = wid >> 1;
    const int warp_n = wid & 1;
    const int gid = lane >> 2;
    const int tig = lane & 3;
    const int lr = (lane & 7) + ((lane >> 3) & 1) * 8;
    const uint32_t lc = (uint32_t)(((lane >> 4) & 1) * 16);

    float acc[2][8][4];
#pragma unroll
    for (int t = 0; t < 2; t++)
#pragma unroll
        for (int j = 0; j < 8; j++)
#pragma unroll
            for (int e = 0; e < 4; e++) acc[t][j][e] = 0.f;

    int r0f = tid >> 2, c0f = tid & 3;
    int r1f = (tid + 256) >> 2, c1f = (tid + 256) & 3;
    const uint32_t so0 = (uint32_t)(r0f * RWB + c0f * 16);
    const uint32_t so1 = (uint32_t)(r1f * RWB + c1f * 16);
    const size_t gA0 = (size_t)(m0 + r0f) * CH + c0f * 8;
    const size_t gA1 = (size_t)(m0 + r1f) * CH + c1f * 8;
    const size_t gB0 = (size_t)r0f * HD + c0f * 8;
    const size_t gB1 = (size_t)r1f * HD + c1f * 8;

    auto fill = [&](int stage, int chunk) {
        const int k0 = chunk * BKE;
        const uint32_t stb = sb + (uint32_t)(stage * STB);
        cp16(stb + OFFAH + so0, Ah + gA0 + k0);
        cp16(stb + OFFAL + so0, Al + gA0 + k0);
        cp16(stb + OFFBH + so0, Bh + gB0 + k0);
        cp16(stb + OFFBL + so0, Bl + gB0 + k0);
        cp16(stb + OFFAH + so1, Ah + gA1 + k0);
        cp16(stb + OFFAL + so1, Al + gA1 + k0);
        cp16(stb + OFFBH + so1, Bh + gB1 + k0);
        cp16(stb + OFFBL + so1, Bl + gB1 + k0);
        asm volatile("cp.async.commit_group;" ::: "memory");
    };

    const uint32_t raF = (uint32_t)((warp_m * 32 + lr) * RWB) + lc;
    const uint32_t rbF = (uint32_t)((warp_n * 64 + lr) * RWB) + lc;

    float zacc = 0.f;

    fill(0, 0);
#pragma unroll
    for (int i = 0; i < 4; i++) {
        asm volatile("cp.async.wait_group 0;" ::: "memory");
        __syncthreads();
        if (i + 1 < 4) fill((i + 1) & 1, i + 1);

        const uint32_t stb = sb + (uint32_t)((i & 1) * STB);

        if (tid < 128) {
            const uint32_t qh = stb + OFFAH + (uint32_t)(tid * RWB);
            const float* ksp = g_ksum + bh * HD + i * BKE;
#pragma unroll
            for (int cc = 0; cc < 32; cc += 2) {
                uint32_t hv, lv;
                asm("ld.shared.b32 %0, [%1];" : "=r"(hv) : "r"(qh + cc * 2));
                asm("ld.shared.b32 %0, [%1];" : "=r"(lv)
                    : "r"(qh + (OFFAL - OFFAH) + cc * 2));
                __nv_bfloat162 h2 = *reinterpret_cast<__nv_bfloat162*>(&hv);
                __nv_bfloat162 l2 = *reinterpret_cast<__nv_bfloat162*>(&lv);
                float q0 = __bfloat162float(h2.x) + __bfloat162float(l2.x);
                float q1 = __bfloat162float(h2.y) + __bfloat162float(l2.y);
                zacc += q0 * __ldg(ksp + cc) + q1 * __ldg(ksp + cc + 1);
            }
        }

#pragma unroll
        for (int ks = 0; ks < 2; ks++) {
            const uint32_t kofs = (uint32_t)(ks * 32);
            uint32_t ah[2][4], al[2][4];
#pragma unroll
            for (int t = 0; t < 2; t++) {
                uint32_t ra = stb + OFFAH + raF + (uint32_t)(t * 16 * RWB) + kofs;
                LDM4(ah[t][0], ah[t][1], ah[t][2], ah[t][3], ra);
                LDM4(al[t][0], al[t][1], al[t][2], al[t][3], ra + (OFFAL - OFFAH));
            }
#pragma unroll
            for (int g = 0; g < 4; g++) {
                uint32_t rb = stb + OFFBH + rbF + (uint32_t)(g * 16 * RWB) + kofs;
                uint32_t bh4[4], bl4[4];
                LDM4(bh4[0], bh4[1], bh4[2], bh4[3], rb);
                uint32_t b0h[2] = { bh4[0], bh4[2] }, b1h[2] = { bh4[1], bh4[3] };
#pragma unroll
                for (int t = 0; t < 2; t++) {
                    MMA_BF16(acc[t][2*g],   ah[t], b0h);
                    MMA_BF16(acc[t][2*g+1], ah[t], b1h);
                }
                LDM4(bl4[0], bl4[1], bl4[2], bl4[3], rb + (OFFBL - OFFBH));
                uint32_t b0l[2] = { bl4[0], bl4[2] }, b1l[2] = { bl4[1], bl4[3] };
#pragma unroll
                for (int t = 0; t < 2; t++) {
                    MMA_BF16(acc[t][2*g],   al[t], b0h);
                    MMA_BF16(acc[t][2*g+1], al[t], b1h);
                }
#pragma unroll
                for (int t = 0; t < 2; t++) {
                    MMA_BF16(acc[t][2*g],   ah[t], b0l);
                    MMA_BF16(acc[t][2*g+1], ah[t], b1l);
                }
            }
        }
    }

    __syncthreads();
    float* zs = reinterpret_cast<float*>(smem);
    if (tid < 128) zs[tid] = 1.f / (zacc + 1e-6f);
    __syncthreads();

#pragma unroll
    for (int t = 0; t < 2; t++) {
        int lr0 = warp_m * 32 + t * 16 + gid;
#pragma unroll
        for (int j = 0; j < 8; j++) {
            int d = warp_n * 64 + j * 8 + 2 * tig;
#pragma unroll
            for (int half = 0; half < 2; half++) {
                int lrow = lr0 + half * 8;
                int i = m0 + lrow;
                float zv = zs[lrow];
                size_t base = (size_t)(b * SEQ + i) * CH + hoff + d;
                float f0 = g_x[base]     + acc[t][j][half * 2]     * zv;
                float f1 = g_x[base + 1] + acc[t][j][half * 2 + 1] * zv;
                __nv_bfloat16 h0 = __float2bfloat16_rn(f0);
                __nv_bfloat16 h1 = __float2bfloat16_rn(f1);
                __nv_bfloat16 l0 = __float2bfloat16_rn(f0 - __bfloat162float(h0));
                __nv_bfloat16 l1 = __float2bfloat16_rn(f1 - __bfloat162float(h1));
                *reinterpret_cast<__nv_bfloat162*>(&g_abh[base]) = { h0, h1 };
                *reinterpret_cast<__nv_bfloat162*>(&g_abl[base]) = { l0, l1 };
            }
        }
    }
}

// ---------------------------------------------------------------------------
__global__ void softplus_kernel(const float* __restrict__ scale) {
    int c = blockIdx.x * 256 + threadIdx.x;
    if (c < CH) g_sc[c] = log1pf(expf(scale[c]));
}

// ---------------------------------------------------------------------------
__device__ __forceinline__ float warp_sum(float s) {
#pragma unroll
    for (int o = 16; o > 0; o >>= 1) s += __shfl_xor_sync(0xffffffffu, s, o);
    return s;
}

// qknorm: warp per row; q and k both -> bf16 hi/lo.
__global__ __launch_bounds__(256) void qknorm_kernel(const float* __restrict__ pos) {
    const int w = blockIdx.x * 8 + (threadIdx.x >> 5);
    const int lane = threadIdx.x & 31;
    const size_t row = (size_t)w;
    const int n = w & (SEQ - 1);
    const float* qrow = g_q + row * CH;
    const float* krow = g_k + row * CH;
    const float* prow = pos + (size_t)n * CH;

    float scv[20];
#pragma unroll
    for (int t = 0; t < 20; t++) scv[t] = g_sc[lane + 32 * t];

    {
        float v[20]; float s = 0.f;
#pragma unroll
        for (int t = 0; t < 20; t++) {
            float raw = qrow[lane + 32 * t];
            float val = (fmaxf(raw, 0.f) + 1e-6f) / scv[t];
            v[t] = val; s += val * val;
        }
        float n1 = sqrtf(warp_sum(s));
        s = 0.f;
#pragma unroll
        for (int t = 0; t < 20; t++) { float c3 = v[t]*v[t]*v[t]; v[t] = c3; s += c3*c3; }
        float sc2 = n1 / sqrtf(warp_sum(s));
#pragma unroll
        for (int t = 0; t < 20; t++) {
            float f = v[t] * sc2;
            __nv_bfloat16 h = __float2bfloat16_rn(f);
            __nv_bfloat16 l = __float2bfloat16_rn(f - __bfloat162float(h));
            g_qbh[row * CH + lane + 32 * t] = h;
            g_qbl[row * CH + lane + 32 * t] = l;
        }
    }
    {
        float v[20]; float s = 0.f;
#pragma unroll
        for (int t = 0; t < 20; t++) {
            float raw = krow[lane + 32 * t] + prow[lane + 32 * t];
            float val = (fmaxf(raw, 0.f) + 1e-6f) / scv[t];
            v[t] = val; s += val * val;
        }
        float n1 = sqrtf(warp_sum(s));
        s = 0.f;
#pragma unroll
        for (int t = 0; t < 20; t++) { float c3 = v[t]*v[t]*v[t]; v[t] = c3; s += c3*c3; }
        float sc2 = n1 / sqrtf(warp_sum(s));
#pragma unroll
        for (int t = 0; t < 20; t++) {
            float f = v[t] * sc2;
            __nv_bfloat16 h = __float2bfloat16_rn(f);
            __nv_bfloat16 l = __float2bfloat16_rn(f - __bfloat162float(h));
            g_kbh[row * CH + lane + 32 * t] = h;
            g_kbl[row * CH + lane + 32 * t] = l;
        }
    }
}

__global__ void zero_kernel() {
    int idx = blockIdx.x * 256 + threadIdx.x;
    if (idx < BH * HD * HD) g_kv2[idx] = 0.f;
    if (idx < BH * HD)      g_ksum[idx] = 0.f;
}

// kv2^T + bf16 split: [bh][c][d] fp32 -> [bh][d][c] hi/lo
__global__ __launch_bounds__(256) void kv2t_split() {
    const int bh = blockIdx.x;
    const int e = blockIdx.y * 256 + threadIdx.x;
    const int d = e >> 7, c = e & 127;
    float v = g_kv2[bh * HD * HD + c * HD + d];
    __nv_bfloat16 h = __float2bfloat16_rn(v);
    __nv_bfloat16 l = __float2bfloat16_rn(v - __bfloat162float(h));
    g_k2h[bh * HD * HD + d * HD + c] = h;
    g_k2l[bh * HD * HD + d * HD + c] = l;
}

// ---------------------------------------------------------------------------
// depthwise conv reading v hi/lo splits
// ---------------------------------------------------------------------------
__global__ __launch_bounds__(256) void conv_s(
    const float* __restrict__ w, const float* __restrict__ bias)
{
    extern __shared__ float sv[];   // [8][68][32]
    const int bh = blockIdx.x, yt = blockIdx.y, dc = blockIdx.z;
    const int b = bh / NH, hoff = (bh % NH) * HD;
    const int tid = threadIdx.x;
    const int d = tid & 31;
    const int xg = tid >> 5;
    const __nv_bfloat16* vh = g_vbh + (size_t)b * SEQ * CH + hoff + dc * 32;
    const __nv_bfloat16* vl = g_vbl + (size_t)b * SEQ * CH + hoff + dc * 32;

    {
        int p = tid;
        int r = p >> 5, rest = p & 31;
        int xi = rest >> 3, d4 = rest & 7;
        int ix = (xi < 2) ? xi : (xi + 64);
        *reinterpret_cast<float4*>(&sv[(r * 68 + ix) * 32 + d4 * 4]) =
            make_float4(0.f, 0.f, 0.f, 0.f);
    }
    for (int p = tid; p < 2048; p += 256) {
        int r = p >> 8, rest = p & 255;
        int x = rest >> 2, d8 = rest & 3;
        int y = yt * 4 - 2 + r;
        float f[8];
        if ((unsigned)y < 64u) {
            uint4 hv = *reinterpret_cast<const uint4*>(
                &vh[(size_t)(y * 64 + x) * CH + d8 * 8]);
            uint4 lv = *reinterpret_cast<const uint4*>(
                &vl[(size_t)(y * 64 + x) * CH + d8 * 8]);
            const __nv_bfloat162* h2 = reinterpret_cast<const __nv_bfloat162*>(&hv);
            const __nv_bfloat162* l2 = reinterpret_cast<const __nv_bfloat162*>(&lv);
#pragma unroll
            for (int j = 0; j < 4; j++) {
                f[2*j]   = __bfloat162float(h2[j].x) + __bfloat162float(l2[j].x);
                f[2*j+1] = __bfloat162float(h2[j].y) + __bfloat162float(l2[j].y);
            }
        } else {
#pragma unroll
            for (int j = 0; j < 8; j++) f[j] = 0.f;
        }
        float* dst = &sv[(r * 68 + x + 2) * 32 + d8 * 8];
        *reinterpret_cast<float4*>(dst)     = make_float4(f[0], f[1], f[2], f[3]);
        *reinterpret_cast<float4*>(dst + 4) = make_float4(f[4], f[5], f[6], f[7]);
    }
    __syncthreads();

    float wr[25];
#pragma unroll
    for (int k = 0; k < 25; k++) wr[k] = __ldg(&w[(dc * 32 + d) * 25 + k]);
    const float bv = __ldg(&bias[dc * 32 + d]);

#pragma unroll
    for (int y = 0; y < 4; y++) {
#pragma unroll
        for (int xo = 0; xo < 8; xo++) {
            int x = xg * 8 + xo;
            float acc = bv;
#pragma unroll
            for (int ky = 0; ky < 5; ky++)
#pragma unroll
                for (int kx = 0; kx < 5; kx++)
                    acc += wr[ky * 5 + kx] * sv[((y + ky) * 68 + (x + kx)) * 32 + d];
            int oy = yt * 4 + y;
            g_x[(size_t)(b * SEQ + oy * 64 + x) * CH + hoff + dc * 32 + d] = acc;
        }
    }
}

// ---------------------------------------------------------------------------
extern "C" void kernel_launch(void* const* d_in, const int* in_sizes, int n_in,
                              void* d_out, int out_size)
{
    const float* x1    = (const float*)d_in[0];
    const float* x2    = (const float*)d_in[1];
    const float* Wq    = (const float*)d_in[2];
    const float* Wkv   = (const float*)d_in[3];
    const float* Wproj = (const float*)d_in[4];
    const float* bproj = (const float*)d_in[5];
    const float* dwc_w = (const float*)d_in[6];
    const float* dwc_b = (const float*)d_in[7];
    const float* scale = (const float*)d_in[8];
    const float* pos   = (const float*)d_in[9];
    float* out = (float*)d_out;

    cudaFuncSetAttribute(gemm_merged,
        cudaFuncAttributeMaxDynamicSharedMemorySize, SMEM_GB);
    cudaFuncSetAttribute(gemm_proj,
        cudaFuncAttributeMaxDynamicSharedMemorySize, SMEM_GB);
    cudaFuncSetAttribute(attn_gemm,
        cudaFuncAttributeMaxDynamicSharedMemorySize, SMEM_GB);
    cudaFuncSetAttribute(kv2_mma,
        cudaFuncAttributeMaxDynamicSharedMemorySize, SMEM_KV2);
    cudaFuncSetAttribute(conv_s,
        cudaFuncAttributeMaxDynamicSharedMemorySize, 8 * 68 * 32 * 4);

    const int M = BATCH * SEQ;              // 32768
    const int XN4 = M * CH / 4;

    // side stream + events for conv overlap (created/destroyed per call:
    // host-side ops, legal alongside stream capture; fork/join via events)
    cudaStream_t side;
    cudaEvent_t evFork, evJoin;
    cudaStreamCreateWithFlags(&side, cudaStreamNonBlocking);
    cudaEventCreateWithFlags(&evFork, cudaEventDisableTiming);
    cudaEventCreateWithFlags(&evJoin, cudaEventDisableTiming);

    split_w<<<4 * CC / 1024, 256>>>(Wq, Wkv, Wproj);
    softplus_kernel<<<3, 256>>>(scale);
    zero_kernel<<<(BH * HD * HD + 255) / 256, 256>>>();
    split_x12<<<2 * (XN4 / 256), 256>>>(x1, x2, XN4);
    gemm_merged<<<dim3(15, M / BMM), 256, SMEM_GB>>>();        // v+k+q

    // fork: conv depends only on v splits
    cudaEventRecord(evFork, 0);
    cudaStreamWaitEvent(side, evFork, 0);
    conv_s<<<dim3(BH, 16, 4), 256, 8 * 68 * 32 * 4, side>>>(dwc_w, dwc_b);
    cudaEventRecord(evJoin, side);

    // main chain meanwhile
    qknorm_kernel<<<M / 8, 256>>>(pos);
    kv2_mma<<<dim3(BH, 8), 256, SMEM_KV2>>>();
    kv2t_split<<<dim3(BH, 64), 256>>>();

    // join before attn (needs g_x from conv)
    cudaStreamWaitEvent(0, evJoin, 0);
    attn_gemm<<<BH * 32, 256, SMEM_GB>>>();

    gemm_proj<<<dim3(5, M / BMM), 256, SMEM_GB>>>(out, bproj);

    cudaEventDestroy(evFork);
    cudaEventDestroy(evJoin);
    cudaStreamDestroy(side);
}